// round 1
// baseline (speedup 1.0000x reference)
#include <cuda_runtime.h>
#include <cuda_bf16.h>
#include <math.h>

#define D_EMBED 512
#define NHEAD   8
#define DH      64
#define DFF     2048
#define BATCH   2
#define SEQ     4096
#define NROWS   (BATCH*SEQ)   // 8192

// ---------------- scratch (static device allocations; no cudaMalloc allowed) ----
__device__ float g_q[BATCH*NHEAD*SEQ*DH];
__device__ float g_k[BATCH*NHEAD*SEQ*DH];
__device__ float g_v[BATCH*NHEAD*SEQ*DH];
__device__ float g_ctx[NROWS*D_EMBED];
__device__ float g_res1[NROWS*D_EMBED];
__device__ float g_h[NROWS*D_EMBED];
__device__ float g_ff[(size_t)NROWS*DFF];
__device__ float g_res2[NROWS*D_EMBED];

__device__ __forceinline__ float gelu_f(float x) {
    return 0.5f * x * (1.0f + erff(x * 0.70710678118654752f));
}

// ---------------- generic SGEMM: C = A[MxK] @ W[KxN] + bias, epilogue by MODE --
// MODE 0: QKV scatter  out[((b*H+h)*SEQ+l)*DH+d]
// MODE 1: plain bias
// MODE 2: bias + residual
// MODE 3: bias + exact GELU
template<int MODE>
__global__ __launch_bounds__(256)
void gemm_k(const float* __restrict__ A, const float* __restrict__ W,
            const float* __restrict__ bias, const float* __restrict__ resid,
            float* __restrict__ out, int M, int N, int K)
{
    __shared__ float As[16][65];
    __shared__ float Bs[16][65];

    const int tid = threadIdx.x;
    const int tx = tid & 15, ty = tid >> 4;
    const int m0 = blockIdx.y * 64, n0 = blockIdx.x * 64;

    float acc[4][4] = {};

    for (int k0 = 0; k0 < K; k0 += 16) {
        #pragma unroll
        for (int s = 0; s < 4; ++s) {
            int idx = tid + s * 256;
            int ar = idx >> 4, ac = idx & 15;       // A tile: 64 rows x 16 cols
            As[ac][ar] = A[(size_t)(m0 + ar) * K + k0 + ac];
            int br = idx >> 6, bc = idx & 63;       // W tile: 16 rows x 64 cols
            Bs[br][bc] = W[(size_t)(k0 + br) * N + n0 + bc];
        }
        __syncthreads();
        #pragma unroll
        for (int kk = 0; kk < 16; ++kk) {
            float ra[4], rb[4];
            #pragma unroll
            for (int i = 0; i < 4; ++i) ra[i] = As[kk][ty * 4 + i];
            #pragma unroll
            for (int j = 0; j < 4; ++j) rb[j] = Bs[kk][tx * 4 + j];
            #pragma unroll
            for (int i = 0; i < 4; ++i)
                #pragma unroll
                for (int j = 0; j < 4; ++j)
                    acc[i][j] += ra[i] * rb[j];
        }
        __syncthreads();
    }

    #pragma unroll
    for (int i = 0; i < 4; ++i) {
        int m = m0 + ty * 4 + i;
        #pragma unroll
        for (int j = 0; j < 4; ++j) {
            int n = n0 + tx * 4 + j;
            float c = acc[i][j] + bias[n];
            if (MODE == 0) {
                int b = m >> 12;          // SEQ = 4096 rows per batch
                int l = m & (SEQ - 1);
                int h = n >> 6;
                int d = n & 63;
                out[((size_t)(b * NHEAD + h) * SEQ + l) * DH + d] = c;
            } else if (MODE == 1) {
                out[(size_t)m * N + n] = c;
            } else if (MODE == 2) {
                out[(size_t)m * N + n] = c + resid[(size_t)m * N + n];
            } else {
                out[(size_t)m * N + n] = gelu_f(c);
            }
        }
    }
}

// ---------------- flash attention, fp32, BQ=BK=64, Dh=64 ----------------------
// Grid: (SEQ/64, NHEAD, BATCH), 256 threads.
// Thread t: query row r = t>>2, quad = t&3 owns dims [quad*16, quad*16+16).
__global__ __launch_bounds__(256)
void attn_k(const float* __restrict__ q, const float* __restrict__ k,
            const float* __restrict__ v, const int* __restrict__ mask,
            float* __restrict__ ctx)
{
    const int qt = blockIdx.x, h = blockIdx.y, b = blockIdx.z;
    const int tid = threadIdx.x;
    const int r = tid >> 2, quad = tid & 3;

    const float* qb = q + ((size_t)(b * NHEAD + h) * SEQ) * DH;
    const float* kb = k + ((size_t)(b * NHEAD + h) * SEQ) * DH;
    const float* vb = v + ((size_t)(b * NHEAD + h) * SEQ) * DH;

    __shared__ float4 Ks[64 * 16];
    __shared__ float4 Vs[64 * 16];
    __shared__ int    Ms[64];

    float4 Q[4];
    {
        const float4* qrow = (const float4*)(qb + (size_t)(qt * 64 + r) * DH) + quad * 4;
        #pragma unroll
        for (int i = 0; i < 4; ++i) {
            float4 t = qrow[i];
            Q[i] = make_float4(t.x * 0.125f, t.y * 0.125f, t.z * 0.125f, t.w * 0.125f);
        }
    }

    float4 O[4];
    #pragma unroll
    for (int i = 0; i < 4; ++i) O[i] = make_float4(0.f, 0.f, 0.f, 0.f);
    float mprev = -1e30f, lsum = 0.f;

    for (int t = 0; t < SEQ / 64; ++t) {
        __syncthreads();
        const float4* ksrc = (const float4*)(kb + (size_t)t * 64 * DH);
        const float4* vsrc = (const float4*)(vb + (size_t)t * 64 * DH);
        #pragma unroll
        for (int i = tid; i < 1024; i += 256) { Ks[i] = ksrc[i]; Vs[i] = vsrc[i]; }
        if (tid < 64) Ms[tid] = mask[b * SEQ + t * 64 + tid];
        __syncthreads();

        float S[64];
        float mt = -1e30f;
        #pragma unroll
        for (int j = 0; j < 64; ++j) {
            const float4* kr = &Ks[j * 16 + quad * 4];
            float s = 0.f;
            #pragma unroll
            for (int i = 0; i < 4; ++i) {
                float4 kv = kr[i];
                s += Q[i].x * kv.x + Q[i].y * kv.y + Q[i].z * kv.z + Q[i].w * kv.w;
            }
            s += __shfl_xor_sync(0xffffffffu, s, 1);
            s += __shfl_xor_sync(0xffffffffu, s, 2);
            s = Ms[j] ? s : -1e9f;
            S[j] = s;
            mt = fmaxf(mt, s);
        }

        float mnew  = fmaxf(mprev, mt);
        float alpha = __expf(mprev - mnew);
        lsum *= alpha;
        #pragma unroll
        for (int i = 0; i < 4; ++i) {
            O[i].x *= alpha; O[i].y *= alpha; O[i].z *= alpha; O[i].w *= alpha;
        }
        #pragma unroll
        for (int j = 0; j < 64; ++j) {
            float p = __expf(S[j] - mnew);
            lsum += p;
            const float4* vr = &Vs[j * 16 + quad * 4];
            #pragma unroll
            for (int i = 0; i < 4; ++i) {
                float4 vv = vr[i];
                O[i].x += p * vv.x; O[i].y += p * vv.y;
                O[i].z += p * vv.z; O[i].w += p * vv.w;
            }
        }
        mprev = mnew;
    }

    float inv = 1.f / lsum;
    float* orow = ctx + (size_t)(b * SEQ + qt * 64 + r) * D_EMBED + h * DH + quad * 16;
    #pragma unroll
    for (int i = 0; i < 4; ++i)
        ((float4*)orow)[i] = make_float4(O[i].x * inv, O[i].y * inv, O[i].z * inv, O[i].w * inv);
}

// ---------------- LayerNorm over rows of 512 ----------------------------------
__global__ __launch_bounds__(128)
void ln_k(const float* __restrict__ in, const float* __restrict__ gam,
          const float* __restrict__ bet, float* __restrict__ out)
{
    const int row = blockIdx.x;
    const int tid = threadIdx.x;
    float4 vx = ((const float4*)(in + (size_t)row * D_EMBED))[tid];
    float s  = vx.x + vx.y + vx.z + vx.w;
    float ss = vx.x * vx.x + vx.y * vx.y + vx.z * vx.z + vx.w * vx.w;
    #pragma unroll
    for (int o = 16; o; o >>= 1) {
        s  += __shfl_xor_sync(0xffffffffu, s, o);
        ss += __shfl_xor_sync(0xffffffffu, ss, o);
    }
    __shared__ float sh[8];
    if ((tid & 31) == 0) { sh[tid >> 5] = s; sh[4 + (tid >> 5)] = ss; }
    __syncthreads();
    float S  = sh[0] + sh[1] + sh[2] + sh[3];
    float SS = sh[4] + sh[5] + sh[6] + sh[7];
    float mu   = S * (1.f / 512.f);
    float var  = SS * (1.f / 512.f) - mu * mu;
    float rstd = rsqrtf(var + 1e-5f);
    float4 g  = ((const float4*)gam)[tid];
    float4 bb = ((const float4*)bet)[tid];
    float4 o;
    o.x = (vx.x - mu) * rstd * g.x + bb.x;
    o.y = (vx.y - mu) * rstd * g.y + bb.y;
    o.z = (vx.z - mu) * rstd * g.z + bb.z;
    o.w = (vx.w - mu) * rstd * g.w + bb.w;
    ((float4*)(out + (size_t)row * D_EMBED))[tid] = o;
}

// ---------------- launcher -----------------------------------------------------
extern "C" void kernel_launch(void* const* d_in, const int* in_sizes, int n_in,
                              void* d_out, int out_size)
{
    const float* x    = (const float*)d_in[0];
    const int*   mask = (const int*)  d_in[1];
    const float* Wq   = (const float*)d_in[2];
    const float* bq   = (const float*)d_in[3];
    const float* Wk   = (const float*)d_in[4];
    const float* bk   = (const float*)d_in[5];
    const float* Wv   = (const float*)d_in[6];
    const float* bv   = (const float*)d_in[7];
    const float* Wo   = (const float*)d_in[8];
    const float* bo   = (const float*)d_in[9];

    const float *ln1g, *ln1b, *ln2g, *ln2b, *W1, *b1, *W2, *b2;
    if (in_sizes[12] == D_EMBED * DFF) {
        // function-signature order: ln1_g, ln1_b, W1, b1, W2, b2, ln2_g, ln2_b
        ln1g = (const float*)d_in[10]; ln1b = (const float*)d_in[11];
        W1   = (const float*)d_in[12]; b1   = (const float*)d_in[13];
        W2   = (const float*)d_in[14]; b2   = (const float*)d_in[15];
        ln2g = (const float*)d_in[16]; ln2b = (const float*)d_in[17];
    } else {
        // dict order: ln1_g, ln1_b, ln2_g, ln2_b, W1, b1, W2, b2
        ln1g = (const float*)d_in[10]; ln1b = (const float*)d_in[11];
        ln2g = (const float*)d_in[12]; ln2b = (const float*)d_in[13];
        W1   = (const float*)d_in[14]; b1   = (const float*)d_in[15];
        W2   = (const float*)d_in[16]; b2   = (const float*)d_in[17];
    }

    float *q, *k, *v, *ctx, *res1, *h, *ff, *res2;
    cudaGetSymbolAddress((void**)&q,    g_q);
    cudaGetSymbolAddress((void**)&k,    g_k);
    cudaGetSymbolAddress((void**)&v,    g_v);
    cudaGetSymbolAddress((void**)&ctx,  g_ctx);
    cudaGetSymbolAddress((void**)&res1, g_res1);
    cudaGetSymbolAddress((void**)&h,    g_h);
    cudaGetSymbolAddress((void**)&ff,   g_ff);
    cudaGetSymbolAddress((void**)&res2, g_res2);

    dim3 blk(256);
    dim3 gProj(D_EMBED / 64, NROWS / 64);

    gemm_k<0><<<gProj, blk>>>(x, Wq, bq, nullptr, q, NROWS, D_EMBED, D_EMBED);
    gemm_k<0><<<gProj, blk>>>(x, Wk, bk, nullptr, k, NROWS, D_EMBED, D_EMBED);
    gemm_k<0><<<gProj, blk>>>(x, Wv, bv, nullptr, v, NROWS, D_EMBED, D_EMBED);

    attn_k<<<dim3(SEQ / 64, NHEAD, BATCH), blk>>>(q, k, v, mask, ctx);

    gemm_k<2><<<gProj, blk>>>(ctx, Wo, bo, x, res1, NROWS, D_EMBED, D_EMBED);
    ln_k<<<NROWS, 128>>>(res1, ln1g, ln1b, h);

    gemm_k<3><<<dim3(DFF / 64, NROWS / 64), blk>>>(h, W1, b1, nullptr, ff, NROWS, DFF, D_EMBED);
    gemm_k<2><<<gProj, blk>>>(ff, W2, b2, h, res2, NROWS, D_EMBED, DFF);
    ln_k<<<NROWS, 128>>>(res2, ln2g, ln2b, (float*)d_out);
}

// round 2
// speedup vs baseline: 2.6245x; 2.6245x over previous
#include <cuda_runtime.h>
#include <math.h>

#define D_EMBED 512
#define NHEAD   8
#define DH      64
#define DFF     2048
#define BATCH   2
#define SEQ     4096
#define NROWS   (BATCH*SEQ)   // 8192

// ---------------- scratch ------------------------------------------------------
__device__ float g_q[BATCH*NHEAD*SEQ*DH];
__device__ float g_k[BATCH*NHEAD*SEQ*DH];
__device__ float g_v[BATCH*NHEAD*SEQ*DH];
__device__ float g_ctx[NROWS*D_EMBED];
__device__ float g_res1[NROWS*D_EMBED];
__device__ float g_h[NROWS*D_EMBED];
__device__ float g_ff[(size_t)NROWS*DFF];
__device__ float g_res2[NROWS*D_EMBED];

// ---------------- f32x2 packed math helpers ------------------------------------
typedef unsigned long long u64;

__device__ __forceinline__ u64 pack2(float x, float y) {
    u64 r; asm("mov.b64 %0, {%1, %2};" : "=l"(r) : "f"(x), "f"(y)); return r;
}
__device__ __forceinline__ void unpack2(u64 v, float& x, float& y) {
    asm("mov.b64 {%0, %1}, %2;" : "=f"(x), "=f"(y) : "l"(v));
}
#define FMA2(d, a, b) asm("fma.rn.f32x2 %0, %1, %2, %0;" : "+l"(d) : "l"(a), "l"(b))
#define MUL2(d, a)    asm("mul.rn.f32x2 %0, %0, %1;"     : "+l"(d) : "l"(a))

__device__ __forceinline__ float gelu_f(float x) {
    return 0.5f * x * (1.0f + erff(x * 0.70710678118654752f));
}

// ---------------- SGEMM 128x128x16, 8x8 frags, fma.rn.f32x2 --------------------
// MODE 0: QKV scatter (+bias)   MODE 2: bias+residual   MODE 3: bias+GELU
#define AST 132
#define BST 132
template<int MODE>
__global__ __launch_bounds__(256)
void gemm128(const float* __restrict__ A, const float* __restrict__ W,
             const float* __restrict__ bias, const float* __restrict__ resid,
             float* __restrict__ out, int M, int N, int K)
{
    __shared__ float As[16 * AST];   // transposed: As[k][m]
    __shared__ float Bs[16 * BST];   // Bs[k][n]

    const int tid = threadIdx.x;
    const int tx = tid & 15, ty = tid >> 4;
    const int m0 = blockIdx.y * 128, n0 = blockIdx.x * 128;

    u64 acc[4][8];
    #pragma unroll
    for (int p = 0; p < 4; ++p)
        #pragma unroll
        for (int j = 0; j < 8; ++j) acc[p][j] = 0ULL;

    for (int k0 = 0; k0 < K; k0 += 16) {
        #pragma unroll
        for (int s = 0; s < 2; ++s) {
            int idx = tid + s * 256;
            int m = idx >> 2, kg = idx & 3;       // A: 128 m x 16 k
            float4 av = *(const float4*)(A + (size_t)(m0 + m) * K + k0 + kg * 4);
            As[(kg * 4 + 0) * AST + m] = av.x;
            As[(kg * 4 + 1) * AST + m] = av.y;
            As[(kg * 4 + 2) * AST + m] = av.z;
            As[(kg * 4 + 3) * AST + m] = av.w;
            int kb = idx >> 5, ng = idx & 31;     // B: 16 k x 128 n
            *(float4*)&Bs[kb * BST + ng * 4] =
                *(const float4*)(W + (size_t)(k0 + kb) * N + n0 + ng * 4);
        }
        __syncthreads();
        #pragma unroll
        for (int kk = 0; kk < 16; ++kk) {
            const float* ap = &As[kk * AST + ty * 8];
            ulonglong2 a01 = *(const ulonglong2*)ap;
            ulonglong2 a23 = *(const ulonglong2*)(ap + 4);
            u64 aq[4] = {a01.x, a01.y, a23.x, a23.y};
            const float* bp = &Bs[kk * BST + tx * 8];
            float4 b0 = *(const float4*)bp;
            float4 b1 = *(const float4*)(bp + 4);
            float bf[8] = {b0.x, b0.y, b0.z, b0.w, b1.x, b1.y, b1.z, b1.w};
            #pragma unroll
            for (int j = 0; j < 8; ++j) {
                u64 bd = pack2(bf[j], bf[j]);
                #pragma unroll
                for (int p = 0; p < 4; ++p) FMA2(acc[p][j], aq[p], bd);
            }
        }
        __syncthreads();
    }

    // epilogue
    float bse[8];
    #pragma unroll
    for (int j = 0; j < 8; ++j) bse[j] = bias[n0 + tx * 8 + j];

    #pragma unroll
    for (int p = 0; p < 4; ++p) {
        float c0[8], c1[8];
        #pragma unroll
        for (int j = 0; j < 8; ++j) unpack2(acc[p][j], c0[j], c1[j]);
        #pragma unroll
        for (int half = 0; half < 2; ++half) {
            float* c = half ? c1 : c0;
            int m = m0 + ty * 8 + 2 * p + half;
            #pragma unroll
            for (int j = 0; j < 8; ++j) {
                int n = n0 + tx * 8 + j;
                float v = c[j] + bse[j];
                if (MODE == 0) {
                    int b = m >> 12, l = m & (SEQ - 1);
                    int hh = n >> 6, d = n & 63;
                    out[((size_t)(b * NHEAD + hh) * SEQ + l) * DH + d] = v;
                } else if (MODE == 2) {
                    out[(size_t)m * N + n] = v + resid[(size_t)m * N + n];
                } else {
                    out[(size_t)m * N + n] = gelu_f(v);
                }
            }
        }
    }
}

// ---------------- flash attention, f32x2, BQ=128, BK=64 ------------------------
// 128 threads: ty = tid>>3 (16 q-groups of 8), tx = tid&7 (8 groups: k in S, d in PV)
#define QST 132
#define KST 68
#define PST 132
#define SMEM_ATTN ((64*QST + 64*KST + 64*64 + 64*PST) * 4 + 64 * 4)

__global__ __launch_bounds__(128)
void attn_k(const float* __restrict__ q, const float* __restrict__ k,
            const float* __restrict__ v, const int* __restrict__ mask,
            float* __restrict__ ctx)
{
    extern __shared__ float sm[];
    float* Qs = sm;                   // [64 d][128 q]  stride QST
    float* Ks = Qs + 64 * QST;        // [64 d][64 k]   stride KST
    float* Vs = Ks + 64 * KST;        // [64 k][64 d]   stride 64
    float* Ps = Vs + 64 * 64;         // [64 k][128 q]  stride PST
    int*   Ms = (int*)(Ps + 64 * PST);

    const int qt = blockIdx.x, h = blockIdx.y, b = blockIdx.z;
    const int tid = threadIdx.x;
    const int ty = tid >> 3, tx = tid & 7;

    const float* qb = q + ((size_t)(b * NHEAD + h) * SEQ) * DH;
    const float* kb = k + ((size_t)(b * NHEAD + h) * SEQ) * DH;
    const float* vb = v + ((size_t)(b * NHEAD + h) * SEQ) * DH;

    // load+scale+transpose Q tile (128 x 64)
    for (int idx = tid; idx < 2048; idx += 128) {
        int qr = idx >> 4, dg = idx & 15;
        float4 val = *(const float4*)(qb + (size_t)(qt * 128 + qr) * DH + dg * 4);
        Qs[(dg * 4 + 0) * QST + qr] = val.x * 0.125f;
        Qs[(dg * 4 + 1) * QST + qr] = val.y * 0.125f;
        Qs[(dg * 4 + 2) * QST + qr] = val.z * 0.125f;
        Qs[(dg * 4 + 3) * QST + qr] = val.w * 0.125f;
    }

    u64 O2[8][4];
    float m_[8], l_[8];
    #pragma unroll
    for (int i = 0; i < 8; ++i) {
        m_[i] = -1e30f; l_[i] = 0.f;
        #pragma unroll
        for (int jp = 0; jp < 4; ++jp) O2[i][jp] = 0ULL;
    }

    for (int t = 0; t < SEQ / 64; ++t) {
        __syncthreads();   // also covers initial Qs fill
        // K tile: transpose into Ks[d][k]
        for (int idx = tid; idx < 1024; idx += 128) {
            int kr = idx >> 4, dg = idx & 15;
            float4 kv = *(const float4*)(kb + (size_t)(t * 64 + kr) * DH + dg * 4);
            Ks[(dg * 4 + 0) * KST + kr] = kv.x;
            Ks[(dg * 4 + 1) * KST + kr] = kv.y;
            Ks[(dg * 4 + 2) * KST + kr] = kv.z;
            Ks[(dg * 4 + 3) * KST + kr] = kv.w;
        }
        // V tile: direct
        for (int idx = tid; idx < 1024; idx += 128)
            *(float4*)&Vs[idx * 4] = *(const float4*)(vb + (size_t)t * 64 * DH + idx * 4);
        if (tid < 64) Ms[tid] = mask[b * SEQ + t * 64 + tid];
        __syncthreads();

        // ---- S = Q K^T (8q x 8k frag, q-pairs packed) ----
        u64 acc[4][8];
        #pragma unroll
        for (int p = 0; p < 4; ++p)
            #pragma unroll
            for (int j = 0; j < 8; ++j) acc[p][j] = 0ULL;

        #pragma unroll 4
        for (int kk = 0; kk < 64; ++kk) {
            const float* qp = &Qs[kk * QST + ty * 8];
            ulonglong2 qa = *(const ulonglong2*)qp;
            ulonglong2 qc = *(const ulonglong2*)(qp + 4);
            u64 qq[4] = {qa.x, qa.y, qc.x, qc.y};
            const float* kp = &Ks[kk * KST + tx * 8];
            float4 k0 = *(const float4*)kp;
            float4 k1 = *(const float4*)(kp + 4);
            float kf[8] = {k0.x, k0.y, k0.z, k0.w, k1.x, k1.y, k1.z, k1.w};
            #pragma unroll
            for (int j = 0; j < 8; ++j) {
                u64 kd = pack2(kf[j], kf[j]);
                #pragma unroll
                for (int p = 0; p < 4; ++p) FMA2(acc[p][j], qq[p], kd);
            }
        }

        float S[8][8];
        #pragma unroll
        for (int p = 0; p < 4; ++p)
            #pragma unroll
            for (int j = 0; j < 8; ++j) unpack2(acc[p][j], S[2 * p][j], S[2 * p + 1][j]);

        #pragma unroll
        for (int j = 0; j < 8; ++j) {
            if (Ms[tx * 8 + j] == 0) {
                #pragma unroll
                for (int i = 0; i < 8; ++i) S[i][j] = -1e9f;
            }
        }

        // ---- online softmax (rows reduced over tx: lanes xor 1,2,4) ----
        #pragma unroll
        for (int i = 0; i < 8; ++i) {
            float rmax = S[i][0];
            #pragma unroll
            for (int j = 1; j < 8; ++j) rmax = fmaxf(rmax, S[i][j]);
            rmax = fmaxf(rmax, __shfl_xor_sync(0xffffffffu, rmax, 1));
            rmax = fmaxf(rmax, __shfl_xor_sync(0xffffffffu, rmax, 2));
            rmax = fmaxf(rmax, __shfl_xor_sync(0xffffffffu, rmax, 4));
            float mn = fmaxf(m_[i], rmax);
            float al = __expf(m_[i] - mn);
            m_[i] = mn;
            l_[i] *= al;
            u64 ad = pack2(al, al);
            #pragma unroll
            for (int jp = 0; jp < 4; ++jp) MUL2(O2[i][jp], ad);
            float rs = 0.f;
            #pragma unroll
            for (int j = 0; j < 8; ++j) {
                float pv = __expf(S[i][j] - mn);
                S[i][j] = pv;
                rs += pv;
            }
            rs += __shfl_xor_sync(0xffffffffu, rs, 1);
            rs += __shfl_xor_sync(0xffffffffu, rs, 2);
            rs += __shfl_xor_sync(0xffffffffu, rs, 4);
            l_[i] += rs;
        }

        // ---- stage P transposed: Ps[k][q] ----
        #pragma unroll
        for (int j = 0; j < 8; ++j) {
            float* pd = &Ps[(tx * 8 + j) * PST + ty * 8];
            *(float4*)pd       = make_float4(S[0][j], S[1][j], S[2][j], S[3][j]);
            *(float4*)(pd + 4) = make_float4(S[4][j], S[5][j], S[6][j], S[7][j]);
        }
        __syncthreads();

        // ---- O += P V  (8q x 8d frag, d-pairs packed) ----
        #pragma unroll 4
        for (int kk = 0; kk < 64; ++kk) {
            const float* pp = &Ps[kk * PST + ty * 8];
            float4 p0 = *(const float4*)pp;
            float4 p1 = *(const float4*)(pp + 4);
            float pf[8] = {p0.x, p0.y, p0.z, p0.w, p1.x, p1.y, p1.z, p1.w};
            const float* vp = &Vs[kk * 64 + tx * 8];
            ulonglong2 v01 = *(const ulonglong2*)vp;
            ulonglong2 v23 = *(const ulonglong2*)(vp + 4);
            u64 vv[4] = {v01.x, v01.y, v23.x, v23.y};
            #pragma unroll
            for (int i = 0; i < 8; ++i) {
                u64 pd = pack2(pf[i], pf[i]);
                #pragma unroll
                for (int jp = 0; jp < 4; ++jp) FMA2(O2[i][jp], pd, vv[jp]);
            }
        }
    }

    // ---- write ctx ----
    #pragma unroll
    for (int i = 0; i < 8; ++i) {
        float inv = 1.f / l_[i];
        float o[8];
        #pragma unroll
        for (int jp = 0; jp < 4; ++jp) unpack2(O2[i][jp], o[2 * jp], o[2 * jp + 1]);
        int row = b * SEQ + qt * 128 + ty * 8 + i;
        float* dst = ctx + (size_t)row * D_EMBED + h * DH + tx * 8;
        *(float4*)dst       = make_float4(o[0] * inv, o[1] * inv, o[2] * inv, o[3] * inv);
        *(float4*)(dst + 4) = make_float4(o[4] * inv, o[5] * inv, o[6] * inv, o[7] * inv);
    }
}

// ---------------- LayerNorm over rows of 512 ------------------------------------
__global__ __launch_bounds__(128)
void ln_k(const float* __restrict__ in, const float* __restrict__ gam,
          const float* __restrict__ bet, float* __restrict__ out)
{
    const int row = blockIdx.x;
    const int tid = threadIdx.x;
    float4 vx = ((const float4*)(in + (size_t)row * D_EMBED))[tid];
    float s  = vx.x + vx.y + vx.z + vx.w;
    float ss = vx.x * vx.x + vx.y * vx.y + vx.z * vx.z + vx.w * vx.w;
    #pragma unroll
    for (int o = 16; o; o >>= 1) {
        s  += __shfl_xor_sync(0xffffffffu, s, o);
        ss += __shfl_xor_sync(0xffffffffu, ss, o);
    }
    __shared__ float sh[8];
    if ((tid & 31) == 0) { sh[tid >> 5] = s; sh[4 + (tid >> 5)] = ss; }
    __syncthreads();
    float S  = sh[0] + sh[1] + sh[2] + sh[3];
    float SS = sh[4] + sh[5] + sh[6] + sh[7];
    float mu   = S * (1.f / 512.f);
    float var  = SS * (1.f / 512.f) - mu * mu;
    float rstd = rsqrtf(var + 1e-5f);
    float4 g  = ((const float4*)gam)[tid];
    float4 bb = ((const float4*)bet)[tid];
    float4 o;
    o.x = (vx.x - mu) * rstd * g.x + bb.x;
    o.y = (vx.y - mu) * rstd * g.y + bb.y;
    o.z = (vx.z - mu) * rstd * g.z + bb.z;
    o.w = (vx.w - mu) * rstd * g.w + bb.w;
    ((float4*)(out + (size_t)row * D_EMBED))[tid] = o;
}

// ---------------- launcher -------------------------------------------------------
extern "C" void kernel_launch(void* const* d_in, const int* in_sizes, int n_in,
                              void* d_out, int out_size)
{
    const float* x    = (const float*)d_in[0];
    const int*   mask = (const int*)  d_in[1];
    const float* Wq   = (const float*)d_in[2];
    const float* bq   = (const float*)d_in[3];
    const float* Wk   = (const float*)d_in[4];
    const float* bk   = (const float*)d_in[5];
    const float* Wv   = (const float*)d_in[6];
    const float* bv   = (const float*)d_in[7];
    const float* Wo   = (const float*)d_in[8];
    const float* bo   = (const float*)d_in[9];

    const float *ln1g, *ln1b, *ln2g, *ln2b, *W1, *b1, *W2, *b2;
    if (in_sizes[12] == D_EMBED * DFF) {
        ln1g = (const float*)d_in[10]; ln1b = (const float*)d_in[11];
        W1   = (const float*)d_in[12]; b1   = (const float*)d_in[13];
        W2   = (const float*)d_in[14]; b2   = (const float*)d_in[15];
        ln2g = (const float*)d_in[16]; ln2b = (const float*)d_in[17];
    } else {
        ln1g = (const float*)d_in[10]; ln1b = (const float*)d_in[11];
        ln2g = (const float*)d_in[12]; ln2b = (const float*)d_in[13];
        W1   = (const float*)d_in[14]; b1   = (const float*)d_in[15];
        W2   = (const float*)d_in[16]; b2   = (const float*)d_in[17];
    }

    float *q, *k, *v, *ctx, *res1, *h, *ff, *res2;
    cudaGetSymbolAddress((void**)&q,    g_q);
    cudaGetSymbolAddress((void**)&k,    g_k);
    cudaGetSymbolAddress((void**)&v,    g_v);
    cudaGetSymbolAddress((void**)&ctx,  g_ctx);
    cudaGetSymbolAddress((void**)&res1, g_res1);
    cudaGetSymbolAddress((void**)&h,    g_h);
    cudaGetSymbolAddress((void**)&ff,   g_ff);
    cudaGetSymbolAddress((void**)&res2, g_res2);

    static bool attr_done = false;
    if (!attr_done) {
        cudaFuncSetAttribute(attn_k, cudaFuncAttributeMaxDynamicSharedMemorySize, SMEM_ATTN);
        attr_done = true;
    }

    dim3 blk(256);
    dim3 gProj(D_EMBED / 128, NROWS / 128);   // (4, 64)

    gemm128<0><<<gProj, blk>>>(x, Wq, bq, nullptr, q, NROWS, D_EMBED, D_EMBED);
    gemm128<0><<<gProj, blk>>>(x, Wk, bk, nullptr, k, NROWS, D_EMBED, D_EMBED);
    gemm128<0><<<gProj, blk>>>(x, Wv, bv, nullptr, v, NROWS, D_EMBED, D_EMBED);

    attn_k<<<dim3(SEQ / 128, NHEAD, BATCH), 128, SMEM_ATTN>>>(q, k, v, mask, ctx);

    gemm128<2><<<gProj, blk>>>(ctx, Wo, bo, x, res1, NROWS, D_EMBED, D_EMBED);
    ln_k<<<NROWS, 128>>>(res1, ln1g, ln1b, h);

    gemm128<3><<<dim3(DFF / 128, NROWS / 128), blk>>>(h, W1, b1, nullptr, ff, NROWS, DFF, D_EMBED);
    gemm128<2><<<gProj, blk>>>(ff, W2, b2, h, res2, NROWS, D_EMBED, DFF);
    ln_k<<<NROWS, 128>>>(res2, ln2g, ln2b, (float*)d_out);
}

// round 4
// speedup vs baseline: 2.6526x; 1.0107x over previous
#include <cuda_runtime.h>
#include <math.h>
#include <stdint.h>

#define D_EMBED 512
#define NHEAD   8
#define DH      64
#define DFF     2048
#define BATCH   2
#define SEQ     4096
#define NROWS   (BATCH*SEQ)   // 8192

// ---- arch feature detection: tcgen05 only exists in the sm_103a-specific pass --
#if defined(__CUDA_ARCH__)
# if defined(__CUDA_ARCH_HAS_FEATURE__)
#  if __CUDA_ARCH_HAS_FEATURE__(SM103_ALL)
#   define HAS_TC 1
#  endif
# endif
# if !defined(HAS_TC) && defined(__CUDA_ARCH_SPECIFIC__)
#  define HAS_TC 1
# endif
#endif
#ifndef HAS_TC
# define HAS_TC 0
#endif

// ---------------- scratch ------------------------------------------------------
__device__ float g_q[BATCH*NHEAD*SEQ*DH];
__device__ float g_k[BATCH*NHEAD*SEQ*DH];
__device__ float g_v[BATCH*NHEAD*SEQ*DH];
__device__ float g_ctx[NROWS*D_EMBED];
__device__ float g_res1[NROWS*D_EMBED];
__device__ float g_h[NROWS*D_EMBED];
__device__ float g_ff[(size_t)NROWS*DFF];
__device__ float g_res2[NROWS*D_EMBED];
// transposed tf32-rounded weights (B operands, K-major [N][K])
__device__ float g_wqkvt[3*D_EMBED*D_EMBED];
__device__ float g_wot[D_EMBED*D_EMBED];
__device__ float g_w1t[DFF*D_EMBED];
__device__ float g_w2t[D_EMBED*DFF];

// ---------------- common helpers -----------------------------------------------
typedef unsigned long long u64;
__device__ __forceinline__ u64 pack2(float x, float y) {
    u64 r; asm("mov.b64 %0, {%1, %2};" : "=l"(r) : "f"(x), "f"(y)); return r;
}
__device__ __forceinline__ void unpack2(u64 v, float& x, float& y) {
    asm("mov.b64 {%0, %1}, %2;" : "=f"(x), "=f"(y) : "l"(v));
}
#define FMA2(d, a, b) asm("fma.rn.f32x2 %0, %1, %2, %0;" : "+l"(d) : "l"(a), "l"(b))
#define MUL2(d, a)    asm("mul.rn.f32x2 %0, %0, %1;"     : "+l"(d) : "l"(a))

__device__ __forceinline__ float cvt_tf32(float x) {
    uint32_t u; asm("cvt.rna.tf32.f32 %0, %1;" : "=r"(u) : "f"(x));
    return __uint_as_float(u);
}
__device__ __forceinline__ float gelu_f(float x) {
    return 0.5f * x * (1.0f + erff(x * 0.70710678118654752f));
}

#if HAS_TC
__device__ __forceinline__ uint32_t elect_one_pred() {
    uint32_t pred;
    asm volatile("{\n\t.reg .pred p;\n\telect.sync _|p, 0xFFFFFFFF;\n\t"
                 "selp.b32 %0, 1, 0, p;\n\t}" : "=r"(pred));
    return pred;
}
#endif
__device__ __forceinline__ uint32_t smem_u32(const void* p) {
    uint32_t a;
    asm("{ .reg .u64 t; cvta.to.shared.u64 t, %1; cvt.u32.u64 %0, t; }" : "=r"(a) : "l"(p));
    return a;
}

#if HAS_TC
#define MBAR_INIT(a, n) asm volatile("mbarrier.init.shared.b64 [%0], %1;" :: "r"(a), "r"(n) : "memory")
#define MBAR_WAIT(a, par) do { \
    uint32_t _m = (a), _p = (par), _d; \
    asm volatile("{\n\t.reg .pred p;\n\t" \
        "mbarrier.try_wait.parity.acquire.cta.shared::cta.b64 p, [%1], %2;\n\t" \
        "selp.b32 %0, 1, 0, p;\n\t}" : "=r"(_d) : "r"(_m), "r"(_p) : "memory"); \
    if (!_d) { asm volatile("{\n\t.reg .pred P1;\n\tWL_%=:\n\t" \
        "mbarrier.try_wait.parity.acquire.cta.shared::cta.b64 P1, [%0], %1, 0x989680;\n\t" \
        "@P1 bra.uni WD_%=;\n\tbra.uni WL_%=;\n\tWD_%=:\n\t}" \
        :: "r"(_m), "r"(_p) : "memory"); } \
} while (0)

#define TC_ALLOC(sa, n)   asm volatile("tcgen05.alloc.cta_group::1.sync.aligned.shared::cta.b32 [%0], %1;" :: "r"(sa), "r"(n) : "memory")
#define TC_DEALLOC(t, n)  asm volatile("tcgen05.dealloc.cta_group::1.sync.aligned.b32 %0, %1;" :: "r"(t), "r"(n))
#define TC_COMMIT(mb)     asm volatile("tcgen05.commit.cta_group::1.mbarrier::arrive::one.shared::cluster.b64 [%0];" :: "r"(mb) : "memory")
#define TC_FENCE_AFTER()  asm volatile("tcgen05.fence::after_thread_sync;" ::: "memory")
#define TC_WAIT_LD()      asm volatile("tcgen05.wait::ld.sync.aligned;" ::: "memory")
#define FENCE_ASYNC()     asm volatile("fence.proxy.async.shared::cta;" ::: "memory")

#define TC_LD_X32(r, ta) \
    asm volatile("tcgen05.ld.sync.aligned.32x32b.x32.b32 " \
        "{%0, %1, %2, %3, %4, %5, %6, %7, %8, %9, %10, %11, %12, %13, %14, %15, " \
        " %16, %17, %18, %19, %20, %21, %22, %23, %24, %25, %26, %27, %28, %29, %30, %31}, [%32];" \
        : "=r"((r)[0]), "=r"((r)[1]), "=r"((r)[2]), "=r"((r)[3]), \
          "=r"((r)[4]), "=r"((r)[5]), "=r"((r)[6]), "=r"((r)[7]), \
          "=r"((r)[8]), "=r"((r)[9]), "=r"((r)[10]), "=r"((r)[11]), \
          "=r"((r)[12]), "=r"((r)[13]), "=r"((r)[14]), "=r"((r)[15]), \
          "=r"((r)[16]), "=r"((r)[17]), "=r"((r)[18]), "=r"((r)[19]), \
          "=r"((r)[20]), "=r"((r)[21]), "=r"((r)[22]), "=r"((r)[23]), \
          "=r"((r)[24]), "=r"((r)[25]), "=r"((r)[26]), "=r"((r)[27]), \
          "=r"((r)[28]), "=r"((r)[29]), "=r"((r)[30]), "=r"((r)[31]) \
        : "r"(ta))

#define TC_MMA_TF32(dt, ad, bd, id, en) do { \
    uint32_t _e = (en) ? 1u : 0u; \
    asm volatile("{\n\t.reg .pred p;\n\tsetp.ne.u32 p, %5, 0;\n\t" \
        "tcgen05.mma.cta_group::1.kind::tf32 [%0], %1, %2, %3, {%4, %4, %4, %4}, p;\n\t}" \
        :: "r"(dt), "l"(ad), "l"(bd), "r"(id), "r"(0u), "r"(_e) : "memory"); \
} while (0)

__device__ __forceinline__ uint64_t make_desc(uint32_t addr) {
    return ((uint64_t)2 << 61) | ((uint64_t)1 << 46) | ((uint64_t)64 << 32) |
           ((uint64_t)1 << 16) | (uint64_t)((addr >> 4) & 0x3FFF);
}
#define IDESC_T ((1u << 4) | (2u << 7) | (2u << 10) | ((128u / 8) << 17) | ((128u / 16) << 24))
#endif // HAS_TC

// ---------------- weight transpose + tf32 round: dst[C][R] = cvt(src[R][C]) ----
__global__ __launch_bounds__(256)
void transpose_cvt(const float* __restrict__ src, float* __restrict__ dst, int R, int C)
{
    __shared__ float t[32][33];
    int r0 = blockIdx.y * 32, c0 = blockIdx.x * 32;
    int tx = threadIdx.x & 31, ty = threadIdx.x >> 5;
    #pragma unroll
    for (int i = 0; i < 32; i += 8)
        t[ty + i][tx] = src[(size_t)(r0 + ty + i) * C + c0 + tx];
    __syncthreads();
    #pragma unroll
    for (int i = 0; i < 32; i += 8)
        dst[(size_t)(c0 + ty + i) * R + r0 + tx] = cvt_tf32(t[tx][ty + i]);
}

// ---------------- GEMM: out = A[8192xK] @ Wt[N][K]^T + bias --------------------
// MODE 0: QKV scatter   MODE 2: bias+residual   MODE 3: bias+GELU
// 128 threads, grid (N/128, 8192/128). tcgen05 TF32 path or SIMT f32x2 fallback.
template<int MODE>
__global__ __launch_bounds__(128)
void gemmT(const float* __restrict__ A, const float* __restrict__ Wt,
           const float* __restrict__ bias0, const float* __restrict__ bias1,
           const float* __restrict__ bias2, const float* __restrict__ resid,
           float* __restrict__ out0, float* __restrict__ out1, float* __restrict__ out2,
           int N, int K)
{
    extern __shared__ __align__(1024) float sm[];
    const int tid = threadIdx.x, wid = tid >> 5, lane = tid & 31;
    const int n0 = blockIdx.x * 128, m0 = blockIdx.y * 128;

#if HAS_TC
    __shared__ uint32_t s_tptr;
    __shared__ unsigned long long s_mbar[2];
    const uint32_t smb = smem_u32(sm);

    if (wid == 0) TC_ALLOC(smem_u32(&s_tptr), 128);
    if (tid == 0) { MBAR_INIT(smem_u32(&s_mbar[0]), 1); MBAR_INIT(smem_u32(&s_mbar[1]), 1); }
    __syncthreads();
    const uint32_t tmem = s_tptr;
    const uint32_t mb0 = smem_u32(&s_mbar[0]), mb1 = smem_u32(&s_mbar[1]);

    const int NC = K >> 5;
    int ph0 = 0, ph1 = 0;

    for (int c = 0; c < NC; ++c) {
        const int buf = c & 1;
        if (c >= 2) {
            if (buf == 0) { MBAR_WAIT(mb0, ph0 & 1); ph0++; }
            else          { MBAR_WAIT(mb1, ph1 & 1); ph1++; }
        }
        float* As = sm + buf * 8192;
        float* Bs = As + 4096;
        const float* Ag = A  + (size_t)m0 * K + c * 32;
        const float* Bg = Wt + (size_t)n0 * K + c * 32;
        #pragma unroll
        for (int i = 0; i < 8; ++i) {
            int idx = tid + i * 128;
            int row = idx >> 3, c4 = idx & 7;
            int off = row * 128 + c4 * 16;
            int sw = off ^ ((off >> 3) & 0x70);
            float4 v = *(const float4*)(Ag + (size_t)row * K + c4 * 4);
            v.x = cvt_tf32(v.x); v.y = cvt_tf32(v.y);
            v.z = cvt_tf32(v.z); v.w = cvt_tf32(v.w);
            *(float4*)((char*)As + sw) = v;
            *(float4*)((char*)Bs + sw) = *(const float4*)(Bg + (size_t)row * K + c4 * 4);
        }
        __syncthreads();
        if (wid == 0 && elect_one_pred()) {
            FENCE_ASYNC();
            uint64_t ad = make_desc(smb + buf * 32768);
            uint64_t bd = make_desc(smb + buf * 32768 + 16384);
            #pragma unroll
            for (int s = 0; s < 4; ++s)
                TC_MMA_TF32(tmem, ad + 2 * s, bd + 2 * s, IDESC_T, (c > 0) || (s > 0));
            TC_COMMIT(buf ? mb1 : mb0);
        }
    }
    MBAR_WAIT(mb0, ph0 & 1);
    MBAR_WAIT(mb1, ph1 & 1);
    TC_FENCE_AFTER();
    __syncthreads();

    for (int cg = 0; cg < 4; ++cg) {
        uint32_t r[32];
        TC_LD_X32(r, tmem + cg * 32);
        TC_WAIT_LD();
        int ml = (wid << 5) | lane;
        #pragma unroll
        for (int c2 = 0; c2 < 32; ++c2) sm[ml * 33 + c2] = __uint_as_float(r[c2]);
        __syncthreads();

        const int m = m0 + tid;
        const int nb = n0 + cg * 32;
        if (MODE == 0) {
            const int which = nb >> 9;
            const int hh = (nb >> 6) & 7;
            const int db = nb & 63;
            const float* bp = (which == 0) ? bias0 : (which == 1) ? bias1 : bias2;
            float* outw     = (which == 0) ? out0  : (which == 1) ? out1  : out2;
            const int b_ = m >> 12, l = m & (SEQ - 1);
            float* dst = outw + ((size_t)(b_ * NHEAD + hh) * SEQ + l) * DH + db;
            const int bb = nb & 511;
            #pragma unroll
            for (int c2 = 0; c2 < 32; ++c2)
                dst[c2] = sm[tid * 33 + c2] + bp[bb + c2];
        } else if (MODE == 2) {
            float* dst = out0 + (size_t)m * N + nb;
            const float* rs = resid + (size_t)m * N + nb;
            #pragma unroll
            for (int c2 = 0; c2 < 32; ++c2)
                dst[c2] = sm[tid * 33 + c2] + bias0[nb + c2] + rs[c2];
        } else {
            float* dst = out0 + (size_t)m * N + nb;
            #pragma unroll
            for (int c2 = 0; c2 < 32; ++c2)
                dst[c2] = gelu_f(sm[tid * 33 + c2] + bias0[nb + c2]);
        }
        __syncthreads();
    }

    if (wid == 0) TC_DEALLOC(tmem, 128);

#else
    // ---------- SIMT f32x2 fallback: two 128x64 passes, 8x8 frags ----------
    float* As = sm;              // [16][132] transposed A
    float* Bs = sm + 16 * 132;   // [16][68]
    const int ty = tid >> 3, tx = tid & 7;

    for (int pass = 0; pass < 2; ++pass) {
        const int np = n0 + pass * 64;
        u64 acc[4][8];
        #pragma unroll
        for (int p = 0; p < 4; ++p)
            #pragma unroll
            for (int j = 0; j < 8; ++j) acc[p][j] = 0ULL;

        for (int k0 = 0; k0 < K; k0 += 16) {
            __syncthreads();
            #pragma unroll
            for (int s = 0; s < 4; ++s) {
                int idx = tid + s * 128;
                int mr = idx >> 2, kg = idx & 3;
                float4 av = *(const float4*)(A + (size_t)(m0 + mr) * K + k0 + kg * 4);
                As[(kg * 4 + 0) * 132 + mr] = av.x;
                As[(kg * 4 + 1) * 132 + mr] = av.y;
                As[(kg * 4 + 2) * 132 + mr] = av.z;
                As[(kg * 4 + 3) * 132 + mr] = av.w;
            }
            #pragma unroll
            for (int s = 0; s < 2; ++s) {
                int idx = tid + s * 128;
                int nr = idx >> 2, kg = idx & 3;
                float4 bv = *(const float4*)(Wt + (size_t)(np + nr) * K + k0 + kg * 4);
                Bs[(kg * 4 + 0) * 68 + nr] = bv.x;
                Bs[(kg * 4 + 1) * 68 + nr] = bv.y;
                Bs[(kg * 4 + 2) * 68 + nr] = bv.z;
                Bs[(kg * 4 + 3) * 68 + nr] = bv.w;
            }
            __syncthreads();
            #pragma unroll
            for (int kk = 0; kk < 16; ++kk) {
                const float* ap = &As[kk * 132 + ty * 8];
                ulonglong2 a01 = *(const ulonglong2*)ap;
                ulonglong2 a23 = *(const ulonglong2*)(ap + 4);
                u64 aq[4] = {a01.x, a01.y, a23.x, a23.y};
                const float* bp = &Bs[kk * 68 + tx * 8];
                float4 b0 = *(const float4*)bp;
                float4 b1 = *(const float4*)(bp + 4);
                float bf[8] = {b0.x, b0.y, b0.z, b0.w, b1.x, b1.y, b1.z, b1.w};
                #pragma unroll
                for (int j = 0; j < 8; ++j) {
                    u64 bd = pack2(bf[j], bf[j]);
                    #pragma unroll
                    for (int p = 0; p < 4; ++p) FMA2(acc[p][j], aq[p], bd);
                }
            }
        }

        #pragma unroll
        for (int p = 0; p < 4; ++p) {
            float c0[8], c1[8];
            #pragma unroll
            for (int j = 0; j < 8; ++j) unpack2(acc[p][j], c0[j], c1[j]);
            #pragma unroll
            for (int half = 0; half < 2; ++half) {
                float* cc = half ? c1 : c0;
                int m = m0 + ty * 8 + 2 * p + half;
                #pragma unroll
                for (int j = 0; j < 8; ++j) {
                    int n = np + tx * 8 + j;
                    float v = cc[j];
                    if (MODE == 0) {
                        const int which = n >> 9;
                        const float* bp2 = (which == 0) ? bias0 : (which == 1) ? bias1 : bias2;
                        float* outw     = (which == 0) ? out0  : (which == 1) ? out1  : out2;
                        v += bp2[n & 511];
                        int b_ = m >> 12, l = m & (SEQ - 1);
                        int hh = (n >> 6) & 7, db = n & 63;
                        outw[((size_t)(b_ * NHEAD + hh) * SEQ + l) * DH + db] = v;
                    } else if (MODE == 2) {
                        out0[(size_t)m * N + n] = v + bias0[n] + resid[(size_t)m * N + n];
                    } else {
                        out0[(size_t)m * N + n] = gelu_f(v + bias0[n]);
                    }
                }
            }
        }
        __syncthreads();
    }
#endif
}

// ---------------- flash attention (f32x2 SIMT, unchanged) ----------------------
#define QST 132
#define KST 68
#define PST 132
#define SMEM_ATTN ((64*QST + 64*KST + 64*64 + 64*PST) * 4 + 64 * 4)

__global__ __launch_bounds__(128)
void attn_k(const float* __restrict__ q, const float* __restrict__ k,
            const float* __restrict__ v, const int* __restrict__ mask,
            float* __restrict__ ctx)
{
    extern __shared__ float smA[];
    float* Qs = smA;
    float* Ks = Qs + 64 * QST;
    float* Vs = Ks + 64 * KST;
    float* Ps = Vs + 64 * 64;
    int*   Ms = (int*)(Ps + 64 * PST);

    const int qt = blockIdx.x, h = blockIdx.y, b = blockIdx.z;
    const int tid = threadIdx.x;
    const int ty = tid >> 3, tx = tid & 7;

    const float* qb = q + ((size_t)(b * NHEAD + h) * SEQ) * DH;
    const float* kb = k + ((size_t)(b * NHEAD + h) * SEQ) * DH;
    const float* vb = v + ((size_t)(b * NHEAD + h) * SEQ) * DH;

    for (int idx = tid; idx < 2048; idx += 128) {
        int qr = idx >> 4, dg = idx & 15;
        float4 val = *(const float4*)(qb + (size_t)(qt * 128 + qr) * DH + dg * 4);
        Qs[(dg * 4 + 0) * QST + qr] = val.x * 0.125f;
        Qs[(dg * 4 + 1) * QST + qr] = val.y * 0.125f;
        Qs[(dg * 4 + 2) * QST + qr] = val.z * 0.125f;
        Qs[(dg * 4 + 3) * QST + qr] = val.w * 0.125f;
    }

    u64 O2[8][4];
    float m_[8], l_[8];
    #pragma unroll
    for (int i = 0; i < 8; ++i) {
        m_[i] = -1e30f; l_[i] = 0.f;
        #pragma unroll
        for (int jp = 0; jp < 4; ++jp) O2[i][jp] = 0ULL;
    }

    for (int t = 0; t < SEQ / 64; ++t) {
        __syncthreads();
        for (int idx = tid; idx < 1024; idx += 128) {
            int kr = idx >> 4, dg = idx & 15;
            float4 kv = *(const float4*)(kb + (size_t)(t * 64 + kr) * DH + dg * 4);
            Ks[(dg * 4 + 0) * KST + kr] = kv.x;
            Ks[(dg * 4 + 1) * KST + kr] = kv.y;
            Ks[(dg * 4 + 2) * KST + kr] = kv.z;
            Ks[(dg * 4 + 3) * KST + kr] = kv.w;
        }
        for (int idx = tid; idx < 1024; idx += 128)
            *(float4*)&Vs[idx * 4] = *(const float4*)(vb + (size_t)t * 64 * DH + idx * 4);
        if (tid < 64) Ms[tid] = mask[b * SEQ + t * 64 + tid];
        __syncthreads();

        u64 acc[4][8];
        #pragma unroll
        for (int p = 0; p < 4; ++p)
            #pragma unroll
            for (int j = 0; j < 8; ++j) acc[p][j] = 0ULL;

        #pragma unroll 4
        for (int kk = 0; kk < 64; ++kk) {
            const float* qp = &Qs[kk * QST + ty * 8];
            ulonglong2 qa = *(const ulonglong2*)qp;
            ulonglong2 qc = *(const ulonglong2*)(qp + 4);
            u64 qq[4] = {qa.x, qa.y, qc.x, qc.y};
            const float* kp = &Ks[kk * KST + tx * 8];
            float4 k0 = *(const float4*)kp;
            float4 k1 = *(const float4*)(kp + 4);
            float kf[8] = {k0.x, k0.y, k0.z, k0.w, k1.x, k1.y, k1.z, k1.w};
            #pragma unroll
            for (int j = 0; j < 8; ++j) {
                u64 kd = pack2(kf[j], kf[j]);
                #pragma unroll
                for (int p = 0; p < 4; ++p) FMA2(acc[p][j], qq[p], kd);
            }
        }

        float S[8][8];
        #pragma unroll
        for (int p = 0; p < 4; ++p)
            #pragma unroll
            for (int j = 0; j < 8; ++j) unpack2(acc[p][j], S[2 * p][j], S[2 * p + 1][j]);

        #pragma unroll
        for (int j = 0; j < 8; ++j) {
            if (Ms[tx * 8 + j] == 0) {
                #pragma unroll
                for (int i = 0; i < 8; ++i) S[i][j] = -1e9f;
            }
        }

        #pragma unroll
        for (int i = 0; i < 8; ++i) {
            float rmax = S[i][0];
            #pragma unroll
            for (int j = 1; j < 8; ++j) rmax = fmaxf(rmax, S[i][j]);
            rmax = fmaxf(rmax, __shfl_xor_sync(0xffffffffu, rmax, 1));
            rmax = fmaxf(rmax, __shfl_xor_sync(0xffffffffu, rmax, 2));
            rmax = fmaxf(rmax, __shfl_xor_sync(0xffffffffu, rmax, 4));
            float mn = fmaxf(m_[i], rmax);
            float al = __expf(m_[i] - mn);
            m_[i] = mn;
            l_[i] *= al;
            u64 ad = pack2(al, al);
            #pragma unroll
            for (int jp = 0; jp < 4; ++jp) MUL2(O2[i][jp], ad);
            float rs = 0.f;
            #pragma unroll
            for (int j = 0; j < 8; ++j) {
                float pv = __expf(S[i][j] - mn);
                S[i][j] = pv;
                rs += pv;
            }
            rs += __shfl_xor_sync(0xffffffffu, rs, 1);
            rs += __shfl_xor_sync(0xffffffffu, rs, 2);
            rs += __shfl_xor_sync(0xffffffffu, rs, 4);
            l_[i] += rs;
        }

        #pragma unroll
        for (int j = 0; j < 8; ++j) {
            float* pd = &Ps[(tx * 8 + j) * PST + ty * 8];
            *(float4*)pd       = make_float4(S[0][j], S[1][j], S[2][j], S[3][j]);
            *(float4*)(pd + 4) = make_float4(S[4][j], S[5][j], S[6][j], S[7][j]);
        }
        __syncthreads();

        #pragma unroll 4
        for (int kk = 0; kk < 64; ++kk) {
            const float* pp = &Ps[kk * PST + ty * 8];
            float4 p0 = *(const float4*)pp;
            float4 p1 = *(const float4*)(pp + 4);
            float pf[8] = {p0.x, p0.y, p0.z, p0.w, p1.x, p1.y, p1.z, p1.w};
            const float* vp = &Vs[kk * 64 + tx * 8];
            ulonglong2 v01 = *(const ulonglong2*)vp;
            ulonglong2 v23 = *(const ulonglong2*)(vp + 4);
            u64 vv[4] = {v01.x, v01.y, v23.x, v23.y};
            #pragma unroll
            for (int i = 0; i < 8; ++i) {
                u64 pd = pack2(pf[i], pf[i]);
                #pragma unroll
                for (int jp = 0; jp < 4; ++jp) FMA2(O2[i][jp], pd, vv[jp]);
            }
        }
    }

    #pragma unroll
    for (int i = 0; i < 8; ++i) {
        float inv = 1.f / l_[i];
        float o[8];
        #pragma unroll
        for (int jp = 0; jp < 4; ++jp) unpack2(O2[i][jp], o[2 * jp], o[2 * jp + 1]);
        int row = b * SEQ + qt * 128 + ty * 8 + i;
        float* dst = ctx + (size_t)row * D_EMBED + h * DH + tx * 8;
        *(float4*)dst       = make_float4(o[0] * inv, o[1] * inv, o[2] * inv, o[3] * inv);
        *(float4*)(dst + 4) = make_float4(o[4] * inv, o[5] * inv, o[6] * inv, o[7] * inv);
    }
}

// ---------------- LayerNorm -----------------------------------------------------
__global__ __launch_bounds__(128)
void ln_k(const float* __restrict__ in, const float* __restrict__ gam,
          const float* __restrict__ bet, float* __restrict__ out)
{
    const int row = blockIdx.x;
    const int tid = threadIdx.x;
    float4 vx = ((const float4*)(in + (size_t)row * D_EMBED))[tid];
    float s  = vx.x + vx.y + vx.z + vx.w;
    float ss = vx.x * vx.x + vx.y * vx.y + vx.z * vx.z + vx.w * vx.w;
    #pragma unroll
    for (int o = 16; o; o >>= 1) {
        s  += __shfl_xor_sync(0xffffffffu, s, o);
        ss += __shfl_xor_sync(0xffffffffu, ss, o);
    }
    __shared__ float sh[8];
    if ((tid & 31) == 0) { sh[tid >> 5] = s; sh[4 + (tid >> 5)] = ss; }
    __syncthreads();
    float S  = sh[0] + sh[1] + sh[2] + sh[3];
    float SS = sh[4] + sh[5] + sh[6] + sh[7];
    float mu   = S * (1.f / 512.f);
    float var  = SS * (1.f / 512.f) - mu * mu;
    float rstd = rsqrtf(var + 1e-5f);
    float4 g  = ((const float4*)gam)[tid];
    float4 bb = ((const float4*)bet)[tid];
    float4 o;
    o.x = (vx.x - mu) * rstd * g.x + bb.x;
    o.y = (vx.y - mu) * rstd * g.y + bb.y;
    o.z = (vx.z - mu) * rstd * g.z + bb.z;
    o.w = (vx.w - mu) * rstd * g.w + bb.w;
    ((float4*)(out + (size_t)row * D_EMBED))[tid] = o;
}

// ---------------- launcher -------------------------------------------------------
extern "C" void kernel_launch(void* const* d_in, const int* in_sizes, int n_in,
                              void* d_out, int out_size)
{
    const float* x    = (const float*)d_in[0];
    const int*   mask = (const int*)  d_in[1];
    const float* Wq   = (const float*)d_in[2];
    const float* bq   = (const float*)d_in[3];
    const float* Wk   = (const float*)d_in[4];
    const float* bk   = (const float*)d_in[5];
    const float* Wv   = (const float*)d_in[6];
    const float* bv   = (const float*)d_in[7];
    const float* Wo   = (const float*)d_in[8];
    const float* bo   = (const float*)d_in[9];

    const float *ln1g, *ln1b, *ln2g, *ln2b, *W1, *b1, *W2, *b2;
    if (in_sizes[12] == D_EMBED * DFF) {
        ln1g = (const float*)d_in[10]; ln1b = (const float*)d_in[11];
        W1   = (const float*)d_in[12]; b1   = (const float*)d_in[13];
        W2   = (const float*)d_in[14]; b2   = (const float*)d_in[15];
        ln2g = (const float*)d_in[16]; ln2b = (const float*)d_in[17];
    } else {
        ln1g = (const float*)d_in[10]; ln1b = (const float*)d_in[11];
        ln2g = (const float*)d_in[12]; ln2b = (const float*)d_in[13];
        W1   = (const float*)d_in[14]; b1   = (const float*)d_in[15];
        W2   = (const float*)d_in[16]; b2   = (const float*)d_in[17];
    }

    float *q, *k, *v, *ctx, *res1, *h, *ff, *res2;
    float *wqkvt, *wot, *w1t, *w2t;
    cudaGetSymbolAddress((void**)&q,    g_q);
    cudaGetSymbolAddress((void**)&k,    g_k);
    cudaGetSymbolAddress((void**)&v,    g_v);
    cudaGetSymbolAddress((void**)&ctx,  g_ctx);
    cudaGetSymbolAddress((void**)&res1, g_res1);
    cudaGetSymbolAddress((void**)&h,    g_h);
    cudaGetSymbolAddress((void**)&ff,   g_ff);
    cudaGetSymbolAddress((void**)&res2, g_res2);
    cudaGetSymbolAddress((void**)&wqkvt, g_wqkvt);
    cudaGetSymbolAddress((void**)&wot,   g_wot);
    cudaGetSymbolAddress((void**)&w1t,   g_w1t);
    cudaGetSymbolAddress((void**)&w2t,   g_w2t);

    static bool attr_done = false;
    if (!attr_done) {
        cudaFuncSetAttribute(attn_k,   cudaFuncAttributeMaxDynamicSharedMemorySize, SMEM_ATTN);
        cudaFuncSetAttribute(gemmT<0>, cudaFuncAttributeMaxDynamicSharedMemorySize, 65536);
        cudaFuncSetAttribute(gemmT<2>, cudaFuncAttributeMaxDynamicSharedMemorySize, 65536);
        cudaFuncSetAttribute(gemmT<3>, cudaFuncAttributeMaxDynamicSharedMemorySize, 65536);
        attr_done = true;
    }

    transpose_cvt<<<dim3(16, 16), 256>>>(Wq, wqkvt,                   512, 512);
    transpose_cvt<<<dim3(16, 16), 256>>>(Wk, wqkvt + 512 * 512,       512, 512);
    transpose_cvt<<<dim3(16, 16), 256>>>(Wv, wqkvt + 2 * 512 * 512,   512, 512);
    transpose_cvt<<<dim3(16, 16), 256>>>(Wo, wot,                     512, 512);
    transpose_cvt<<<dim3(64, 16), 256>>>(W1, w1t,                     512, 2048);
    transpose_cvt<<<dim3(16, 64), 256>>>(W2, w2t,                    2048, 512);

    gemmT<0><<<dim3(12, 64), 128, 65536>>>(x, wqkvt, bq, bk, bv, nullptr,
                                           q, k, v, 3 * D_EMBED, D_EMBED);

    attn_k<<<dim3(SEQ / 128, NHEAD, BATCH), 128, SMEM_ATTN>>>(q, k, v, mask, ctx);

    gemmT<2><<<dim3(4, 64), 128, 65536>>>(ctx, wot, bo, nullptr, nullptr, x,
                                          res1, nullptr, nullptr, D_EMBED, D_EMBED);
    ln_k<<<NROWS, 128>>>(res1, ln1g, ln1b, h);

    gemmT<3><<<dim3(16, 64), 128, 65536>>>(h, w1t, b1, nullptr, nullptr, nullptr,
                                           ff, nullptr, nullptr, DFF, D_EMBED);
    gemmT<2><<<dim3(4, 64), 128, 65536>>>(ff, w2t, b2, nullptr, nullptr, h,
                                          res2, nullptr, nullptr, D_EMBED, DFF);
    ln_k<<<NROWS, 128>>>(res2, ln2g, ln2b, (float*)d_out);
}

// round 5
// speedup vs baseline: 5.0539x; 1.9053x over previous
#include <cuda_runtime.h>
#include <math.h>
#include <stdint.h>

#define D_EMBED 512
#define NHEAD   8
#define DH      64
#define DFF     2048
#define BATCH   2
#define SEQ     4096
#define NROWS   (BATCH*SEQ)   // 8192

// ---- arch feature detection: tcgen05 only exists in the sm_103a-specific pass --
#if defined(__CUDA_ARCH__)
# if defined(__CUDA_ARCH_HAS_FEATURE__)
#  if __CUDA_ARCH_HAS_FEATURE__(SM103_ALL)
#   define HAS_TC 1
#  endif
# endif
# if !defined(HAS_TC) && defined(__CUDA_ARCH_SPECIFIC__)
#  define HAS_TC 1
# endif
#endif
#ifndef HAS_TC
# define HAS_TC 0
#endif

// ---------------- scratch ------------------------------------------------------
__device__ float g_q[BATCH*NHEAD*SEQ*DH];
__device__ float g_k[BATCH*NHEAD*SEQ*DH];
__device__ float g_v[BATCH*NHEAD*SEQ*DH];
__device__ float g_ctx[NROWS*D_EMBED];
__device__ float g_res1[NROWS*D_EMBED];
__device__ float g_h[NROWS*D_EMBED];
__device__ float g_ff[(size_t)NROWS*DFF];
__device__ float g_res2[NROWS*D_EMBED];
__device__ float g_wqkvt[3*D_EMBED*D_EMBED];
__device__ float g_wot[D_EMBED*D_EMBED];
__device__ float g_w1t[DFF*D_EMBED];
__device__ float g_w2t[D_EMBED*DFF];

// ---------------- common helpers -----------------------------------------------
typedef unsigned long long u64;
__device__ __forceinline__ u64 pack2(float x, float y) {
    u64 r; asm("mov.b64 %0, {%1, %2};" : "=l"(r) : "f"(x), "f"(y)); return r;
}
__device__ __forceinline__ void unpack2(u64 v, float& x, float& y) {
    asm("mov.b64 {%0, %1}, %2;" : "=f"(x), "=f"(y) : "l"(v));
}
#define FMA2(d, a, b) asm("fma.rn.f32x2 %0, %1, %2, %0;" : "+l"(d) : "l"(a), "l"(b))
#define MUL2(d, a)    asm("mul.rn.f32x2 %0, %0, %1;"     : "+l"(d) : "l"(a))

__device__ __forceinline__ float cvt_tf32(float x) {
    uint32_t u; asm("cvt.rna.tf32.f32 %0, %1;" : "=r"(u) : "f"(x));
    return __uint_as_float(u);
}
__device__ __forceinline__ uint32_t cvt_tf32_bits(float x) {
    uint32_t u; asm("cvt.rna.tf32.f32 %0, %1;" : "=r"(u) : "f"(x));
    return u;
}
__device__ __forceinline__ float gelu_f(float x) {
    return 0.5f * x * (1.0f + erff(x * 0.70710678118654752f));
}
__device__ __forceinline__ uint32_t smem_u32(const void* p) {
    uint32_t a;
    asm("{ .reg .u64 t; cvta.to.shared.u64 t, %1; cvt.u32.u64 %0, t; }" : "=r"(a) : "l"(p));
    return a;
}

#if HAS_TC
__device__ __forceinline__ uint32_t elect_one_pred() {
    uint32_t pred;
    asm volatile("{\n\t.reg .pred p;\n\telect.sync _|p, 0xFFFFFFFF;\n\t"
                 "selp.b32 %0, 1, 0, p;\n\t}" : "=r"(pred));
    return pred;
}
#define MBAR_INIT(a, n) asm volatile("mbarrier.init.shared.b64 [%0], %1;" :: "r"(a), "r"(n) : "memory")
#define MBAR_WAIT(a, par) do { \
    uint32_t _m = (a), _p = (par), _d; \
    asm volatile("{\n\t.reg .pred p;\n\t" \
        "mbarrier.try_wait.parity.acquire.cta.shared::cta.b64 p, [%1], %2;\n\t" \
        "selp.b32 %0, 1, 0, p;\n\t}" : "=r"(_d) : "r"(_m), "r"(_p) : "memory"); \
    if (!_d) { asm volatile("{\n\t.reg .pred P1;\n\tWL_%=:\n\t" \
        "mbarrier.try_wait.parity.acquire.cta.shared::cta.b64 P1, [%0], %1, 0x989680;\n\t" \
        "@P1 bra.uni WD_%=;\n\tbra.uni WL_%=;\n\tWD_%=:\n\t}" \
        :: "r"(_m), "r"(_p) : "memory"); } \
} while (0)

#define TC_ALLOC(sa, n)   asm volatile("tcgen05.alloc.cta_group::1.sync.aligned.shared::cta.b32 [%0], %1;" :: "r"(sa), "r"(n) : "memory")
#define TC_DEALLOC(t, n)  asm volatile("tcgen05.dealloc.cta_group::1.sync.aligned.b32 %0, %1;" :: "r"(t), "r"(n))
#define TC_COMMIT(mb)     asm volatile("tcgen05.commit.cta_group::1.mbarrier::arrive::one.shared::cluster.b64 [%0];" :: "r"(mb) : "memory")
#define TC_FENCE_AFTER()  asm volatile("tcgen05.fence::after_thread_sync;" ::: "memory")
#define TC_FENCE_BEFORE() asm volatile("tcgen05.fence::before_thread_sync;" ::: "memory")
#define TC_WAIT_LD()      asm volatile("tcgen05.wait::ld.sync.aligned;" ::: "memory")
#define TC_WAIT_ST()      asm volatile("tcgen05.wait::st.sync.aligned;" ::: "memory")
#define FENCE_ASYNC()     asm volatile("fence.proxy.async.shared::cta;" ::: "memory")

#define TC_LD_X32(r, ta) \
    asm volatile("tcgen05.ld.sync.aligned.32x32b.x32.b32 " \
        "{%0, %1, %2, %3, %4, %5, %6, %7, %8, %9, %10, %11, %12, %13, %14, %15, " \
        " %16, %17, %18, %19, %20, %21, %22, %23, %24, %25, %26, %27, %28, %29, %30, %31}, [%32];" \
        : "=r"((r)[0]), "=r"((r)[1]), "=r"((r)[2]), "=r"((r)[3]), \
          "=r"((r)[4]), "=r"((r)[5]), "=r"((r)[6]), "=r"((r)[7]), \
          "=r"((r)[8]), "=r"((r)[9]), "=r"((r)[10]), "=r"((r)[11]), \
          "=r"((r)[12]), "=r"((r)[13]), "=r"((r)[14]), "=r"((r)[15]), \
          "=r"((r)[16]), "=r"((r)[17]), "=r"((r)[18]), "=r"((r)[19]), \
          "=r"((r)[20]), "=r"((r)[21]), "=r"((r)[22]), "=r"((r)[23]), \
          "=r"((r)[24]), "=r"((r)[25]), "=r"((r)[26]), "=r"((r)[27]), \
          "=r"((r)[28]), "=r"((r)[29]), "=r"((r)[30]), "=r"((r)[31]) \
        : "r"(ta))

#define TC_ST_X32(ta, r) \
    asm volatile("tcgen05.st.sync.aligned.32x32b.x32.b32 [%0], " \
        "{%1, %2, %3, %4, %5, %6, %7, %8, %9, %10, %11, %12, %13, %14, %15, %16, " \
        " %17, %18, %19, %20, %21, %22, %23, %24, %25, %26, %27, %28, %29, %30, %31, %32};" \
        :: "r"(ta), \
           "r"((r)[0]), "r"((r)[1]), "r"((r)[2]), "r"((r)[3]), \
           "r"((r)[4]), "r"((r)[5]), "r"((r)[6]), "r"((r)[7]), \
           "r"((r)[8]), "r"((r)[9]), "r"((r)[10]), "r"((r)[11]), \
           "r"((r)[12]), "r"((r)[13]), "r"((r)[14]), "r"((r)[15]), \
           "r"((r)[16]), "r"((r)[17]), "r"((r)[18]), "r"((r)[19]), \
           "r"((r)[20]), "r"((r)[21]), "r"((r)[22]), "r"((r)[23]), \
           "r"((r)[24]), "r"((r)[25]), "r"((r)[26]), "r"((r)[27]), \
           "r"((r)[28]), "r"((r)[29]), "r"((r)[30]), "r"((r)[31]) \
        : "memory")

#define TC_MMA_TF32(dt, ad, bd, id, en) do { \
    uint32_t _e = (en) ? 1u : 0u; \
    asm volatile("{\n\t.reg .pred p;\n\tsetp.ne.u32 p, %5, 0;\n\t" \
        "tcgen05.mma.cta_group::1.kind::tf32 [%0], %1, %2, %3, {%4, %4, %4, %4}, p;\n\t}" \
        :: "r"(dt), "l"(ad), "l"(bd), "r"(id), "r"(0u), "r"(_e) : "memory"); \
} while (0)

#define TC_MMA_TF32_TS(dt, at, bd, id, en) do { \
    uint32_t _e = (en) ? 1u : 0u; \
    asm volatile("{\n\t.reg .pred p;\n\tsetp.ne.u32 p, %5, 0;\n\t" \
        "tcgen05.mma.cta_group::1.kind::tf32 [%0], [%1], %2, %3, {%4, %4, %4, %4}, p;\n\t}" \
        :: "r"(dt), "r"(at), "l"(bd), "r"(id), "r"(0u), "r"(_e) : "memory"); \
} while (0)

__device__ __forceinline__ uint64_t make_desc(uint32_t addr) {
    return ((uint64_t)2 << 61) | ((uint64_t)1 << 46) | ((uint64_t)64 << 32) |
           ((uint64_t)1 << 16) | (uint64_t)((addr >> 4) & 0x3FFF);
}
#define IDESC_T  ((1u << 4) | (2u << 7) | (2u << 10) | ((128u / 8) << 17) | ((128u / 16) << 24))
#define IDESC_QK ((1u << 4) | (2u << 7) | (2u << 10) | (16u << 17) | (8u << 24))
#define IDESC_PV ((1u << 4) | (2u << 7) | (2u << 10) | (8u  << 17) | (8u << 24))
#endif // HAS_TC

// ---------------- weight transpose + tf32 round --------------------------------
__global__ __launch_bounds__(256)
void transpose_cvt(const float* __restrict__ src, float* __restrict__ dst, int R, int C)
{
    __shared__ float t[32][33];
    int r0 = blockIdx.y * 32, c0 = blockIdx.x * 32;
    int tx = threadIdx.x & 31, ty = threadIdx.x >> 5;
    #pragma unroll
    for (int i = 0; i < 32; i += 8)
        t[ty + i][tx] = src[(size_t)(r0 + ty + i) * C + c0 + tx];
    __syncthreads();
    #pragma unroll
    for (int i = 0; i < 32; i += 8)
        dst[(size_t)(c0 + ty + i) * R + r0 + tx] = cvt_tf32(t[tx][ty + i]);
}

// ---------------- linear GEMM (tcgen05 TF32 / SIMT fallback), as R4 ------------
template<int MODE>
__global__ __launch_bounds__(128)
void gemmT(const float* __restrict__ A, const float* __restrict__ Wt,
           const float* __restrict__ bias0, const float* __restrict__ bias1,
           const float* __restrict__ bias2, const float* __restrict__ resid,
           float* __restrict__ out0, float* __restrict__ out1, float* __restrict__ out2,
           int N, int K)
{
    extern __shared__ __align__(1024) float sm[];
    const int tid = threadIdx.x, wid = tid >> 5, lane = tid & 31;
    const int n0 = blockIdx.x * 128, m0 = blockIdx.y * 128;

#if HAS_TC
    __shared__ uint32_t s_tptr;
    __shared__ unsigned long long s_mbar[2];
    const uint32_t smb = smem_u32(sm);

    if (wid == 0) TC_ALLOC(smem_u32(&s_tptr), 128);
    if (tid == 0) { MBAR_INIT(smem_u32(&s_mbar[0]), 1); MBAR_INIT(smem_u32(&s_mbar[1]), 1); }
    __syncthreads();
    const uint32_t tmem = s_tptr;
    const uint32_t mb0 = smem_u32(&s_mbar[0]), mb1 = smem_u32(&s_mbar[1]);

    const int NC = K >> 5;
    int ph0 = 0, ph1 = 0;

    for (int c = 0; c < NC; ++c) {
        const int buf = c & 1;
        if (c >= 2) {
            if (buf == 0) { MBAR_WAIT(mb0, ph0 & 1); ph0++; }
            else          { MBAR_WAIT(mb1, ph1 & 1); ph1++; }
        }
        float* As = sm + buf * 8192;
        float* Bs = As + 4096;
        const float* Ag = A  + (size_t)m0 * K + c * 32;
        const float* Bg = Wt + (size_t)n0 * K + c * 32;
        #pragma unroll
        for (int i = 0; i < 8; ++i) {
            int idx = tid + i * 128;
            int row = idx >> 3, c4 = idx & 7;
            int off = row * 128 + c4 * 16;
            int sw = off ^ ((off >> 3) & 0x70);
            float4 v = *(const float4*)(Ag + (size_t)row * K + c4 * 4);
            v.x = cvt_tf32(v.x); v.y = cvt_tf32(v.y);
            v.z = cvt_tf32(v.z); v.w = cvt_tf32(v.w);
            *(float4*)((char*)As + sw) = v;
            *(float4*)((char*)Bs + sw) = *(const float4*)(Bg + (size_t)row * K + c4 * 4);
        }
        __syncthreads();
        if (wid == 0 && elect_one_pred()) {
            FENCE_ASYNC();
            uint64_t ad = make_desc(smb + buf * 32768);
            uint64_t bd = make_desc(smb + buf * 32768 + 16384);
            #pragma unroll
            for (int s = 0; s < 4; ++s)
                TC_MMA_TF32(tmem, ad + 2 * s, bd + 2 * s, IDESC_T, (c > 0) || (s > 0));
            TC_COMMIT(buf ? mb1 : mb0);
        }
    }
    MBAR_WAIT(mb0, ph0 & 1);
    MBAR_WAIT(mb1, ph1 & 1);
    TC_FENCE_AFTER();
    __syncthreads();

    for (int cg = 0; cg < 4; ++cg) {
        uint32_t r[32];
        TC_LD_X32(r, tmem + cg * 32);
        TC_WAIT_LD();
        int ml = (wid << 5) | lane;
        #pragma unroll
        for (int c2 = 0; c2 < 32; ++c2) sm[ml * 33 + c2] = __uint_as_float(r[c2]);
        __syncthreads();

        const int m = m0 + tid;
        const int nb = n0 + cg * 32;
        if (MODE == 0) {
            const int which = nb >> 9;
            const int hh = (nb >> 6) & 7;
            const int db = nb & 63;
            const float* bp = (which == 0) ? bias0 : (which == 1) ? bias1 : bias2;
            float* outw     = (which == 0) ? out0  : (which == 1) ? out1  : out2;
            const int b_ = m >> 12, l = m & (SEQ - 1);
            float* dst = outw + ((size_t)(b_ * NHEAD + hh) * SEQ + l) * DH + db;
            const int bb = nb & 511;
            #pragma unroll
            for (int c2 = 0; c2 < 32; ++c2)
                dst[c2] = sm[tid * 33 + c2] + bp[bb + c2];
        } else if (MODE == 2) {
            float* dst = out0 + (size_t)m * N + nb;
            const float* rs = resid + (size_t)m * N + nb;
            #pragma unroll
            for (int c2 = 0; c2 < 32; ++c2)
                dst[c2] = sm[tid * 33 + c2] + bias0[nb + c2] + rs[c2];
        } else {
            float* dst = out0 + (size_t)m * N + nb;
            #pragma unroll
            for (int c2 = 0; c2 < 32; ++c2)
                dst[c2] = gelu_f(sm[tid * 33 + c2] + bias0[nb + c2]);
        }
        __syncthreads();
    }

    if (wid == 0) TC_DEALLOC(tmem, 128);

#else
    float* As = sm;
    float* Bs = sm + 16 * 132;
    const int ty = tid >> 3, tx = tid & 7;

    for (int pass = 0; pass < 2; ++pass) {
        const int np = n0 + pass * 64;
        u64 acc[4][8];
        #pragma unroll
        for (int p = 0; p < 4; ++p)
            #pragma unroll
            for (int j = 0; j < 8; ++j) acc[p][j] = 0ULL;

        for (int k0 = 0; k0 < K; k0 += 16) {
            __syncthreads();
            #pragma unroll
            for (int s = 0; s < 4; ++s) {
                int idx = tid + s * 128;
                int mr = idx >> 2, kg = idx & 3;
                float4 av = *(const float4*)(A + (size_t)(m0 + mr) * K + k0 + kg * 4);
                As[(kg * 4 + 0) * 132 + mr] = av.x;
                As[(kg * 4 + 1) * 132 + mr] = av.y;
                As[(kg * 4 + 2) * 132 + mr] = av.z;
                As[(kg * 4 + 3) * 132 + mr] = av.w;
            }
            #pragma unroll
            for (int s = 0; s < 2; ++s) {
                int idx = tid + s * 128;
                int nr = idx >> 2, kg = idx & 3;
                float4 bv = *(const float4*)(Wt + (size_t)(np + nr) * K + k0 + kg * 4);
                Bs[(kg * 4 + 0) * 68 + nr] = bv.x;
                Bs[(kg * 4 + 1) * 68 + nr] = bv.y;
                Bs[(kg * 4 + 2) * 68 + nr] = bv.z;
                Bs[(kg * 4 + 3) * 68 + nr] = bv.w;
            }
            __syncthreads();
            #pragma unroll
            for (int kk = 0; kk < 16; ++kk) {
                const float* ap = &As[kk * 132 + ty * 8];
                ulonglong2 a01 = *(const ulonglong2*)ap;
                ulonglong2 a23 = *(const ulonglong2*)(ap + 4);
                u64 aq[4] = {a01.x, a01.y, a23.x, a23.y};
                const float* bp = &Bs[kk * 68 + tx * 8];
                float4 b0 = *(const float4*)bp;
                float4 b1 = *(const float4*)(bp + 4);
                float bf[8] = {b0.x, b0.y, b0.z, b0.w, b1.x, b1.y, b1.z, b1.w};
                #pragma unroll
                for (int j = 0; j < 8; ++j) {
                    u64 bd = pack2(bf[j], bf[j]);
                    #pragma unroll
                    for (int p = 0; p < 4; ++p) FMA2(acc[p][j], aq[p], bd);
                }
            }
        }

        #pragma unroll
        for (int p = 0; p < 4; ++p) {
            float c0[8], c1[8];
            #pragma unroll
            for (int j = 0; j < 8; ++j) unpack2(acc[p][j], c0[j], c1[j]);
            #pragma unroll
            for (int half = 0; half < 2; ++half) {
                float* cc = half ? c1 : c0;
                int m = m0 + ty * 8 + 2 * p + half;
                #pragma unroll
                for (int j = 0; j < 8; ++j) {
                    int n = np + tx * 8 + j;
                    float v = cc[j];
                    if (MODE == 0) {
                        const int which = n >> 9;
                        const float* bp2 = (which == 0) ? bias0 : (which == 1) ? bias1 : bias2;
                        float* outw     = (which == 0) ? out0  : (which == 1) ? out1  : out2;
                        v += bp2[n & 511];
                        int b_ = m >> 12, l = m & (SEQ - 1);
                        int hh = (n >> 6) & 7, db = n & 63;
                        outw[((size_t)(b_ * NHEAD + hh) * SEQ + l) * DH + db] = v;
                    } else if (MODE == 2) {
                        out0[(size_t)m * N + n] = v + bias0[n] + resid[(size_t)m * N + n];
                    } else {
                        out0[(size_t)m * N + n] = gelu_f(v + bias0[n]);
                    }
                }
            }
        }
        __syncthreads();
    }
#endif
}

// ---------------- attention ----------------------------------------------------
// TC path: BQ=128, BK=128, 256 threads, S+P in TMEM cols 0..127, O in 128..191.
#define ATTN_SMEM 101632

__global__ __launch_bounds__(256, 2)
void attn_k(const float* __restrict__ q, const float* __restrict__ k,
            const float* __restrict__ v, const int* __restrict__ mask,
            float* __restrict__ ctx)
{
    extern __shared__ __align__(1024) float sm[];
    const int qt = blockIdx.x, h = blockIdx.y, b = blockIdx.z;
    const int tid = threadIdx.x;

    const float* qb = q + ((size_t)(b * NHEAD + h) * SEQ) * DH;
    const float* kb = k + ((size_t)(b * NHEAD + h) * SEQ) * DH;
    const float* vb = v + ((size_t)(b * NHEAD + h) * SEQ) * DH;

#if HAS_TC
    float* Qs  = sm;            // 2 chunks [128][32] swizzled = 8192 floats
    float* Ks  = sm + 8192;     // 2 chunks [128][32]
    float* VTs = sm + 16384;    // 4 chunks [64][32]
    int*   Msm = (int*)(sm + 24576);     // [2][128]
    float* lpart = sm + 24832;           // [2][128]

    __shared__ uint32_t s_tptr;
    __shared__ unsigned long long s_mbar[2];

    const int wid = tid >> 5, lane = tid & 31;
    const int sp = wid & 3, ch = wid >> 2;      // subpartition row group, col half
    const int NT = SEQ / 128;                    // 32

    if (wid == 0) TC_ALLOC(smem_u32(&s_tptr), 256);
    if (tid == 0) { MBAR_INIT(smem_u32(&s_mbar[0]), 1); MBAR_INIT(smem_u32(&s_mbar[1]), 1); }
    __syncthreads();
    const uint32_t tmem = s_tptr;
    const uint32_t mbS = smem_u32(&s_mbar[0]), mbO = smem_u32(&s_mbar[1]);
    const uint32_t S_T = tmem, O_T = tmem + 128;

    // ---- prologue: Q (scaled), K[0], VT[0], mask[0] ----
    #pragma unroll
    for (int i = 0; i < 8; ++i) {
        int idx = tid + i * 256;
        int r = idx >> 4, dg = idx & 15;
        float4 vv = *(const float4*)(qb + (size_t)(qt * 128 + r) * DH + dg * 4);
        vv.x = cvt_tf32(vv.x * 0.125f); vv.y = cvt_tf32(vv.y * 0.125f);
        vv.z = cvt_tf32(vv.z * 0.125f); vv.w = cvt_tf32(vv.w * 0.125f);
        int off = r * 128 + (dg & 7) * 16;
        int sw = off ^ ((off >> 3) & 0x70);
        *(float4*)((char*)(Qs + (dg >> 3) * 4096) + sw) = vv;
    }
    #pragma unroll
    for (int i = 0; i < 8; ++i) {
        int idx = tid + i * 256;
        int r = idx >> 4, dg = idx & 15;
        float4 vv = *(const float4*)(kb + (size_t)r * DH + dg * 4);
        vv.x = cvt_tf32(vv.x); vv.y = cvt_tf32(vv.y);
        vv.z = cvt_tf32(vv.z); vv.w = cvt_tf32(vv.w);
        int off = r * 128 + (dg & 7) * 16;
        int sw = off ^ ((off >> 3) & 0x70);
        *(float4*)((char*)(Ks + (dg >> 3) * 4096) + sw) = vv;
    }
    #pragma unroll
    for (int i = 0; i < 8; ++i) {
        int idx = tid + i * 256;
        int kr = idx >> 4, dg = idx & 15;
        float4 vv = *(const float4*)(vb + (size_t)kr * DH + dg * 4);
        float* chk = VTs + (kr >> 5) * 2048;
        int kc = kr & 31;
        float e[4] = {cvt_tf32(vv.x), cvt_tf32(vv.y), cvt_tf32(vv.z), cvt_tf32(vv.w)};
        #pragma unroll
        for (int t2 = 0; t2 < 4; ++t2) {
            int off = (dg * 4 + t2) * 128 + kc * 4;
            int sw = off ^ ((off >> 3) & 0x70);
            *(float*)((char*)chk + sw) = e[t2];
        }
    }
    if (tid < 128) Msm[tid] = mask[b * SEQ + tid];
    __syncthreads();

    if (wid == 0 && elect_one_pred()) {
        FENCE_ASYNC();
        uint64_t qd0 = make_desc(smem_u32(Qs)), qd1 = make_desc(smem_u32(Qs + 4096));
        uint64_t kd0 = make_desc(smem_u32(Ks)), kd1 = make_desc(smem_u32(Ks + 4096));
        #pragma unroll
        for (int s = 0; s < 4; ++s) TC_MMA_TF32(S_T, qd0 + 2 * s, kd0 + 2 * s, IDESC_QK, s > 0);
        #pragma unroll
        for (int s = 0; s < 4; ++s) TC_MMA_TF32(S_T, qd1 + 2 * s, kd1 + 2 * s, IDESC_QK, true);
        TC_COMMIT(mbS);
    }

    float lsum = 0.f;

    for (int t = 0; t < NT; ++t) {
        const int tb = t & 1;
        MBAR_WAIT(mbS, t & 1);
        TC_FENCE_AFTER();

        uint32_t ra[32], rb[32];
        TC_LD_X32(ra, S_T + ch * 64);
        TC_LD_X32(rb, S_T + ch * 64 + 32);
        TC_WAIT_LD();

        const int* mrow = &Msm[tb * 128 + ch * 64];
        #pragma unroll
        for (int j = 0; j < 32; ++j) {
            float s = __uint_as_float(ra[j]);
            s = mrow[j] ? s : -1e9f;
            float p = __expf(fminf(s, 60.f));
            lsum += p;
            ra[j] = cvt_tf32_bits(p);
        }
        #pragma unroll
        for (int j = 0; j < 32; ++j) {
            float s = __uint_as_float(rb[j]);
            s = mrow[32 + j] ? s : -1e9f;
            float p = __expf(fminf(s, 60.f));
            lsum += p;
            rb[j] = cvt_tf32_bits(p);
        }
        TC_ST_X32(S_T + ch * 64, ra);
        TC_ST_X32(S_T + ch * 64 + 32, rb);
        TC_WAIT_ST();
        TC_FENCE_BEFORE();

        // prefetch K[t+1] + mask[t+1] (K smem free: QK(t) already consumed it)
        if (t + 1 < NT) {
            const float* kg = kb + (size_t)(t + 1) * 128 * DH;
            #pragma unroll
            for (int i = 0; i < 8; ++i) {
                int idx = tid + i * 256;
                int r = idx >> 4, dg = idx & 15;
                float4 vv = *(const float4*)(kg + (size_t)r * DH + dg * 4);
                vv.x = cvt_tf32(vv.x); vv.y = cvt_tf32(vv.y);
                vv.z = cvt_tf32(vv.z); vv.w = cvt_tf32(vv.w);
                int off = r * 128 + (dg & 7) * 16;
                int sw = off ^ ((off >> 3) & 0x70);
                *(float4*)((char*)(Ks + (dg >> 3) * 4096) + sw) = vv;
            }
            if (tid < 128) Msm[(1 - tb) * 128 + tid] = mask[b * SEQ + (t + 1) * 128 + tid];
        }
        __syncthreads();

        // PV: O += P(tmem) x VT(smem)
        if (wid == 0 && elect_one_pred()) {
            TC_FENCE_AFTER();
            FENCE_ASYNC();
            #pragma unroll
            for (int cc2 = 0; cc2 < 4; ++cc2) {
                uint64_t vd = make_desc(smem_u32(VTs + cc2 * 2048));
                #pragma unroll
                for (int s = 0; s < 4; ++s)
                    TC_MMA_TF32_TS(O_T, S_T + cc2 * 32 + s * 8, vd + 2 * s, IDESC_PV,
                                   (t > 0) || (cc2 > 0) || (s > 0));
            }
            TC_COMMIT(mbO);
        }

        MBAR_WAIT(mbO, t & 1);

        // prefetch VT[t+1] (VT smem free: PV(t) done) and issue QK[t+1]
        if (t + 1 < NT) {
            const float* vg = vb + (size_t)(t + 1) * 128 * DH;
            #pragma unroll
            for (int i = 0; i < 8; ++i) {
                int idx = tid + i * 256;
                int kr = idx >> 4, dg = idx & 15;
                float4 vv = *(const float4*)(vg + (size_t)kr * DH + dg * 4);
                float* chk = VTs + (kr >> 5) * 2048;
                int kc = kr & 31;
                float e[4] = {cvt_tf32(vv.x), cvt_tf32(vv.y), cvt_tf32(vv.z), cvt_tf32(vv.w)};
                #pragma unroll
                for (int t2 = 0; t2 < 4; ++t2) {
                    int off = (dg * 4 + t2) * 128 + kc * 4;
                    int sw = off ^ ((off >> 3) & 0x70);
                    *(float*)((char*)chk + sw) = e[t2];
                }
            }
            if (wid == 0 && elect_one_pred()) {
                FENCE_ASYNC();
                uint64_t qd0 = make_desc(smem_u32(Qs)), qd1 = make_desc(smem_u32(Qs + 4096));
                uint64_t kd0 = make_desc(smem_u32(Ks)), kd1 = make_desc(smem_u32(Ks + 4096));
                #pragma unroll
                for (int s = 0; s < 4; ++s) TC_MMA_TF32(S_T, qd0 + 2 * s, kd0 + 2 * s, IDESC_QK, s > 0);
                #pragma unroll
                for (int s = 0; s < 4; ++s) TC_MMA_TF32(S_T, qd1 + 2 * s, kd1 + 2 * s, IDESC_QK, true);
                TC_COMMIT(mbS);
            }
        }
        __syncthreads();
    }

    // ---- combine l over col-halves, read O, normalize, store ----
    const int rr = sp * 32 + lane;
    lpart[ch * 128 + rr] = lsum;
    __syncthreads();
    float linv = 1.f / (lpart[rr] + lpart[128 + rr]);

    TC_FENCE_AFTER();
    uint32_t ro[32];
    TC_LD_X32(ro, O_T + ch * 32);
    TC_WAIT_LD();

    float* dst = ctx + (size_t)(b * SEQ + qt * 128 + rr) * D_EMBED + h * DH + ch * 32;
    #pragma unroll
    for (int g = 0; g < 8; ++g) {
        *(float4*)(dst + g * 4) = make_float4(
            __uint_as_float(ro[g * 4 + 0]) * linv, __uint_as_float(ro[g * 4 + 1]) * linv,
            __uint_as_float(ro[g * 4 + 2]) * linv, __uint_as_float(ro[g * 4 + 3]) * linv);
    }
    __syncthreads();
    if (wid == 0) TC_DEALLOC(tmem, 256);

#else
    // ---------- SIMT f32x2 fallback (R2 kernel, threads 128..255 exit) ----------
    if (tid >= 128) return;
    float* Qs = sm;
    float* Ks = Qs + 64 * 132;
    float* Vs = Ks + 64 * 68;
    float* Ps = Vs + 64 * 64;
    int*   Ms = (int*)(Ps + 64 * 132);
    const int ty = tid >> 3, tx = tid & 7;

    for (int idx = tid; idx < 2048; idx += 128) {
        int qr = idx >> 4, dg = idx & 15;
        float4 val = *(const float4*)(qb + (size_t)(qt * 128 + qr) * DH + dg * 4);
        Qs[(dg * 4 + 0) * 132 + qr] = val.x * 0.125f;
        Qs[(dg * 4 + 1) * 132 + qr] = val.y * 0.125f;
        Qs[(dg * 4 + 2) * 132 + qr] = val.z * 0.125f;
        Qs[(dg * 4 + 3) * 132 + qr] = val.w * 0.125f;
    }

    u64 O2[8][4];
    float m_[8], l_[8];
    #pragma unroll
    for (int i = 0; i < 8; ++i) {
        m_[i] = -1e30f; l_[i] = 0.f;
        #pragma unroll
        for (int jp = 0; jp < 4; ++jp) O2[i][jp] = 0ULL;
    }

    for (int t = 0; t < SEQ / 64; ++t) {
        __syncthreads();
        for (int idx = tid; idx < 1024; idx += 128) {
            int kr = idx >> 4, dg = idx & 15;
            float4 kv = *(const float4*)(kb + (size_t)(t * 64 + kr) * DH + dg * 4);
            Ks[(dg * 4 + 0) * 68 + kr] = kv.x;
            Ks[(dg * 4 + 1) * 68 + kr] = kv.y;
            Ks[(dg * 4 + 2) * 68 + kr] = kv.z;
            Ks[(dg * 4 + 3) * 68 + kr] = kv.w;
        }
        for (int idx = tid; idx < 1024; idx += 128)
            *(float4*)&Vs[idx * 4] = *(const float4*)(vb + (size_t)t * 64 * DH + idx * 4);
        if (tid < 64) Ms[tid] = mask[b * SEQ + t * 64 + tid];
        __syncthreads();

        u64 acc[4][8];
        #pragma unroll
        for (int p = 0; p < 4; ++p)
            #pragma unroll
            for (int j = 0; j < 8; ++j) acc[p][j] = 0ULL;

        #pragma unroll 4
        for (int kk = 0; kk < 64; ++kk) {
            const float* qp = &Qs[kk * 132 + ty * 8];
            ulonglong2 qa = *(const ulonglong2*)qp;
            ulonglong2 qc = *(const ulonglong2*)(qp + 4);
            u64 qq[4] = {qa.x, qa.y, qc.x, qc.y};
            const float* kp = &Ks[kk * 68 + tx * 8];
            float4 k0 = *(const float4*)kp;
            float4 k1 = *(const float4*)(kp + 4);
            float kf[8] = {k0.x, k0.y, k0.z, k0.w, k1.x, k1.y, k1.z, k1.w};
            #pragma unroll
            for (int j = 0; j < 8; ++j) {
                u64 kd = pack2(kf[j], kf[j]);
                #pragma unroll
                for (int p = 0; p < 4; ++p) FMA2(acc[p][j], qq[p], kd);
            }
        }

        float S[8][8];
        #pragma unroll
        for (int p = 0; p < 4; ++p)
            #pragma unroll
            for (int j = 0; j < 8; ++j) unpack2(acc[p][j], S[2 * p][j], S[2 * p + 1][j]);

        #pragma unroll
        for (int j = 0; j < 8; ++j) {
            if (Ms[tx * 8 + j] == 0) {
                #pragma unroll
                for (int i = 0; i < 8; ++i) S[i][j] = -1e9f;
            }
        }

        #pragma unroll
        for (int i = 0; i < 8; ++i) {
            float rmax = S[i][0];
            #pragma unroll
            for (int j = 1; j < 8; ++j) rmax = fmaxf(rmax, S[i][j]);
            rmax = fmaxf(rmax, __shfl_xor_sync(0xffffffffu, rmax, 1));
            rmax = fmaxf(rmax, __shfl_xor_sync(0xffffffffu, rmax, 2));
            rmax = fmaxf(rmax, __shfl_xor_sync(0xffffffffu, rmax, 4));
            float mn = fmaxf(m_[i], rmax);
            float al = __expf(m_[i] - mn);
            m_[i] = mn;
            l_[i] *= al;
            u64 ad = pack2(al, al);
            #pragma unroll
            for (int jp = 0; jp < 4; ++jp) MUL2(O2[i][jp], ad);
            float rs = 0.f;
            #pragma unroll
            for (int j = 0; j < 8; ++j) {
                float pv = __expf(S[i][j] - mn);
                S[i][j] = pv;
                rs += pv;
            }
            rs += __shfl_xor_sync(0xffffffffu, rs, 1);
            rs += __shfl_xor_sync(0xffffffffu, rs, 2);
            rs += __shfl_xor_sync(0xffffffffu, rs, 4);
            l_[i] += rs;
        }

        #pragma unroll
        for (int j = 0; j < 8; ++j) {
            float* pd = &Ps[(tx * 8 + j) * 132 + ty * 8];
            *(float4*)pd       = make_float4(S[0][j], S[1][j], S[2][j], S[3][j]);
            *(float4*)(pd + 4) = make_float4(S[4][j], S[5][j], S[6][j], S[7][j]);
        }
        __syncthreads();

        #pragma unroll 4
        for (int kk = 0; kk < 64; ++kk) {
            const float* pp = &Ps[kk * 132 + ty * 8];
            float4 p0 = *(const float4*)pp;
            float4 p1 = *(const float4*)(pp + 4);
            float pf[8] = {p0.x, p0.y, p0.z, p0.w, p1.x, p1.y, p1.z, p1.w};
            const float* vp = &Vs[kk * 64 + tx * 8];
            ulonglong2 v01 = *(const ulonglong2*)vp;
            ulonglong2 v23 = *(const ulonglong2*)(vp + 4);
            u64 vv[4] = {v01.x, v01.y, v23.x, v23.y};
            #pragma unroll
            for (int i = 0; i < 8; ++i) {
                u64 pd = pack2(pf[i], pf[i]);
                #pragma unroll
                for (int jp = 0; jp < 4; ++jp) FMA2(O2[i][jp], pd, vv[jp]);
            }
        }
    }

    #pragma unroll
    for (int i = 0; i < 8; ++i) {
        float inv = 1.f / l_[i];
        float o[8];
        #pragma unroll
        for (int jp = 0; jp < 4; ++jp) unpack2(O2[i][jp], o[2 * jp], o[2 * jp + 1]);
        int row = b * SEQ + qt * 128 + ty * 8 + i;
        float* dst = ctx + (size_t)row * D_EMBED + h * DH + tx * 8;
        *(float4*)dst       = make_float4(o[0] * inv, o[1] * inv, o[2] * inv, o[3] * inv);
        *(float4*)(dst + 4) = make_float4(o[4] * inv, o[5] * inv, o[6] * inv, o[7] * inv);
    }
#endif
}

// ---------------- LayerNorm -----------------------------------------------------
__global__ __launch_bounds__(128)
void ln_k(const float* __restrict__ in, const float* __restrict__ gam,
          const float* __restrict__ bet, float* __restrict__ out)
{
    const int row = blockIdx.x;
    const int tid = threadIdx.x;
    float4 vx = ((const float4*)(in + (size_t)row * D_EMBED))[tid];
    float s  = vx.x + vx.y + vx.z + vx.w;
    float ss = vx.x * vx.x + vx.y * vx.y + vx.z * vx.z + vx.w * vx.w;
    #pragma unroll
    for (int o = 16; o; o >>= 1) {
        s  += __shfl_xor_sync(0xffffffffu, s, o);
        ss += __shfl_xor_sync(0xffffffffu, ss, o);
    }
    __shared__ float sh[8];
    if ((tid & 31) == 0) { sh[tid >> 5] = s; sh[4 + (tid >> 5)] = ss; }
    __syncthreads();
    float S  = sh[0] + sh[1] + sh[2] + sh[3];
    float SS = sh[4] + sh[5] + sh[6] + sh[7];
    float mu   = S * (1.f / 512.f);
    float var  = SS * (1.f / 512.f) - mu * mu;
    float rstd = rsqrtf(var + 1e-5f);
    float4 g  = ((const float4*)gam)[tid];
    float4 bb = ((const float4*)bet)[tid];
    float4 o;
    o.x = (vx.x - mu) * rstd * g.x + bb.x;
    o.y = (vx.y - mu) * rstd * g.y + bb.y;
    o.z = (vx.z - mu) * rstd * g.z + bb.z;
    o.w = (vx.w - mu) * rstd * g.w + bb.w;
    ((float4*)(out + (size_t)row * D_EMBED))[tid] = o;
}

// ---------------- launcher -------------------------------------------------------
extern "C" void kernel_launch(void* const* d_in, const int* in_sizes, int n_in,
                              void* d_out, int out_size)
{
    const float* x    = (const float*)d_in[0];
    const int*   mask = (const int*)  d_in[1];
    const float* Wq   = (const float*)d_in[2];
    const float* bq   = (const float*)d_in[3];
    const float* Wk   = (const float*)d_in[4];
    const float* bk   = (const float*)d_in[5];
    const float* Wv   = (const float*)d_in[6];
    const float* bv   = (const float*)d_in[7];
    const float* Wo   = (const float*)d_in[8];
    const float* bo   = (const float*)d_in[9];

    const float *ln1g, *ln1b, *ln2g, *ln2b, *W1, *b1, *W2, *b2;
    if (in_sizes[12] == D_EMBED * DFF) {
        ln1g = (const float*)d_in[10]; ln1b = (const float*)d_in[11];
        W1   = (const float*)d_in[12]; b1   = (const float*)d_in[13];
        W2   = (const float*)d_in[14]; b2   = (const float*)d_in[15];
        ln2g = (const float*)d_in[16]; ln2b = (const float*)d_in[17];
    } else {
        ln1g = (const float*)d_in[10]; ln1b = (const float*)d_in[11];
        ln2g = (const float*)d_in[12]; ln2b = (const float*)d_in[13];
        W1   = (const float*)d_in[14]; b1   = (const float*)d_in[15];
        W2   = (const float*)d_in[16]; b2   = (const float*)d_in[17];
    }

    float *q, *k, *v, *ctx, *res1, *h, *ff, *res2;
    float *wqkvt, *wot, *w1t, *w2t;
    cudaGetSymbolAddress((void**)&q,    g_q);
    cudaGetSymbolAddress((void**)&k,    g_k);
    cudaGetSymbolAddress((void**)&v,    g_v);
    cudaGetSymbolAddress((void**)&ctx,  g_ctx);
    cudaGetSymbolAddress((void**)&res1, g_res1);
    cudaGetSymbolAddress((void**)&h,    g_h);
    cudaGetSymbolAddress((void**)&ff,   g_ff);
    cudaGetSymbolAddress((void**)&res2, g_res2);
    cudaGetSymbolAddress((void**)&wqkvt, g_wqkvt);
    cudaGetSymbolAddress((void**)&wot,   g_wot);
    cudaGetSymbolAddress((void**)&w1t,   g_w1t);
    cudaGetSymbolAddress((void**)&w2t,   g_w2t);

    static bool attr_done = false;
    if (!attr_done) {
        cudaFuncSetAttribute(attn_k,   cudaFuncAttributeMaxDynamicSharedMemorySize, ATTN_SMEM);
        cudaFuncSetAttribute(gemmT<0>, cudaFuncAttributeMaxDynamicSharedMemorySize, 65536);
        cudaFuncSetAttribute(gemmT<2>, cudaFuncAttributeMaxDynamicSharedMemorySize, 65536);
        cudaFuncSetAttribute(gemmT<3>, cudaFuncAttributeMaxDynamicSharedMemorySize, 65536);
        attr_done = true;
    }

    transpose_cvt<<<dim3(16, 16), 256>>>(Wq, wqkvt,                   512, 512);
    transpose_cvt<<<dim3(16, 16), 256>>>(Wk, wqkvt + 512 * 512,       512, 512);
    transpose_cvt<<<dim3(16, 16), 256>>>(Wv, wqkvt + 2 * 512 * 512,   512, 512);
    transpose_cvt<<<dim3(16, 16), 256>>>(Wo, wot,                     512, 512);
    transpose_cvt<<<dim3(64, 16), 256>>>(W1, w1t,                     512, 2048);
    transpose_cvt<<<dim3(16, 64), 256>>>(W2, w2t,                    2048, 512);

    gemmT<0><<<dim3(12, 64), 128, 65536>>>(x, wqkvt, bq, bk, bv, nullptr,
                                           q, k, v, 3 * D_EMBED, D_EMBED);

    attn_k<<<dim3(SEQ / 128, NHEAD, BATCH), 256, ATTN_SMEM>>>(q, k, v, mask, ctx);

    gemmT<2><<<dim3(4, 64), 128, 65536>>>(ctx, wot, bo, nullptr, nullptr, x,
                                          res1, nullptr, nullptr, D_EMBED, D_EMBED);
    ln_k<<<NROWS, 128>>>(res1, ln1g, ln1b, h);

    gemmT<3><<<dim3(16, 64), 128, 65536>>>(h, w1t, b1, nullptr, nullptr, nullptr,
                                           ff, nullptr, nullptr, DFF, D_EMBED);
    gemmT<2><<<dim3(4, 64), 128, 65536>>>(ff, w2t, b2, nullptr, nullptr, h,
                                          res2, nullptr, nullptr, D_EMBED, DFF);
    ln_k<<<NROWS, 128>>>(res2, ln2g, ln2b, (float*)d_out);
}

// round 6
// speedup vs baseline: 11.1019x; 2.1967x over previous
#include <cuda_runtime.h>
#include <math.h>
#include <stdint.h>

#define D_EMBED 512
#define NHEAD   8
#define DH      64
#define DFF     2048
#define BATCH   2
#define SEQ     4096
#define NROWS   (BATCH*SEQ)   // 8192

#if defined(__CUDA_ARCH__)
# if defined(__CUDA_ARCH_HAS_FEATURE__)
#  if __CUDA_ARCH_HAS_FEATURE__(SM103_ALL)
#   define HAS_TC 1
#  endif
# endif
# if !defined(HAS_TC) && defined(__CUDA_ARCH_SPECIFIC__)
#  define HAS_TC 1
# endif
#endif
#ifndef HAS_TC
# define HAS_TC 0
#endif

// ---------------- scratch ------------------------------------------------------
__device__ float g_q[BATCH*NHEAD*SEQ*DH];
__device__ float g_k[BATCH*NHEAD*SEQ*DH];
__device__ float g_v[BATCH*NHEAD*SEQ*DH];
__device__ float g_ctx[NROWS*D_EMBED];
__device__ float g_res1[NROWS*D_EMBED];
__device__ float g_h[NROWS*D_EMBED];
__device__ float g_ff[(size_t)NROWS*DFF];
__device__ float g_res2[NROWS*D_EMBED];
// pre-swizzled weights: [ntile(256n)][kchunk(32k)][8192 floats swizzled]
__device__ float g_wqkvt[3*D_EMBED*D_EMBED];
__device__ float g_wot[D_EMBED*D_EMBED];
__device__ float g_w1t[DFF*D_EMBED];
__device__ float g_w2t[D_EMBED*DFF];

// ---------------- helpers ------------------------------------------------------
typedef unsigned long long u64;
__device__ __forceinline__ u64 pack2(float x, float y) {
    u64 r; asm("mov.b64 %0, {%1, %2};" : "=l"(r) : "f"(x), "f"(y)); return r;
}
__device__ __forceinline__ void unpack2(u64 v, float& x, float& y) {
    asm("mov.b64 {%0, %1}, %2;" : "=f"(x), "=f"(y) : "l"(v));
}
#define FMA2(d, a, b) asm("fma.rn.f32x2 %0, %1, %2, %0;" : "+l"(d) : "l"(a), "l"(b))
#define MUL2(d, a)    asm("mul.rn.f32x2 %0, %0, %1;"     : "+l"(d) : "l"(a))

__device__ __forceinline__ float gelu_f(float x) {
    return 0.5f * x * (1.0f + erff(x * 0.70710678118654752f));
}
__device__ __forceinline__ uint32_t smem_u32(const void* p) {
    uint32_t a;
    asm("{ .reg .u64 t; cvta.to.shared.u64 t, %1; cvt.u32.u64 %0, t; }" : "=r"(a) : "l"(p));
    return a;
}

#if HAS_TC
__device__ __forceinline__ uint32_t elect_one_pred() {
    uint32_t pred;
    asm volatile("{\n\t.reg .pred p;\n\telect.sync _|p, 0xFFFFFFFF;\n\t"
                 "selp.b32 %0, 1, 0, p;\n\t}" : "=r"(pred));
    return pred;
}
#define MBAR_INIT(a, n) asm volatile("mbarrier.init.shared.b64 [%0], %1;" :: "r"(a), "r"(n) : "memory")
#define MBAR_EXPECT_TX(a, bytes) \
    asm volatile("mbarrier.arrive.expect_tx.shared.b64 _, [%0], %1;" :: "r"(a), "r"(bytes) : "memory")
#define MBAR_WAIT(a, par) do { \
    uint32_t _m = (a), _p = (par), _d; \
    asm volatile("{\n\t.reg .pred p;\n\t" \
        "mbarrier.try_wait.parity.acquire.cta.shared::cta.b64 p, [%1], %2;\n\t" \
        "selp.b32 %0, 1, 0, p;\n\t}" : "=r"(_d) : "r"(_m), "r"(_p) : "memory"); \
    if (!_d) { asm volatile("{\n\t.reg .pred P1;\n\tWL_%=:\n\t" \
        "mbarrier.try_wait.parity.acquire.cta.shared::cta.b64 P1, [%0], %1, 0x989680;\n\t" \
        "@P1 bra.uni WD_%=;\n\tbra.uni WL_%=;\n\tWD_%=:\n\t}" \
        :: "r"(_m), "r"(_p) : "memory"); } \
} while (0)
#define BULK_CP(dst, src, sz, mb) \
    asm volatile("cp.async.bulk.shared::cluster.global.mbarrier::complete_tx::bytes [%0], [%1], %2, [%3];" \
        :: "r"(dst), "l"(src), "r"(sz), "r"(mb) : "memory")

#define TC_ALLOC(sa, n)   asm volatile("tcgen05.alloc.cta_group::1.sync.aligned.shared::cta.b32 [%0], %1;" :: "r"(sa), "r"(n) : "memory")
#define TC_DEALLOC(t, n)  asm volatile("tcgen05.dealloc.cta_group::1.sync.aligned.b32 %0, %1;" :: "r"(t), "r"(n))
#define TC_COMMIT(mb)     asm volatile("tcgen05.commit.cta_group::1.mbarrier::arrive::one.shared::cluster.b64 [%0];" :: "r"(mb) : "memory")
#define TC_FENCE_AFTER()  asm volatile("tcgen05.fence::after_thread_sync;" ::: "memory")
#define TC_FENCE_BEFORE() asm volatile("tcgen05.fence::before_thread_sync;" ::: "memory")
#define TC_WAIT_LD()      asm volatile("tcgen05.wait::ld.sync.aligned;" ::: "memory")
#define TC_WAIT_ST()      asm volatile("tcgen05.wait::st.sync.aligned;" ::: "memory")
#define FENCE_ASYNC()     asm volatile("fence.proxy.async.shared::cta;" ::: "memory")

#define TC_LD_X32(r, ta) \
    asm volatile("tcgen05.ld.sync.aligned.32x32b.x32.b32 " \
        "{%0, %1, %2, %3, %4, %5, %6, %7, %8, %9, %10, %11, %12, %13, %14, %15, " \
        " %16, %17, %18, %19, %20, %21, %22, %23, %24, %25, %26, %27, %28, %29, %30, %31}, [%32];" \
        : "=r"((r)[0]), "=r"((r)[1]), "=r"((r)[2]), "=r"((r)[3]), \
          "=r"((r)[4]), "=r"((r)[5]), "=r"((r)[6]), "=r"((r)[7]), \
          "=r"((r)[8]), "=r"((r)[9]), "=r"((r)[10]), "=r"((r)[11]), \
          "=r"((r)[12]), "=r"((r)[13]), "=r"((r)[14]), "=r"((r)[15]), \
          "=r"((r)[16]), "=r"((r)[17]), "=r"((r)[18]), "=r"((r)[19]), \
          "=r"((r)[20]), "=r"((r)[21]), "=r"((r)[22]), "=r"((r)[23]), \
          "=r"((r)[24]), "=r"((r)[25]), "=r"((r)[26]), "=r"((r)[27]), \
          "=r"((r)[28]), "=r"((r)[29]), "=r"((r)[30]), "=r"((r)[31]) \
        : "r"(ta))

#define TC_ST_X32(ta, r) \
    asm volatile("tcgen05.st.sync.aligned.32x32b.x32.b32 [%0], " \
        "{%1, %2, %3, %4, %5, %6, %7, %8, %9, %10, %11, %12, %13, %14, %15, %16, " \
        " %17, %18, %19, %20, %21, %22, %23, %24, %25, %26, %27, %28, %29, %30, %31, %32};" \
        :: "r"(ta), \
           "r"((r)[0]), "r"((r)[1]), "r"((r)[2]), "r"((r)[3]), \
           "r"((r)[4]), "r"((r)[5]), "r"((r)[6]), "r"((r)[7]), \
           "r"((r)[8]), "r"((r)[9]), "r"((r)[10]), "r"((r)[11]), \
           "r"((r)[12]), "r"((r)[13]), "r"((r)[14]), "r"((r)[15]), \
           "r"((r)[16]), "r"((r)[17]), "r"((r)[18]), "r"((r)[19]), \
           "r"((r)[20]), "r"((r)[21]), "r"((r)[22]), "r"((r)[23]), \
           "r"((r)[24]), "r"((r)[25]), "r"((r)[26]), "r"((r)[27]), \
           "r"((r)[28]), "r"((r)[29]), "r"((r)[30]), "r"((r)[31]) \
        : "memory")

#define TC_MMA_TF32(dt, ad, bd, id, en) do { \
    uint32_t _e = (en) ? 1u : 0u; \
    asm volatile("{\n\t.reg .pred p;\n\tsetp.ne.u32 p, %5, 0;\n\t" \
        "tcgen05.mma.cta_group::1.kind::tf32 [%0], %1, %2, %3, {%4, %4, %4, %4}, p;\n\t}" \
        :: "r"(dt), "l"(ad), "l"(bd), "r"(id), "r"(0u), "r"(_e) : "memory"); \
} while (0)

#define TC_MMA_TF32_TS(dt, at, bd, id, en) do { \
    uint32_t _e = (en) ? 1u : 0u; \
    asm volatile("{\n\t.reg .pred p;\n\tsetp.ne.u32 p, %5, 0;\n\t" \
        "tcgen05.mma.cta_group::1.kind::tf32 [%0], [%1], %2, %3, {%4, %4, %4, %4}, p;\n\t}" \
        :: "r"(dt), "r"(at), "l"(bd), "r"(id), "r"(0u), "r"(_e) : "memory"); \
} while (0)

__device__ __forceinline__ uint64_t make_desc(uint32_t addr) {
    return ((uint64_t)2 << 61) | ((uint64_t)1 << 46) | ((uint64_t)64 << 32) |
           ((uint64_t)1 << 16) | (uint64_t)((addr >> 4) & 0x3FFF);
}
#define IDESC_G  ((1u << 4) | (2u << 7) | (2u << 10) | (32u << 17) | (8u << 24))  // M128 N256
#define IDESC_QK ((1u << 4) | (2u << 7) | (2u << 10) | (16u << 17) | (8u << 24))  // M128 N128
#define IDESC_PV ((1u << 4) | (2u << 7) | (2u << 10) | (8u  << 17) | (8u << 24))  // M128 N64
#endif // HAS_TC

// ---------------- weight pre-swizzle: W[K][N] -> tiled swizzled B --------------
__global__ __launch_bounds__(256)
void prep_swz(const float* __restrict__ W, float* __restrict__ dst, int Kdim, int Ndim)
{
    int k = blockIdx.y;
    int n = blockIdx.x * 256 + threadIdx.x;
    float v = W[(size_t)k * Ndim + n];
    int NC = Kdim >> 5;
    int blk = (n >> 8) * NC + (k >> 5);
    int off = (n & 255) * 128 + (k & 31) * 4;
    int sw = off ^ ((off >> 3) & 0x70);
    *(float*)((char*)(dst + (size_t)blk * 8192) + sw) = v;
}

__device__ __forceinline__ float ld_swz(const float* Wt, int NC, int n, int k) {
    int blk = (n >> 8) * NC + (k >> 5);
    int off = (n & 255) * 128 + (k & 31) * 4;
    int sw = off ^ ((off >> 3) & 0x70);
    return *(const float*)((const char*)(Wt + (size_t)blk * 8192) + sw);
}

// ---------------- GEMM: out[8192xN] = A[8192xK] @ W + bias --------------------
// BM=128, BN=256, BK=32, double-buffered; B via cp.async.bulk from pre-swizzled.
// MODE 0: QKV scatter   MODE 2: bias+residual   MODE 3: bias+GELU
#define GEMM_SMEM 98304
template<int MODE>
__global__ __launch_bounds__(256, 2)
void gemmT(const float* __restrict__ A, const float* __restrict__ Wt,
           const float* __restrict__ bias0, const float* __restrict__ bias1,
           const float* __restrict__ bias2, const float* __restrict__ resid,
           float* __restrict__ out0, float* __restrict__ out1, float* __restrict__ out2,
           int N, int K)
{
    extern __shared__ __align__(1024) float sm[];
    const int tid = threadIdx.x, wid = tid >> 5, lane = tid & 31;
    const int n0 = blockIdx.x * 256, m0 = blockIdx.y * 128;
    const int NC = K >> 5;

#if HAS_TC
    __shared__ uint32_t s_tptr;
    __shared__ unsigned long long s_mb[4];   // B0 B1 M0 M1
    const uint32_t smb = smem_u32(sm);

    if (wid == 0) TC_ALLOC(smem_u32(&s_tptr), 256);
    if (tid == 0) {
        #pragma unroll
        for (int i = 0; i < 4; ++i) MBAR_INIT(smem_u32(&s_mb[i]), 1);
    }
    __syncthreads();
    const uint32_t tmem = s_tptr;
    uint32_t mbB[2] = {smem_u32(&s_mb[0]), smem_u32(&s_mb[1])};
    uint32_t mbM[2] = {smem_u32(&s_mb[2]), smem_u32(&s_mb[3])};

    const float* Ag = A + (size_t)m0 * K;
    const size_t bblk = (size_t)blockIdx.x * NC;

    for (int s = 0; s < NC; ++s) {
        const int buf = s & 1, u = s >> 1;
        if (s >= 2) MBAR_WAIT(mbM[buf], (u + 1) & 1);
        if (tid == 0) {
            MBAR_EXPECT_TX(mbB[buf], 32768u);
            BULK_CP(smb + 32768 + buf * 32768, (const void*)(Wt + (bblk + s) * 8192),
                    32768u, mbB[buf]);
        }
        #pragma unroll
        for (int i = 0; i < 4; ++i) {
            int idx = tid + i * 256;
            int row = idx >> 3, c4 = idx & 7;
            int off = row * 128 + c4 * 16;
            int sw = off ^ ((off >> 3) & 0x70);
            *(float4*)((char*)sm + buf * 16384 + sw) =
                *(const float4*)(Ag + (size_t)row * K + s * 32 + c4 * 4);
        }
        __syncthreads();
        if (wid == 0 && elect_one_pred()) {
            MBAR_WAIT(mbB[buf], u & 1);
            FENCE_ASYNC();
            uint64_t ad = make_desc(smb + buf * 16384);
            uint64_t bd = make_desc(smb + 32768 + buf * 32768);
            #pragma unroll
            for (int s2 = 0; s2 < 4; ++s2)
                TC_MMA_TF32(tmem, ad + 2 * s2, bd + 2 * s2, IDESC_G, (s > 0) || (s2 > 0));
            TC_COMMIT(mbM[buf]);
        }
    }
    MBAR_WAIT(mbM[(NC - 1) & 1], ((NC - 1) >> 1) & 1);
    TC_FENCE_AFTER();
    __syncthreads();

    // epilogue: 4 iterations of 64 columns, staged via smem
    const int sp = wid & 3, ch = wid >> 2;
    for (int cg = 0; cg < 4; ++cg) {
        uint32_t r[32];
        TC_LD_X32(r, tmem + cg * 64 + ch * 32);
        TC_WAIT_LD();
        const int row = sp * 32 + lane;
        #pragma unroll
        for (int j = 0; j < 32; ++j) sm[row * 65 + ch * 32 + j] = __uint_as_float(r[j]);
        __syncthreads();

        const int r2 = tid & 127, sel = tid >> 7;
        const int m = m0 + r2;
        const int n = n0 + cg * 64 + sel * 32;
        const float* src = &sm[r2 * 65 + sel * 32];
        if (MODE == 0) {
            const int which = n >> 9;
            const int hh = (n >> 6) & 7;
            const float* bp = (which == 0) ? bias0 : (which == 1) ? bias1 : bias2;
            float* outw     = (which == 0) ? out0  : (which == 1) ? out1  : out2;
            const int b_ = m >> 12, l = m & (SEQ - 1);
            float* dst = outw + ((size_t)(b_ * NHEAD + hh) * SEQ + l) * DH + (n & 63);
            const int bb = n & 511;
            #pragma unroll
            for (int j = 0; j < 32; ++j) dst[j] = src[j] + bp[bb + j];
        } else if (MODE == 2) {
            float* dst = out0 + (size_t)m * N + n;
            const float* rs = resid + (size_t)m * N + n;
            #pragma unroll
            for (int j = 0; j < 32; ++j) dst[j] = src[j] + bias0[n + j] + rs[j];
        } else {
            float* dst = out0 + (size_t)m * N + n;
            #pragma unroll
            for (int j = 0; j < 32; ++j) dst[j] = gelu_f(src[j] + bias0[n + j]);
        }
        __syncthreads();
    }
    if (wid == 0) TC_DEALLOC(tmem, 256);

#else
    // dead-code correct fallback (never runs on sm_103a hardware)
    for (int e = tid; e < 128 * 256; e += 256) {
        int mr = e >> 8, nc = e & 255;
        int m = m0 + mr, n = n0 + nc;
        float acc = 0.f;
        for (int k = 0; k < K; ++k) acc += A[(size_t)m * K + k] * ld_swz(Wt, NC, n, k);
        if (MODE == 0) {
            const int which = n >> 9;
            const float* bp = (which == 0) ? bias0 : (which == 1) ? bias1 : bias2;
            float* outw     = (which == 0) ? out0  : (which == 1) ? out1  : out2;
            int b_ = m >> 12, l = m & (SEQ - 1);
            outw[((size_t)(b_ * NHEAD + ((n >> 6) & 7)) * SEQ + l) * DH + (n & 63)] =
                acc + bp[n & 511];
        } else if (MODE == 2) {
            out0[(size_t)m * N + n] = acc + bias0[n] + resid[(size_t)m * N + n];
        } else {
            out0[(size_t)m * N + n] = gelu_f(acc + bias0[n]);
        }
    }
#endif
}

// ---------------- attention: BQ=128, BK=128, double-buffered S/K/V -------------
#define ATTN_SMEM 165888

__global__ __launch_bounds__(256, 1)
void attn_k(const float* __restrict__ q, const float* __restrict__ k,
            const float* __restrict__ v, const int* __restrict__ mask,
            float* __restrict__ ctx)
{
    extern __shared__ __align__(1024) float sm[];
    const int qt = blockIdx.x, h = blockIdx.y, b = blockIdx.z;
    const int tid = threadIdx.x;

    const float* qb = q + ((size_t)(b * NHEAD + h) * SEQ) * DH;
    const float* kb = k + ((size_t)(b * NHEAD + h) * SEQ) * DH;
    const float* vb = v + ((size_t)(b * NHEAD + h) * SEQ) * DH;

#if HAS_TC
    float* Qs  = sm;                 // [2 chunks][128 q][32 d] = 8192 f
    float* Ks  = sm + 8192;          // [2 bufs][2 chunks][128 k][32 d]
    float* VTs = sm + 24576;         // [2 bufs][4 chunks][64 d][32 k]
    float* lpart = sm + 40960;       // [2][128]
    int*   Msm = (int*)(sm + 41216); // [2][128]

    __shared__ uint32_t s_tptr;
    __shared__ unsigned long long s_mb[3];
    const int wid = tid >> 5, lane = tid & 31;
    const int sp = wid & 3, ch = wid >> 2;
    const int NT = SEQ / 128;

    if (wid == 0) TC_ALLOC(smem_u32(&s_tptr), 512);
    if (tid == 0) {
        MBAR_INIT(smem_u32(&s_mb[0]), 1);
        MBAR_INIT(smem_u32(&s_mb[1]), 1);
        MBAR_INIT(smem_u32(&s_mb[2]), 1);
    }
    __syncthreads();
    const uint32_t tmem = s_tptr;
    uint32_t mbS[2] = {smem_u32(&s_mb[0]), smem_u32(&s_mb[1])};
    const uint32_t mbO = smem_u32(&s_mb[2]);
    const uint32_t S_T[2] = {tmem, tmem + 128};
    const uint32_t O_T = tmem + 256;

    // Q (scaled)
    #pragma unroll
    for (int i = 0; i < 8; ++i) {
        int idx = tid + i * 256;
        int r = idx >> 4, dg = idx & 15;
        float4 vv = *(const float4*)(qb + (size_t)(qt * 128 + r) * DH + dg * 4);
        vv.x *= 0.125f; vv.y *= 0.125f; vv.z *= 0.125f; vv.w *= 0.125f;
        int off = r * 128 + (dg & 7) * 16;
        int sw = off ^ ((off >> 3) & 0x70);
        *(float4*)((char*)(Qs + (dg >> 3) * 4096) + sw) = vv;
    }

    #define COPY_K(t, buf) do { \
        const float* kg = kb + (size_t)(t) * 128 * DH; \
        _Pragma("unroll") \
        for (int i = 0; i < 8; ++i) { \
            int idx = tid + i * 256; \
            int r = idx >> 4, dg = idx & 15; \
            float4 vv = *(const float4*)(kg + (size_t)r * DH + dg * 4); \
            int off = r * 128 + (dg & 7) * 16; \
            int sw = off ^ ((off >> 3) & 0x70); \
            *(float4*)((char*)(Ks + (buf) * 8192 + (dg >> 3) * 4096) + sw) = vv; \
        } \
        if (tid < 128) Msm[(buf) * 128 + tid] = mask[b * SEQ + (t) * 128 + tid]; \
    } while (0)

    #define COPY_V(t, buf) do { \
        const float* vg = vb + (size_t)(t) * 128 * DH; \
        _Pragma("unroll") \
        for (int i = 0; i < 8; ++i) { \
            int idx = tid + i * 256; \
            int kr = idx >> 4, dg = idx & 15; \
            float4 vv = *(const float4*)(vg + (size_t)kr * DH + dg * 4); \
            float* chk = VTs + (buf) * 8192 + (kr >> 5) * 2048; \
            int kc = kr & 31; \
            float e[4] = {vv.x, vv.y, vv.z, vv.w}; \
            _Pragma("unroll") \
            for (int t2 = 0; t2 < 4; ++t2) { \
                int off = (dg * 4 + t2) * 128 + kc * 4; \
                int sw = off ^ ((off >> 3) & 0x70); \
                *(float*)((char*)chk + sw) = e[t2]; \
            } \
        } \
    } while (0)

    #define ISSUE_QK(buf) do { \
        uint64_t qd0 = make_desc(smem_u32(Qs)); \
        uint64_t kd0 = make_desc(smem_u32(Ks + (buf) * 8192)); \
        _Pragma("unroll") \
        for (int c = 0; c < 2; ++c) \
            _Pragma("unroll") \
            for (int s = 0; s < 4; ++s) \
                TC_MMA_TF32(S_T[buf], qd0 + c * 1024 + 2 * s, kd0 + c * 1024 + 2 * s, \
                            IDESC_QK, (c > 0) || (s > 0)); \
        TC_COMMIT(mbS[buf]); \
    } while (0)
    // note: chunk1 of Q/K is 4096 floats = 16384 B = 1024 desc units

    COPY_K(0, 0); COPY_V(0, 0);
    __syncthreads();
    if (wid == 0 && elect_one_pred()) { FENCE_ASYNC(); ISSUE_QK(0); }
    COPY_K(1, 1); COPY_V(1, 1);
    __syncthreads();
    if (wid == 0 && elect_one_pred()) { FENCE_ASYNC(); ISSUE_QK(1); }

    float lsum = 0.f;

    for (int t = 0; t < NT; ++t) {
        const int buf = t & 1;
        MBAR_WAIT(mbS[buf], (t >> 1) & 1);
        TC_FENCE_AFTER();

        uint32_t ra[32], rb[32];
        TC_LD_X32(ra, S_T[buf] + ch * 64);
        TC_LD_X32(rb, S_T[buf] + ch * 64 + 32);
        TC_WAIT_LD();

        const int* mrow = &Msm[buf * 128 + ch * 64];
        #pragma unroll
        for (int j = 0; j < 32; ++j) {
            float s = __uint_as_float(ra[j]);
            s = mrow[j] ? s : -1e9f;
            float p = __expf(fminf(s, 60.f));
            lsum += p;
            ra[j] = __float_as_uint(p);
        }
        #pragma unroll
        for (int j = 0; j < 32; ++j) {
            float s = __uint_as_float(rb[j]);
            s = mrow[32 + j] ? s : -1e9f;
            float p = __expf(fminf(s, 60.f));
            lsum += p;
            rb[j] = __float_as_uint(p);
        }
        TC_ST_X32(S_T[buf] + ch * 64, ra);
        TC_ST_X32(S_T[buf] + ch * 64 + 32, rb);
        TC_WAIT_ST();
        TC_FENCE_BEFORE();
        __syncthreads();

        if (wid == 0 && elect_one_pred()) {
            TC_FENCE_AFTER();
            FENCE_ASYNC();
            #pragma unroll
            for (int cc = 0; cc < 4; ++cc) {
                uint64_t vd = make_desc(smem_u32(VTs + buf * 8192 + cc * 2048));
                #pragma unroll
                for (int s = 0; s < 4; ++s)
                    TC_MMA_TF32_TS(O_T, S_T[buf] + cc * 32 + s * 8, vd + 2 * s, IDESC_PV,
                                   (t > 0) || (cc > 0) || (s > 0));
            }
            TC_COMMIT(mbO);
        }

        if (t + 2 < NT) COPY_K(t + 2, buf);

        MBAR_WAIT(mbO, t & 1);

        if (t + 2 < NT) {
            COPY_V(t + 2, buf);
            __syncthreads();
            if (wid == 0 && elect_one_pred()) { FENCE_ASYNC(); ISSUE_QK(buf); }
        } else {
            __syncthreads();
        }
    }

    const int rr = sp * 32 + lane;
    lpart[ch * 128 + rr] = lsum;
    __syncthreads();
    float linv = 1.f / (lpart[rr] + lpart[128 + rr]);

    TC_FENCE_AFTER();
    uint32_t ro[32];
    TC_LD_X32(ro, O_T + ch * 32);
    TC_WAIT_LD();

    float* dst = ctx + (size_t)(b * SEQ + qt * 128 + rr) * D_EMBED + h * DH + ch * 32;
    #pragma unroll
    for (int g = 0; g < 8; ++g) {
        *(float4*)(dst + g * 4) = make_float4(
            __uint_as_float(ro[g * 4 + 0]) * linv, __uint_as_float(ro[g * 4 + 1]) * linv,
            __uint_as_float(ro[g * 4 + 2]) * linv, __uint_as_float(ro[g * 4 + 3]) * linv);
    }
    __syncthreads();
    if (wid == 0) TC_DEALLOC(tmem, 512);
    #undef COPY_K
    #undef COPY_V
    #undef ISSUE_QK

#else
    // SIMT fallback (threads 128..255 idle)
    if (tid >= 128) return;
    float* Qs = sm;
    float* Ks = Qs + 64 * 132;
    float* Vs = Ks + 64 * 68;
    float* Ps = Vs + 64 * 64;
    int*   Ms = (int*)(Ps + 64 * 132);
    const int ty = tid >> 3, tx = tid & 7;

    for (int idx = tid; idx < 2048; idx += 128) {
        int qr = idx >> 4, dg = idx & 15;
        float4 val = *(const float4*)(qb + (size_t)(qt * 128 + qr) * DH + dg * 4);
        Qs[(dg * 4 + 0) * 132 + qr] = val.x * 0.125f;
        Qs[(dg * 4 + 1) * 132 + qr] = val.y * 0.125f;
        Qs[(dg * 4 + 2) * 132 + qr] = val.z * 0.125f;
        Qs[(dg * 4 + 3) * 132 + qr] = val.w * 0.125f;
    }

    u64 O2[8][4];
    float m_[8], l_[8];
    #pragma unroll
    for (int i = 0; i < 8; ++i) {
        m_[i] = -1e30f; l_[i] = 0.f;
        #pragma unroll
        for (int jp = 0; jp < 4; ++jp) O2[i][jp] = 0ULL;
    }

    for (int t = 0; t < SEQ / 64; ++t) {
        __syncthreads();
        for (int idx = tid; idx < 1024; idx += 128) {
            int kr = idx >> 4, dg = idx & 15;
            float4 kv = *(const float4*)(kb + (size_t)(t * 64 + kr) * DH + dg * 4);
            Ks[(dg * 4 + 0) * 68 + kr] = kv.x;
            Ks[(dg * 4 + 1) * 68 + kr] = kv.y;
            Ks[(dg * 4 + 2) * 68 + kr] = kv.z;
            Ks[(dg * 4 + 3) * 68 + kr] = kv.w;
        }
        for (int idx = tid; idx < 1024; idx += 128)
            *(float4*)&Vs[idx * 4] = *(const float4*)(vb + (size_t)t * 64 * DH + idx * 4);
        if (tid < 64) Ms[tid] = mask[b * SEQ + t * 64 + tid];
        __syncthreads();

        u64 acc[4][8];
        #pragma unroll
        for (int p = 0; p < 4; ++p)
            #pragma unroll
            for (int j = 0; j < 8; ++j) acc[p][j] = 0ULL;

        #pragma unroll 4
        for (int kk = 0; kk < 64; ++kk) {
            const float* qp = &Qs[kk * 132 + ty * 8];
            ulonglong2 qa = *(const ulonglong2*)qp;
            ulonglong2 qc = *(const ulonglong2*)(qp + 4);
            u64 qq[4] = {qa.x, qa.y, qc.x, qc.y};
            const float* kp = &Ks[kk * 68 + tx * 8];
            float4 k0 = *(const float4*)kp;
            float4 k1 = *(const float4*)(kp + 4);
            float kf[8] = {k0.x, k0.y, k0.z, k0.w, k1.x, k1.y, k1.z, k1.w};
            #pragma unroll
            for (int j = 0; j < 8; ++j) {
                u64 kd = pack2(kf[j], kf[j]);
                #pragma unroll
                for (int p = 0; p < 4; ++p) FMA2(acc[p][j], qq[p], kd);
            }
        }

        float S[8][8];
        #pragma unroll
        for (int p = 0; p < 4; ++p)
            #pragma unroll
            for (int j = 0; j < 8; ++j) unpack2(acc[p][j], S[2 * p][j], S[2 * p + 1][j]);

        #pragma unroll
        for (int j = 0; j < 8; ++j) {
            if (Ms[tx * 8 + j] == 0) {
                #pragma unroll
                for (int i = 0; i < 8; ++i) S[i][j] = -1e9f;
            }
        }

        #pragma unroll
        for (int i = 0; i < 8; ++i) {
            float rmax = S[i][0];
            #pragma unroll
            for (int j = 1; j < 8; ++j) rmax = fmaxf(rmax, S[i][j]);
            rmax = fmaxf(rmax, __shfl_xor_sync(0xffffffffu, rmax, 1));
            rmax = fmaxf(rmax, __shfl_xor_sync(0xffffffffu, rmax, 2));
            rmax = fmaxf(rmax, __shfl_xor_sync(0xffffffffu, rmax, 4));
            float mn = fmaxf(m_[i], rmax);
            float al = __expf(m_[i] - mn);
            m_[i] = mn;
            l_[i] *= al;
            u64 ad = pack2(al, al);
            #pragma unroll
            for (int jp = 0; jp < 4; ++jp) MUL2(O2[i][jp], ad);
            float rs = 0.f;
            #pragma unroll
            for (int j = 0; j < 8; ++j) {
                float pv = __expf(S[i][j] - mn);
                S[i][j] = pv;
                rs += pv;
            }
            rs += __shfl_xor_sync(0xffffffffu, rs, 1);
            rs += __shfl_xor_sync(0xffffffffu, rs, 2);
            rs += __shfl_xor_sync(0xffffffffu, rs, 4);
            l_[i] += rs;
        }

        #pragma unroll
        for (int j = 0; j < 8; ++j) {
            float* pd = &Ps[(tx * 8 + j) * 132 + ty * 8];
            *(float4*)pd       = make_float4(S[0][j], S[1][j], S[2][j], S[3][j]);
            *(float4*)(pd + 4) = make_float4(S[4][j], S[5][j], S[6][j], S[7][j]);
        }
        __syncthreads();

        #pragma unroll 4
        for (int kk = 0; kk < 64; ++kk) {
            const float* pp = &Ps[kk * 132 + ty * 8];
            float4 p0 = *(const float4*)pp;
            float4 p1 = *(const float4*)(pp + 4);
            float pf[8] = {p0.x, p0.y, p0.z, p0.w, p1.x, p1.y, p1.z, p1.w};
            const float* vp = &Vs[kk * 64 + tx * 8];
            ulonglong2 v01 = *(const ulonglong2*)vp;
            ulonglong2 v23 = *(const ulonglong2*)(vp + 4);
            u64 vv[4] = {v01.x, v01.y, v23.x, v23.y};
            #pragma unroll
            for (int i = 0; i < 8; ++i) {
                u64 pd = pack2(pf[i], pf[i]);
                #pragma unroll
                for (int jp = 0; jp < 4; ++jp) FMA2(O2[i][jp], pd, vv[jp]);
            }
        }
    }

    #pragma unroll
    for (int i = 0; i < 8; ++i) {
        float inv = 1.f / l_[i];
        float o[8];
        #pragma unroll
        for (int jp = 0; jp < 4; ++jp) unpack2(O2[i][jp], o[2 * jp], o[2 * jp + 1]);
        int row = b * SEQ + qt * 128 + ty * 8 + i;
        float* dst = ctx + (size_t)row * D_EMBED + h * DH + tx * 8;
        *(float4*)dst       = make_float4(o[0] * inv, o[1] * inv, o[2] * inv, o[3] * inv);
        *(float4*)(dst + 4) = make_float4(o[4] * inv, o[5] * inv, o[6] * inv, o[7] * inv);
    }
#endif
}

// ---------------- LayerNorm -----------------------------------------------------
__global__ __launch_bounds__(128)
void ln_k(const float* __restrict__ in, const float* __restrict__ gam,
          const float* __restrict__ bet, float* __restrict__ out)
{
    const int row = blockIdx.x;
    const int tid = threadIdx.x;
    float4 vx = ((const float4*)(in + (size_t)row * D_EMBED))[tid];
    float s  = vx.x + vx.y + vx.z + vx.w;
    float ss = vx.x * vx.x + vx.y * vx.y + vx.z * vx.z + vx.w * vx.w;
    #pragma unroll
    for (int o = 16; o; o >>= 1) {
        s  += __shfl_xor_sync(0xffffffffu, s, o);
        ss += __shfl_xor_sync(0xffffffffu, ss, o);
    }
    __shared__ float sh[8];
    if ((tid & 31) == 0) { sh[tid >> 5] = s; sh[4 + (tid >> 5)] = ss; }
    __syncthreads();
    float S  = sh[0] + sh[1] + sh[2] + sh[3];
    float SS = sh[4] + sh[5] + sh[6] + sh[7];
    float mu   = S * (1.f / 512.f);
    float var  = SS * (1.f / 512.f) - mu * mu;
    float rstd = rsqrtf(var + 1e-5f);
    float4 g  = ((const float4*)gam)[tid];
    float4 bb = ((const float4*)bet)[tid];
    float4 o;
    o.x = (vx.x - mu) * rstd * g.x + bb.x;
    o.y = (vx.y - mu) * rstd * g.y + bb.y;
    o.z = (vx.z - mu) * rstd * g.z + bb.z;
    o.w = (vx.w - mu) * rstd * g.w + bb.w;
    ((float4*)(out + (size_t)row * D_EMBED))[tid] = o;
}

// ---------------- launcher -------------------------------------------------------
extern "C" void kernel_launch(void* const* d_in, const int* in_sizes, int n_in,
                              void* d_out, int out_size)
{
    const float* x    = (const float*)d_in[0];
    const int*   mask = (const int*)  d_in[1];
    const float* Wq   = (const float*)d_in[2];
    const float* bq   = (const float*)d_in[3];
    const float* Wk   = (const float*)d_in[4];
    const float* bk   = (const float*)d_in[5];
    const float* Wv   = (const float*)d_in[6];
    const float* bv   = (const float*)d_in[7];
    const float* Wo   = (const float*)d_in[8];
    const float* bo   = (const float*)d_in[9];

    const float *ln1g, *ln1b, *ln2g, *ln2b, *W1, *b1, *W2, *b2;
    if (in_sizes[12] == D_EMBED * DFF) {
        ln1g = (const float*)d_in[10]; ln1b = (const float*)d_in[11];
        W1   = (const float*)d_in[12]; b1   = (const float*)d_in[13];
        W2   = (const float*)d_in[14]; b2   = (const float*)d_in[15];
        ln2g = (const float*)d_in[16]; ln2b = (const float*)d_in[17];
    } else {
        ln1g = (const float*)d_in[10]; ln1b = (const float*)d_in[11];
        ln2g = (const float*)d_in[12]; ln2b = (const float*)d_in[13];
        W1   = (const float*)d_in[14]; b1   = (const float*)d_in[15];
        W2   = (const float*)d_in[16]; b2   = (const float*)d_in[17];
    }

    float *q, *k, *v, *ctx, *res1, *h, *ff, *res2;
    float *wqkvt, *wot, *w1t, *w2t;
    cudaGetSymbolAddress((void**)&q,    g_q);
    cudaGetSymbolAddress((void**)&k,    g_k);
    cudaGetSymbolAddress((void**)&v,    g_v);
    cudaGetSymbolAddress((void**)&ctx,  g_ctx);
    cudaGetSymbolAddress((void**)&res1, g_res1);
    cudaGetSymbolAddress((void**)&h,    g_h);
    cudaGetSymbolAddress((void**)&ff,   g_ff);
    cudaGetSymbolAddress((void**)&res2, g_res2);
    cudaGetSymbolAddress((void**)&wqkvt, g_wqkvt);
    cudaGetSymbolAddress((void**)&wot,   g_wot);
    cudaGetSymbolAddress((void**)&w1t,   g_w1t);
    cudaGetSymbolAddress((void**)&w2t,   g_w2t);

    static bool attr_done = false;
    if (!attr_done) {
        cudaFuncSetAttribute(attn_k,   cudaFuncAttributeMaxDynamicSharedMemorySize, ATTN_SMEM);
        cudaFuncSetAttribute(gemmT<0>, cudaFuncAttributeMaxDynamicSharedMemorySize, GEMM_SMEM);
        cudaFuncSetAttribute(gemmT<2>, cudaFuncAttributeMaxDynamicSharedMemorySize, GEMM_SMEM);
        cudaFuncSetAttribute(gemmT<3>, cudaFuncAttributeMaxDynamicSharedMemorySize, GEMM_SMEM);
        attr_done = true;
    }

    // weight pre-swizzle ([ntile][kchunk][8192f])
    prep_swz<<<dim3(2, 512), 256>>>(Wq, wqkvt,                512, 512);
    prep_swz<<<dim3(2, 512), 256>>>(Wk, wqkvt + 512 * 512,    512, 512);
    prep_swz<<<dim3(2, 512), 256>>>(Wv, wqkvt + 2 * 512 * 512, 512, 512);
    prep_swz<<<dim3(2, 512), 256>>>(Wo, wot,                  512, 512);
    prep_swz<<<dim3(8, 512), 256>>>(W1, w1t,                  512, 2048);
    prep_swz<<<dim3(2, 2048), 256>>>(W2, w2t,                2048, 512);

    gemmT<0><<<dim3(6, 64), 256, GEMM_SMEM>>>(x, wqkvt, bq, bk, bv, nullptr,
                                              q, k, v, 3 * D_EMBED, D_EMBED);

    attn_k<<<dim3(SEQ / 128, NHEAD, BATCH), 256, ATTN_SMEM>>>(q, k, v, mask, ctx);

    gemmT<2><<<dim3(2, 64), 256, GEMM_SMEM>>>(ctx, wot, bo, nullptr, nullptr, x,
                                              res1, nullptr, nullptr, D_EMBED, D_EMBED);
    ln_k<<<NROWS, 128>>>(res1, ln1g, ln1b, h);

    gemmT<3><<<dim3(8, 64), 256, GEMM_SMEM>>>(h, w1t, b1, nullptr, nullptr, nullptr,
                                              ff, nullptr, nullptr, DFF, D_EMBED);
    gemmT<2><<<dim3(2, 64), 256, GEMM_SMEM>>>(ff, w2t, b2, nullptr, nullptr, h,
                                              res2, nullptr, nullptr, D_EMBED, DFF);
    ln_k<<<NROWS, 128>>>(res2, ln2g, ln2b, (float*)d_out);
}

// round 8
// speedup vs baseline: 16.6856x; 1.5030x over previous
#include <cuda_runtime.h>
#include <math.h>
#include <stdint.h>

#define D_EMBED 512
#define NHEAD   8
#define DH      64
#define DFF     2048
#define BATCH   2
#define SEQ     4096
#define NROWS   (BATCH*SEQ)   // 8192

#if defined(__CUDA_ARCH__)
# if defined(__CUDA_ARCH_HAS_FEATURE__)
#  if __CUDA_ARCH_HAS_FEATURE__(SM103_ALL)
#   define HAS_TC 1
#  endif
# endif
# if !defined(HAS_TC) && defined(__CUDA_ARCH_SPECIFIC__)
#  define HAS_TC 1
# endif
#endif
#ifndef HAS_TC
# define HAS_TC 0
#endif

// ---------------- scratch ------------------------------------------------------
// q,k: per (b,h,tile128): 8192 f = [2 dchunk][128 row][32 d] swizzled
// v:   per (b,h,tile128): 8192 f = [4 kchunk][64 d][32 k]    swizzled
__device__ float g_q[BATCH*NHEAD*SEQ*DH];
__device__ float g_k[BATCH*NHEAD*SEQ*DH];
__device__ float g_v[BATCH*NHEAD*SEQ*DH];
// ctx, ff: GEMM-A-tile swizzled: [mtile][kchunk32][4096 f]
__device__ float g_ctx[NROWS*D_EMBED];
__device__ float g_ff[(size_t)NROWS*DFF];
__device__ float g_res1[NROWS*D_EMBED];
__device__ float g_h[NROWS*D_EMBED];
__device__ float g_res2[NROWS*D_EMBED];
// pre-swizzled weights: [ntile(256n)][kchunk(32k)][8192 f]
__device__ float g_wqkvt[3*D_EMBED*D_EMBED];
__device__ float g_wot[D_EMBED*D_EMBED];
__device__ float g_w1t[DFF*D_EMBED];
__device__ float g_w2t[D_EMBED*DFF];

// ---------------- helpers ------------------------------------------------------
__device__ __forceinline__ float gelu_f(float x) {
    return 0.5f * x * (1.0f + erff(x * 0.70710678118654752f));
}
__device__ __forceinline__ uint32_t smem_u32(const void* p) {
    uint32_t a;
    asm("{ .reg .u64 t; cvta.to.shared.u64 t, %1; cvt.u32.u64 %0, t; }" : "=r"(a) : "l"(p));
    return a;
}
__device__ __forceinline__ int swz_fi(int r, int j) {
    int g = j >> 2;
    return r * 32 + ((g ^ (r & 7)) << 2) + (j & 3);
}
__device__ __forceinline__ float ld_swz(const float* Wt, int NC, int n, int k) {
    int blk = (n >> 8) * NC + (k >> 5);
    int off = (n & 255) * 128 + (k & 31) * 4;
    int sw = off ^ ((off >> 3) & 0x70);
    return *(const float*)((const char*)(Wt + (size_t)blk * 8192) + sw);
}

#if HAS_TC
__device__ __forceinline__ uint32_t elect_one_pred() {
    uint32_t pred;
    asm volatile("{\n\t.reg .pred p;\n\telect.sync _|p, 0xFFFFFFFF;\n\t"
                 "selp.b32 %0, 1, 0, p;\n\t}" : "=r"(pred));
    return pred;
}
#define MBAR_INIT(a, n) asm volatile("mbarrier.init.shared.b64 [%0], %1;" :: "r"(a), "r"(n) : "memory")
#define MBAR_EXPECT_TX(a, bytes) \
    asm volatile("mbarrier.arrive.expect_tx.shared.b64 _, [%0], %1;" :: "r"(a), "r"(bytes) : "memory")
#define MBAR_WAIT(a, par) do { \
    uint32_t _m = (a), _p = (par), _d; \
    asm volatile("{\n\t.reg .pred p;\n\t" \
        "mbarrier.try_wait.parity.acquire.cta.shared::cta.b64 p, [%1], %2;\n\t" \
        "selp.b32 %0, 1, 0, p;\n\t}" : "=r"(_d) : "r"(_m), "r"(_p) : "memory"); \
    if (!_d) { asm volatile("{\n\t.reg .pred P1;\n\tWL_%=:\n\t" \
        "mbarrier.try_wait.parity.acquire.cta.shared::cta.b64 P1, [%0], %1, 0x989680;\n\t" \
        "@P1 bra.uni WD_%=;\n\tbra.uni WL_%=;\n\tWD_%=:\n\t}" \
        :: "r"(_m), "r"(_p) : "memory"); } \
} while (0)
#define BULK_CP(dst, src, sz, mb) \
    asm volatile("cp.async.bulk.shared::cluster.global.mbarrier::complete_tx::bytes [%0], [%1], %2, [%3];" \
        :: "r"(dst), "l"(src), "r"(sz), "r"(mb) : "memory")

#define TC_ALLOC(sa, n)   asm volatile("tcgen05.alloc.cta_group::1.sync.aligned.shared::cta.b32 [%0], %1;" :: "r"(sa), "r"(n) : "memory")
#define TC_DEALLOC(t, n)  asm volatile("tcgen05.dealloc.cta_group::1.sync.aligned.b32 %0, %1;" :: "r"(t), "r"(n))
#define TC_COMMIT(mb)     asm volatile("tcgen05.commit.cta_group::1.mbarrier::arrive::one.shared::cluster.b64 [%0];" :: "r"(mb) : "memory")
#define TC_FENCE_AFTER()  asm volatile("tcgen05.fence::after_thread_sync;" ::: "memory")
#define TC_FENCE_BEFORE() asm volatile("tcgen05.fence::before_thread_sync;" ::: "memory")
#define TC_WAIT_LD()      asm volatile("tcgen05.wait::ld.sync.aligned;" ::: "memory")
#define TC_WAIT_ST()      asm volatile("tcgen05.wait::st.sync.aligned;" ::: "memory")
#define FENCE_ASYNC()     asm volatile("fence.proxy.async.shared::cta;" ::: "memory")

#define TC_LD_X32(r, ta) \
    asm volatile("tcgen05.ld.sync.aligned.32x32b.x32.b32 " \
        "{%0, %1, %2, %3, %4, %5, %6, %7, %8, %9, %10, %11, %12, %13, %14, %15, " \
        " %16, %17, %18, %19, %20, %21, %22, %23, %24, %25, %26, %27, %28, %29, %30, %31}, [%32];" \
        : "=r"((r)[0]), "=r"((r)[1]), "=r"((r)[2]), "=r"((r)[3]), \
          "=r"((r)[4]), "=r"((r)[5]), "=r"((r)[6]), "=r"((r)[7]), \
          "=r"((r)[8]), "=r"((r)[9]), "=r"((r)[10]), "=r"((r)[11]), \
          "=r"((r)[12]), "=r"((r)[13]), "=r"((r)[14]), "=r"((r)[15]), \
          "=r"((r)[16]), "=r"((r)[17]), "=r"((r)[18]), "=r"((r)[19]), \
          "=r"((r)[20]), "=r"((r)[21]), "=r"((r)[22]), "=r"((r)[23]), \
          "=r"((r)[24]), "=r"((r)[25]), "=r"((r)[26]), "=r"((r)[27]), \
          "=r"((r)[28]), "=r"((r)[29]), "=r"((r)[30]), "=r"((r)[31]) \
        : "r"(ta))

#define TC_ST_X32(ta, r) \
    asm volatile("tcgen05.st.sync.aligned.32x32b.x32.b32 [%0], " \
        "{%1, %2, %3, %4, %5, %6, %7, %8, %9, %10, %11, %12, %13, %14, %15, %16, " \
        " %17, %18, %19, %20, %21, %22, %23, %24, %25, %26, %27, %28, %29, %30, %31, %32};" \
        :: "r"(ta), \
           "r"((r)[0]), "r"((r)[1]), "r"((r)[2]), "r"((r)[3]), \
           "r"((r)[4]), "r"((r)[5]), "r"((r)[6]), "r"((r)[7]), \
           "r"((r)[8]), "r"((r)[9]), "r"((r)[10]), "r"((r)[11]), \
           "r"((r)[12]), "r"((r)[13]), "r"((r)[14]), "r"((r)[15]), \
           "r"((r)[16]), "r"((r)[17]), "r"((r)[18]), "r"((r)[19]), \
           "r"((r)[20]), "r"((r)[21]), "r"((r)[22]), "r"((r)[23]), \
           "r"((r)[24]), "r"((r)[25]), "r"((r)[26]), "r"((r)[27]), \
           "r"((r)[28]), "r"((r)[29]), "r"((r)[30]), "r"((r)[31]) \
        : "memory")

#define TC_MMA_TF32(dt, ad, bd, id, en) do { \
    uint32_t _e = (en) ? 1u : 0u; \
    asm volatile("{\n\t.reg .pred p;\n\tsetp.ne.u32 p, %5, 0;\n\t" \
        "tcgen05.mma.cta_group::1.kind::tf32 [%0], %1, %2, %3, {%4, %4, %4, %4}, p;\n\t}" \
        :: "r"(dt), "l"(ad), "l"(bd), "r"(id), "r"(0u), "r"(_e) : "memory"); \
} while (0)

#define TC_MMA_TF32_TS(dt, at, bd, id, en) do { \
    uint32_t _e = (en) ? 1u : 0u; \
    asm volatile("{\n\t.reg .pred p;\n\tsetp.ne.u32 p, %5, 0;\n\t" \
        "tcgen05.mma.cta_group::1.kind::tf32 [%0], [%1], %2, %3, {%4, %4, %4, %4}, p;\n\t}" \
        :: "r"(dt), "r"(at), "l"(bd), "r"(id), "r"(0u), "r"(_e) : "memory"); \
} while (0)

__device__ __forceinline__ uint64_t make_desc(uint32_t addr) {
    return ((uint64_t)2 << 61) | ((uint64_t)1 << 46) | ((uint64_t)64 << 32) |
           ((uint64_t)1 << 16) | (uint64_t)((addr >> 4) & 0x3FFF);
}
#define IDESC_G  ((1u << 4) | (2u << 7) | (2u << 10) | (32u << 17) | (8u << 24))  // M128 N256
#define IDESC_QK ((1u << 4) | (2u << 7) | (2u << 10) | (16u << 17) | (8u << 24))  // M128 N128
#define IDESC_PV ((1u << 4) | (2u << 7) | (2u << 10) | (8u  << 17) | (8u << 24))  // M128 N64
#endif // HAS_TC

// ---------------- single-launch weight pre-swizzle ------------------------------
__global__ __launch_bounds__(256)
void prep_all(const float* __restrict__ Wq, const float* __restrict__ Wk,
              const float* __restrict__ Wv, const float* __restrict__ Wo,
              const float* __restrict__ W1, const float* __restrict__ W2,
              float* __restrict__ wqkvt, float* __restrict__ wot,
              float* __restrict__ w1t, float* __restrict__ w2t)
{
    int id = blockIdx.x;
    const float* src; float* dst; int Kd, Nd, lb;
    if      (id < 1024) { src = Wq; dst = wqkvt;            Kd = 512;  Nd = 512;  lb = id; }
    else if (id < 2048) { src = Wk; dst = wqkvt + 512*512;  Kd = 512;  Nd = 512;  lb = id - 1024; }
    else if (id < 3072) { src = Wv; dst = wqkvt + 2*512*512;Kd = 512;  Nd = 512;  lb = id - 2048; }
    else if (id < 4096) { src = Wo; dst = wot;              Kd = 512;  Nd = 512;  lb = id - 3072; }
    else if (id < 8192) { src = W1; dst = w1t;              Kd = 512;  Nd = 2048; lb = id - 4096; }
    else                { src = W2; dst = w2t;              Kd = 2048; Nd = 512;  lb = id - 8192; }
    int e = lb * 256 + threadIdx.x;
    int k = e / Nd, n = e % Nd;
    float v = src[e];
    int NC = Kd >> 5;
    int blk = (n >> 8) * NC + (k >> 5);
    int off = (n & 255) * 128 + (k & 31) * 4;
    int sw = off ^ ((off >> 3) & 0x70);
    *(float*)((char*)(dst + (size_t)blk * 8192) + sw) = v;
}

// ---------------- GEMM: out[8192xN] = A @ W + bias -----------------------------
#define GEMM_SMEM 98304
template<int MODE, int ASWZ>
__global__ __launch_bounds__(256, 2)
void gemmT(const float* __restrict__ A, const float* __restrict__ Wt,
           const float* __restrict__ bias0, const float* __restrict__ bias1,
           const float* __restrict__ bias2, const float* __restrict__ resid,
           float* __restrict__ out0, float* __restrict__ out1, float* __restrict__ out2,
           int N, int K)
{
    extern __shared__ __align__(1024) float sm[];
    const int tid = threadIdx.x, wid = tid >> 5, lane = tid & 31;
    const int n0 = blockIdx.x * 256, m0 = blockIdx.y * 128;
    const int NC = K >> 5;

#if HAS_TC
    __shared__ uint32_t s_tptr;
    __shared__ unsigned long long s_mb[4];   // B0 B1 M0 M1
    const uint32_t smb = smem_u32(sm);

    if (wid == 0) TC_ALLOC(smem_u32(&s_tptr), 256);
    if (tid == 0) {
        #pragma unroll
        for (int i = 0; i < 4; ++i) MBAR_INIT(smem_u32(&s_mb[i]), 1);
    }
    __syncthreads();
    const uint32_t tmem = s_tptr;
    uint32_t mbB[2] = {smem_u32(&s_mb[0]), smem_u32(&s_mb[1])};
    uint32_t mbM[2] = {smem_u32(&s_mb[2]), smem_u32(&s_mb[3])};
    const size_t bblk = (size_t)blockIdx.x * NC;

    if (ASWZ) {
        if (tid == 0) {
            int cB[2] = {0, 0}, cM[2] = {0, 0};
            const size_t ablk = (size_t)blockIdx.y * NC;
            #pragma unroll
            for (int s = 0; s < 2; ++s) {
                MBAR_EXPECT_TX(mbB[s], 49152u);
                BULK_CP(smb + s * 16384, (const void*)(A + (ablk + s) * 4096), 16384u, mbB[s]);
                BULK_CP(smb + 32768 + s * 32768, (const void*)(Wt + (bblk + s) * 8192), 32768u, mbB[s]);
            }
            for (int s = 0; s < NC; ++s) {
                const int buf = s & 1;
                MBAR_WAIT(mbB[buf], cB[buf] & 1); cB[buf]++;
                uint64_t ad = make_desc(smb + buf * 16384);
                uint64_t bd = make_desc(smb + 32768 + buf * 32768);
                #pragma unroll
                for (int s2 = 0; s2 < 4; ++s2)
                    TC_MMA_TF32(tmem, ad + 2 * s2, bd + 2 * s2, IDESC_G, (s > 0) || (s2 > 0));
                TC_COMMIT(mbM[buf]);
                if (s + 2 < NC) {
                    MBAR_WAIT(mbM[buf], cM[buf] & 1); cM[buf]++;
                    MBAR_EXPECT_TX(mbB[buf], 49152u);
                    BULK_CP(smb + buf * 16384, (const void*)(A + (ablk + s + 2) * 4096), 16384u, mbB[buf]);
                    BULK_CP(smb + 32768 + buf * 32768, (const void*)(Wt + (bblk + s + 2) * 8192), 32768u, mbB[buf]);
                }
            }
            MBAR_WAIT(mbM[0], cM[0] & 1);
            MBAR_WAIT(mbM[1], cM[1] & 1);
        }
        __syncthreads();
        TC_FENCE_AFTER();
    } else {
        const float* Ag = A + (size_t)m0 * K;
        for (int s = 0; s < NC; ++s) {
            const int buf = s & 1, u = s >> 1;
            if (s >= 2) MBAR_WAIT(mbM[buf], (u + 1) & 1);
            if (tid == 0) {
                MBAR_EXPECT_TX(mbB[buf], 32768u);
                BULK_CP(smb + 32768 + buf * 32768, (const void*)(Wt + (bblk + s) * 8192),
                        32768u, mbB[buf]);
            }
            #pragma unroll
            for (int i = 0; i < 4; ++i) {
                int idx = tid + i * 256;
                int row = idx >> 3, c4 = idx & 7;
                int off = row * 128 + c4 * 16;
                int sw = off ^ ((off >> 3) & 0x70);
                *(float4*)((char*)sm + buf * 16384 + sw) =
                    *(const float4*)(Ag + (size_t)row * K + s * 32 + c4 * 4);
            }
            __syncthreads();
            if (wid == 0 && elect_one_pred()) {
                MBAR_WAIT(mbB[buf], u & 1);
                FENCE_ASYNC();
                uint64_t ad = make_desc(smb + buf * 16384);
                uint64_t bd = make_desc(smb + 32768 + buf * 32768);
                #pragma unroll
                for (int s2 = 0; s2 < 4; ++s2)
                    TC_MMA_TF32(tmem, ad + 2 * s2, bd + 2 * s2, IDESC_G, (s > 0) || (s2 > 0));
                TC_COMMIT(mbM[buf]);
            }
        }
        MBAR_WAIT(mbM[(NC - 1) & 1], ((NC - 1) >> 1) & 1);
        MBAR_WAIT(mbM[NC & 1], ((NC - 2) >> 1) & 1);
        TC_FENCE_AFTER();
        __syncthreads();
    }

    // ---- epilogue: 4 iterations of 64 cols staged via smem (stride 65) ----
    const int sp = wid & 3, chh = wid >> 2;
    for (int cg = 0; cg < 4; ++cg) {
        uint32_t r[32];
        TC_LD_X32(r, tmem + cg * 64 + chh * 32);
        TC_WAIT_LD();
        const int row = sp * 32 + lane;
        #pragma unroll
        for (int j = 0; j < 32; ++j) sm[row * 65 + chh * 32 + j] = __uint_as_float(r[j]);
        __syncthreads();

        const int nb = n0 + cg * 64;
        if (MODE == 0) {
            const int which = nb >> 9;
            const int hh = (nb >> 6) & 7;
            const int b_ = m0 >> 12;
            const int tile = (m0 & 4095) >> 7;
            const size_t tbase = ((size_t)(b_ * NHEAD + hh) * (SEQ / 128) + tile) * 8192;
            if (which < 2) {
                const int r2 = tid & 127, sel = tid >> 7;
                const float* bp = which ? bias1 : bias0;
                float* outw = which ? out1 : out0;
                const float scale = which ? 1.f : 0.125f;
                const float* src = &sm[r2 * 65 + sel * 32];
                float vv[32];
                #pragma unroll
                for (int j = 0; j < 32; ++j)
                    vv[j] = (src[j] + bp[(nb & 511) + sel * 32 + j]) * scale;
                float* dstb = outw + tbase + sel * 4096 + r2 * 32;
                #pragma unroll
                for (int g = 0; g < 8; ++g)
                    *(float4*)(dstb + ((g ^ (r2 & 7)) << 2)) =
                        make_float4(vv[g * 4], vv[g * 4 + 1], vv[g * 4 + 2], vv[g * 4 + 3]);
            } else {
                const int dloc = tid & 63, kg = tid >> 6;
                const float bia = bias2[(nb & 511) + dloc];
                float vv[32];
                #pragma unroll
                for (int i = 0; i < 32; ++i)
                    vv[i] = sm[(kg * 32 + i) * 65 + dloc] + bia;
                float* dstb = out2 + tbase + kg * 2048 + dloc * 32;
                #pragma unroll
                for (int g = 0; g < 8; ++g)
                    *(float4*)(dstb + ((g ^ (dloc & 7)) << 2)) =
                        make_float4(vv[g * 4], vv[g * 4 + 1], vv[g * 4 + 2], vv[g * 4 + 3]);
            }
        } else if (MODE == 2) {
            const int r2 = tid & 127, sel = tid >> 7;
            const int m = m0 + r2;
            const int n = nb + sel * 32;
            const float* src = &sm[r2 * 65 + sel * 32];   // 4B-aligned only: scalar reads
            float* dst = out0 + (size_t)m * N + n;
            const float* rs = resid + (size_t)m * N + n;
            #pragma unroll
            for (int g = 0; g < 8; ++g) {
                float4 b4 = *(const float4*)(bias0 + n + g * 4);
                float4 r4 = *(const float4*)(rs + g * 4);
                *(float4*)(dst + g * 4) = make_float4(
                    src[g * 4 + 0] + b4.x + r4.x, src[g * 4 + 1] + b4.y + r4.y,
                    src[g * 4 + 2] + b4.z + r4.z, src[g * 4 + 3] + b4.w + r4.w);
            }
        } else {
            const int r2 = tid & 127, sel = tid >> 7;
            const int n = nb + sel * 32;
            const float* src = &sm[r2 * 65 + sel * 32];
            float vv[32];
            #pragma unroll
            for (int j = 0; j < 32; ++j) vv[j] = gelu_f(src[j] + bias0[n + j]);
            float* dstb = out0 + ((size_t)(m0 >> 7) * (DFF / 32) + (n >> 5)) * 4096 + r2 * 32;
            #pragma unroll
            for (int g = 0; g < 8; ++g)
                *(float4*)(dstb + ((g ^ (r2 & 7)) << 2)) =
                    make_float4(vv[g * 4], vv[g * 4 + 1], vv[g * 4 + 2], vv[g * 4 + 3]);
        }
        __syncthreads();
    }
    if (wid == 0) TC_DEALLOC(tmem, 256);

#else
    // naive correct fallback (never runs on sm_103a HW)
    for (int e = tid; e < 128 * 256; e += 256) {
        int mr = e & 127, nc = e >> 7;
        int m = m0 + mr, n = n0 + nc;
        float acc = 0.f;
        for (int k = 0; k < K; ++k) {
            float a = ASWZ ? A[((size_t)(m >> 7) * NC + (k >> 5)) * 4096 + swz_fi(m & 127, k & 31)]
                           : A[(size_t)m * K + k];
            acc += a * ld_swz(Wt, NC, n, k);
        }
        if (MODE == 0) {
            int which = n >> 9, hh = (n >> 6) & 7;
            int b_ = m >> 12, l = m & (SEQ - 1);
            size_t tbase = ((size_t)(b_ * NHEAD + hh) * (SEQ / 128) + (l >> 7)) * 8192;
            if (which < 2) {
                const float* bp = which ? bias1 : bias0;
                float* outw = which ? out1 : out0;
                float val = (acc + bp[n & 511]) * (which ? 1.f : 0.125f);
                outw[tbase + ((n >> 5) & 1) * 4096 + swz_fi(l & 127, n & 31)] = val;
            } else {
                out2[tbase + ((l & 127) >> 5) * 2048 + swz_fi(n & 63, l & 31)] = acc + bias2[n & 511];
            }
        } else if (MODE == 2) {
            out0[(size_t)m * N + n] = acc + bias0[n] + resid[(size_t)m * N + n];
        } else {
            out0[((size_t)(m >> 7) * (DFF / 32) + (n >> 5)) * 4096 + swz_fi(m & 127, n & 31)] =
                gelu_f(acc + bias0[n]);
        }
    }
#endif
}

// ---------------- attention: all-bulk loads, softmax-only SIMT ------------------
#define ATTN_SMEM 166912

__global__ __launch_bounds__(256, 1)
void attn_k(const float* __restrict__ q, const float* __restrict__ k,
            const float* __restrict__ v, const int* __restrict__ mask,
            float* __restrict__ ctx)
{
    extern __shared__ __align__(1024) float sm[];
    const int qt = blockIdx.x, h = blockIdx.y, b = blockIdx.z;
    const int tid = threadIdx.x;
    const size_t tb = (size_t)(b * NHEAD + h) * (SEQ / 128);

#if HAS_TC
    float* Qs  = sm;                  // 8192 f
    float* Ks  = sm + 8192;           // 2 x 8192
    float* VTs = sm + 24576;          // 2 x 8192
    float* lpart = sm + 40960;        // 256
    int*   Msm = (int*)(sm + 41216);  // 4 x 128

    __shared__ uint32_t s_tptr;
    __shared__ unsigned long long s_mb[7];   // K0 K1 V0 V1 S0 S1 O
    const int wid = tid >> 5, lane = tid & 31;
    const int sp = wid & 3, chh = wid >> 2;
    const int NT = SEQ / 128;

    if (wid == 0) TC_ALLOC(smem_u32(&s_tptr), 512);
    if (tid == 0) {
        #pragma unroll
        for (int i = 0; i < 7; ++i) MBAR_INIT(smem_u32(&s_mb[i]), 1);
    }
    __syncthreads();
    const uint32_t tmem = s_tptr;
    uint32_t mbK[2] = {smem_u32(&s_mb[0]), smem_u32(&s_mb[1])};
    uint32_t mbV[2] = {smem_u32(&s_mb[2]), smem_u32(&s_mb[3])};
    uint32_t mbS[2] = {smem_u32(&s_mb[4]), smem_u32(&s_mb[5])};
    const uint32_t mbO = smem_u32(&s_mb[6]);
    const uint32_t S_T[2] = {tmem, tmem + 128};
    const uint32_t O_T = tmem + 256;

    #define ISSUE_QK(buf) do { \
        uint64_t qd0 = make_desc(smem_u32(Qs)); \
        uint64_t kd0 = make_desc(smem_u32(Ks + (buf) * 8192)); \
        _Pragma("unroll") \
        for (int c = 0; c < 2; ++c) \
            _Pragma("unroll") \
            for (int s = 0; s < 4; ++s) \
                TC_MMA_TF32(S_T[buf], qd0 + c * 1024 + 2 * s, kd0 + c * 1024 + 2 * s, \
                            IDESC_QK, (c > 0) || (s > 0)); \
        TC_COMMIT(mbS[buf]); \
    } while (0)

    if (tid == 0) {
        MBAR_EXPECT_TX(mbK[0], 65536u);
        BULK_CP(smem_u32(Qs), (const void*)(q + (tb + qt) * 8192), 32768u, mbK[0]);
        BULK_CP(smem_u32(Ks), (const void*)(k + tb * 8192), 32768u, mbK[0]);
        MBAR_EXPECT_TX(mbV[0], 32768u);
        BULK_CP(smem_u32(VTs), (const void*)(v + tb * 8192), 32768u, mbV[0]);
        MBAR_EXPECT_TX(mbK[1], 32768u);
        BULK_CP(smem_u32(Ks + 8192), (const void*)(k + (tb + 1) * 8192), 32768u, mbK[1]);
        MBAR_EXPECT_TX(mbV[1], 32768u);
        BULK_CP(smem_u32(VTs + 8192), (const void*)(v + (tb + 1) * 8192), 32768u, mbV[1]);
    }
    if (tid < 128) {
        Msm[tid] = mask[b * SEQ + tid];
        Msm[128 + tid] = mask[b * SEQ + 128 + tid];
    }
    __syncthreads();

    int cK[2] = {1, 1}, cV[2] = {0, 0};
    if (tid == 0) {
        MBAR_WAIT(mbK[0], 0);
        ISSUE_QK(0);
        MBAR_WAIT(mbK[1], 0);
        ISSUE_QK(1);
    }

    float lsum = 0.f;

    for (int t = 0; t < NT; ++t) {
        const int buf = t & 1;
        MBAR_WAIT(mbS[buf], (t >> 1) & 1);
        TC_FENCE_AFTER();

        if (tid == 0 && t + 2 < NT) {
            MBAR_EXPECT_TX(mbK[buf], 32768u);
            BULK_CP(smem_u32(Ks + buf * 8192), (const void*)(k + (tb + t + 2) * 8192),
                    32768u, mbK[buf]);
        }

        uint32_t ra[32], rb[32];
        TC_LD_X32(ra, S_T[buf] + chh * 64);
        TC_LD_X32(rb, S_T[buf] + chh * 64 + 32);
        TC_WAIT_LD();
        const int* mrow = &Msm[(t & 3) * 128 + chh * 64];
        #pragma unroll
        for (int j = 0; j < 32; ++j) {
            float s = __uint_as_float(ra[j]);
            s = mrow[j] ? s : -1e9f;
            float p = __expf(fminf(s, 60.f));
            lsum += p;
            ra[j] = __float_as_uint(p);
        }
        #pragma unroll
        for (int j = 0; j < 32; ++j) {
            float s = __uint_as_float(rb[j]);
            s = mrow[32 + j] ? s : -1e9f;
            float p = __expf(fminf(s, 60.f));
            lsum += p;
            rb[j] = __float_as_uint(p);
        }
        TC_ST_X32(S_T[buf] + chh * 64, ra);
        TC_ST_X32(S_T[buf] + chh * 64 + 32, rb);
        TC_WAIT_ST();
        TC_FENCE_BEFORE();

        if (t + 2 < NT && tid < 128)
            Msm[((t + 2) & 3) * 128 + tid] = mask[b * SEQ + (t + 2) * 128 + tid];
        __syncthreads();

        if (tid == 0) {
            TC_FENCE_AFTER();
            MBAR_WAIT(mbV[buf], cV[buf] & 1); cV[buf]++;
            #pragma unroll
            for (int cc = 0; cc < 4; ++cc) {
                uint64_t vd = make_desc(smem_u32(VTs + buf * 8192 + cc * 2048));
                #pragma unroll
                for (int s = 0; s < 4; ++s)
                    TC_MMA_TF32_TS(O_T, S_T[buf] + cc * 32 + s * 8, vd + 2 * s, IDESC_PV,
                                   (t > 0) || (cc > 0) || (s > 0));
            }
            TC_COMMIT(mbO);
        }

        MBAR_WAIT(mbO, t & 1);

        if (tid == 0 && t + 2 < NT) {
            MBAR_EXPECT_TX(mbV[buf], 32768u);
            BULK_CP(smem_u32(VTs + buf * 8192), (const void*)(v + (tb + t + 2) * 8192),
                    32768u, mbV[buf]);
            MBAR_WAIT(mbK[buf], cK[buf] & 1); cK[buf]++;
            ISSUE_QK(buf);
        }
        __syncthreads();
    }

    // combine l over halves, read O, normalize, store ctx in A-swizzled layout
    const int rr = sp * 32 + lane;
    lpart[chh * 128 + rr] = lsum;
    __syncthreads();
    float linv = 1.f / (lpart[rr] + lpart[128 + rr]);

    TC_FENCE_AFTER();
    uint32_t ro[32];
    TC_LD_X32(ro, O_T + chh * 32);
    TC_WAIT_LD();

    float vv[32];
    #pragma unroll
    for (int j = 0; j < 32; ++j) vv[j] = __uint_as_float(ro[j]) * linv;
    float* dstb = ctx + ((size_t)(b * (SEQ / 128) + qt) * (D_EMBED / 32) + h * 2 + chh) * 4096
                      + rr * 32;
    #pragma unroll
    for (int g = 0; g < 8; ++g)
        *(float4*)(dstb + ((g ^ (rr & 7)) << 2)) =
            make_float4(vv[g * 4], vv[g * 4 + 1], vv[g * 4 + 2], vv[g * 4 + 3]);
    __syncthreads();
    if (wid == 0) TC_DEALLOC(tmem, 512);
    #undef ISSUE_QK

#else
    // naive correct fallback (never runs on sm_103a HW)
    if (tid >= 128) return;
    const int rr = tid;
    const float* qb2 = q + (tb + qt) * 8192;
    float qv[64], o[64];
    #pragma unroll
    for (int d = 0; d < 64; ++d) {
        qv[d] = qb2[(d >> 5) * 4096 + swz_fi(rr, d & 31)];
        o[d] = 0.f;
    }
    float lsum = 0.f;
    for (int l = 0; l < SEQ; ++l) {
        int kt = l >> 7, r = l & 127;
        const float* kb2 = k + (tb + kt) * 8192;
        float s = 0.f;
        for (int d = 0; d < 64; ++d) s += qv[d] * kb2[(d >> 5) * 4096 + swz_fi(r, d & 31)];
        s = mask[b * SEQ + l] ? s : -1e9f;
        float p = __expf(fminf(s, 60.f));
        lsum += p;
        const float* vb2 = v + (tb + kt) * 8192;
        for (int d = 0; d < 64; ++d) o[d] += p * vb2[(r >> 5) * 2048 + swz_fi(d, r & 31)];
    }
    float linv = 1.f / lsum;
    for (int ch = 0; ch < 2; ++ch) {
        float* dstb = ctx + ((size_t)(b * (SEQ / 128) + qt) * (D_EMBED / 32) + h * 2 + ch) * 4096;
        for (int j = 0; j < 32; ++j)
            dstb[swz_fi(rr, j)] = o[ch * 32 + j] * linv;
    }
#endif
}

// ---------------- LayerNorm -----------------------------------------------------
__global__ __launch_bounds__(128)
void ln_k(const float* __restrict__ in, const float* __restrict__ gam,
          const float* __restrict__ bet, float* __restrict__ out)
{
    const int row = blockIdx.x;
    const int tid = threadIdx.x;
    float4 vx = ((const float4*)(in + (size_t)row * D_EMBED))[tid];
    float s  = vx.x + vx.y + vx.z + vx.w;
    float ss = vx.x * vx.x + vx.y * vx.y + vx.z * vx.z + vx.w * vx.w;
    #pragma unroll
    for (int o = 16; o; o >>= 1) {
        s  += __shfl_xor_sync(0xffffffffu, s, o);
        ss += __shfl_xor_sync(0xffffffffu, ss, o);
    }
    __shared__ float sh[8];
    if ((tid & 31) == 0) { sh[tid >> 5] = s; sh[4 + (tid >> 5)] = ss; }
    __syncthreads();
    float S  = sh[0] + sh[1] + sh[2] + sh[3];
    float SS = sh[4] + sh[5] + sh[6] + sh[7];
    float mu   = S * (1.f / 512.f);
    float var  = SS * (1.f / 512.f) - mu * mu;
    float rstd = rsqrtf(var + 1e-5f);
    float4 g  = ((const float4*)gam)[tid];
    float4 bb = ((const float4*)bet)[tid];
    float4 o;
    o.x = (vx.x - mu) * rstd * g.x + bb.x;
    o.y = (vx.y - mu) * rstd * g.y + bb.y;
    o.z = (vx.z - mu) * rstd * g.z + bb.z;
    o.w = (vx.w - mu) * rstd * g.w + bb.w;
    ((float4*)(out + (size_t)row * D_EMBED))[tid] = o;
}

// ---------------- launcher -------------------------------------------------------
extern "C" void kernel_launch(void* const* d_in, const int* in_sizes, int n_in,
                              void* d_out, int out_size)
{
    const float* x    = (const float*)d_in[0];
    const int*   mask = (const int*)  d_in[1];
    const float* Wq   = (const float*)d_in[2];
    const float* bq   = (const float*)d_in[3];
    const float* Wk   = (const float*)d_in[4];
    const float* bk   = (const float*)d_in[5];
    const float* Wv   = (const float*)d_in[6];
    const float* bv   = (const float*)d_in[7];
    const float* Wo   = (const float*)d_in[8];
    const float* bo   = (const float*)d_in[9];

    const float *ln1g, *ln1b, *ln2g, *ln2b, *W1, *b1, *W2, *b2;
    if (in_sizes[12] == D_EMBED * DFF) {
        ln1g = (const float*)d_in[10]; ln1b = (const float*)d_in[11];
        W1   = (const float*)d_in[12]; b1   = (const float*)d_in[13];
        W2   = (const float*)d_in[14]; b2   = (const float*)d_in[15];
        ln2g = (const float*)d_in[16]; ln2b = (const float*)d_in[17];
    } else {
        ln1g = (const float*)d_in[10]; ln1b = (const float*)d_in[11];
        ln2g = (const float*)d_in[12]; ln2b = (const float*)d_in[13];
        W1   = (const float*)d_in[14]; b1   = (const float*)d_in[15];
        W2   = (const float*)d_in[16]; b2   = (const float*)d_in[17];
    }

    float *q, *k, *v, *ctx, *res1, *h, *ff, *res2;
    float *wqkvt, *wot, *w1t, *w2t;
    cudaGetSymbolAddress((void**)&q,    g_q);
    cudaGetSymbolAddress((void**)&k,    g_k);
    cudaGetSymbolAddress((void**)&v,    g_v);
    cudaGetSymbolAddress((void**)&ctx,  g_ctx);
    cudaGetSymbolAddress((void**)&res1, g_res1);
    cudaGetSymbolAddress((void**)&h,    g_h);
    cudaGetSymbolAddress((void**)&ff,   g_ff);
    cudaGetSymbolAddress((void**)&res2, g_res2);
    cudaGetSymbolAddress((void**)&wqkvt, g_wqkvt);
    cudaGetSymbolAddress((void**)&wot,   g_wot);
    cudaGetSymbolAddress((void**)&w1t,   g_w1t);
    cudaGetSymbolAddress((void**)&w2t,   g_w2t);

    static bool attr_done = false;
    if (!attr_done) {
        cudaFuncSetAttribute(attn_k, cudaFuncAttributeMaxDynamicSharedMemorySize, ATTN_SMEM);
        cudaFuncSetAttribute((gemmT<0,0>), cudaFuncAttributeMaxDynamicSharedMemorySize, GEMM_SMEM);
        cudaFuncSetAttribute((gemmT<2,1>), cudaFuncAttributeMaxDynamicSharedMemorySize, GEMM_SMEM);
        cudaFuncSetAttribute((gemmT<3,0>), cudaFuncAttributeMaxDynamicSharedMemorySize, GEMM_SMEM);
        attr_done = true;
    }

    prep_all<<<12288, 256>>>(Wq, Wk, Wv, Wo, W1, W2, wqkvt, wot, w1t, w2t);

    gemmT<0,0><<<dim3(6, 64), 256, GEMM_SMEM>>>(x, wqkvt, bq, bk, bv, nullptr,
                                                q, k, v, 3 * D_EMBED, D_EMBED);

    attn_k<<<dim3(SEQ / 128, NHEAD, BATCH), 256, ATTN_SMEM>>>(q, k, v, mask, ctx);

    gemmT<2,1><<<dim3(2, 64), 256, GEMM_SMEM>>>(ctx, wot, bo, nullptr, nullptr, x,
                                                res1, nullptr, nullptr, D_EMBED, D_EMBED);
    ln_k<<<NROWS, 128>>>(res1, ln1g, ln1b, h);

    gemmT<3,0><<<dim3(8, 64), 256, GEMM_SMEM>>>(h, w1t, b1, nullptr, nullptr, nullptr,
                                                ff, nullptr, nullptr, DFF, D_EMBED);
    gemmT<2,1><<<dim3(2, 64), 256, GEMM_SMEM>>>(ff, w2t, b2, nullptr, nullptr, h,
                                                res2, nullptr, nullptr, D_EMBED, DFF);
    ln_k<<<NROWS, 128>>>(res2, ln2g, ln2b, (float*)d_out);
}

// round 9
// speedup vs baseline: 17.6333x; 1.0568x over previous
#include <cuda_runtime.h>
#include <math.h>
#include <stdint.h>

#define D_EMBED 512
#define NHEAD   8
#define DH      64
#define DFF     2048
#define BATCH   2
#define SEQ     4096
#define NROWS   (BATCH*SEQ)   // 8192

#if defined(__CUDA_ARCH__)
# if defined(__CUDA_ARCH_HAS_FEATURE__)
#  if __CUDA_ARCH_HAS_FEATURE__(SM103_ALL)
#   define HAS_TC 1
#  endif
# endif
# if !defined(HAS_TC) && defined(__CUDA_ARCH_SPECIFIC__)
#  define HAS_TC 1
# endif
#endif
#ifndef HAS_TC
# define HAS_TC 0
#endif

// ---------------- scratch ------------------------------------------------------
__device__ float g_q[BATCH*NHEAD*SEQ*DH];
__device__ float g_k[BATCH*NHEAD*SEQ*DH];
__device__ float g_v[BATCH*NHEAD*SEQ*DH];
__device__ float g_ctx[NROWS*D_EMBED];
__device__ float g_ff[(size_t)NROWS*DFF];
__device__ float g_res1[NROWS*D_EMBED];
__device__ float g_h[NROWS*D_EMBED];
__device__ float g_res2[NROWS*D_EMBED];
__device__ float g_wqkvt[3*D_EMBED*D_EMBED];
__device__ float g_wot[D_EMBED*D_EMBED];
__device__ float g_w1t[DFF*D_EMBED];
__device__ float g_w2t[D_EMBED*DFF];

// ---------------- helpers ------------------------------------------------------
__device__ __forceinline__ float gelu_f(float x) {
    return 0.5f * x * (1.0f + erff(x * 0.70710678118654752f));
}
__device__ __forceinline__ uint32_t smem_u32(const void* p) {
    uint32_t a;
    asm("{ .reg .u64 t; cvta.to.shared.u64 t, %1; cvt.u32.u64 %0, t; }" : "=r"(a) : "l"(p));
    return a;
}
__device__ __forceinline__ int swz_fi(int r, int j) {
    int g = j >> 2;
    return r * 32 + ((g ^ (r & 7)) << 2) + (j & 3);
}
__device__ __forceinline__ float ld_swz(const float* Wt, int NC, int n, int k) {
    int blk = (n >> 8) * NC + (k >> 5);
    int off = (n & 255) * 128 + (k & 31) * 4;
    int sw = off ^ ((off >> 3) & 0x70);
    return *(const float*)((const char*)(Wt + (size_t)blk * 8192) + sw);
}

#if HAS_TC
__device__ __forceinline__ uint32_t elect_one_pred() {
    uint32_t pred;
    asm volatile("{\n\t.reg .pred p;\n\telect.sync _|p, 0xFFFFFFFF;\n\t"
                 "selp.b32 %0, 1, 0, p;\n\t}" : "=r"(pred));
    return pred;
}
#define MBAR_INIT(a, n) asm volatile("mbarrier.init.shared.b64 [%0], %1;" :: "r"(a), "r"(n) : "memory")
#define MBAR_EXPECT_TX(a, bytes) \
    asm volatile("mbarrier.arrive.expect_tx.shared.b64 _, [%0], %1;" :: "r"(a), "r"(bytes) : "memory")
#define MBAR_WAIT(a, par) do { \
    uint32_t _m = (a), _p = (par), _d; \
    asm volatile("{\n\t.reg .pred p;\n\t" \
        "mbarrier.try_wait.parity.acquire.cta.shared::cta.b64 p, [%1], %2;\n\t" \
        "selp.b32 %0, 1, 0, p;\n\t}" : "=r"(_d) : "r"(_m), "r"(_p) : "memory"); \
    if (!_d) { asm volatile("{\n\t.reg .pred P1;\n\tWL_%=:\n\t" \
        "mbarrier.try_wait.parity.acquire.cta.shared::cta.b64 P1, [%0], %1, 0x989680;\n\t" \
        "@P1 bra.uni WD_%=;\n\tbra.uni WL_%=;\n\tWD_%=:\n\t}" \
        :: "r"(_m), "r"(_p) : "memory"); } \
} while (0)
#define BULK_CP(dst, src, sz, mb) \
    asm volatile("cp.async.bulk.shared::cluster.global.mbarrier::complete_tx::bytes [%0], [%1], %2, [%3];" \
        :: "r"(dst), "l"(src), "r"(sz), "r"(mb) : "memory")

#define TC_ALLOC(sa, n)   asm volatile("tcgen05.alloc.cta_group::1.sync.aligned.shared::cta.b32 [%0], %1;" :: "r"(sa), "r"(n) : "memory")
#define TC_DEALLOC(t, n)  asm volatile("tcgen05.dealloc.cta_group::1.sync.aligned.b32 %0, %1;" :: "r"(t), "r"(n))
#define TC_COMMIT(mb)     asm volatile("tcgen05.commit.cta_group::1.mbarrier::arrive::one.shared::cluster.b64 [%0];" :: "r"(mb) : "memory")
#define TC_FENCE_AFTER()  asm volatile("tcgen05.fence::after_thread_sync;" ::: "memory")
#define TC_FENCE_BEFORE() asm volatile("tcgen05.fence::before_thread_sync;" ::: "memory")
#define TC_WAIT_LD()      asm volatile("tcgen05.wait::ld.sync.aligned;" ::: "memory")
#define TC_WAIT_ST()      asm volatile("tcgen05.wait::st.sync.aligned;" ::: "memory")
#define FENCE_ASYNC()     asm volatile("fence.proxy.async.shared::cta;" ::: "memory")

#define TC_LD_X32(r, ta) \
    asm volatile("tcgen05.ld.sync.aligned.32x32b.x32.b32 " \
        "{%0, %1, %2, %3, %4, %5, %6, %7, %8, %9, %10, %11, %12, %13, %14, %15, " \
        " %16, %17, %18, %19, %20, %21, %22, %23, %24, %25, %26, %27, %28, %29, %30, %31}, [%32];" \
        : "=r"((r)[0]), "=r"((r)[1]), "=r"((r)[2]), "=r"((r)[3]), \
          "=r"((r)[4]), "=r"((r)[5]), "=r"((r)[6]), "=r"((r)[7]), \
          "=r"((r)[8]), "=r"((r)[9]), "=r"((r)[10]), "=r"((r)[11]), \
          "=r"((r)[12]), "=r"((r)[13]), "=r"((r)[14]), "=r"((r)[15]), \
          "=r"((r)[16]), "=r"((r)[17]), "=r"((r)[18]), "=r"((r)[19]), \
          "=r"((r)[20]), "=r"((r)[21]), "=r"((r)[22]), "=r"((r)[23]), \
          "=r"((r)[24]), "=r"((r)[25]), "=r"((r)[26]), "=r"((r)[27]), \
          "=r"((r)[28]), "=r"((r)[29]), "=r"((r)[30]), "=r"((r)[31]) \
        : "r"(ta))

#define TC_ST_X32(ta, r) \
    asm volatile("tcgen05.st.sync.aligned.32x32b.x32.b32 [%0], " \
        "{%1, %2, %3, %4, %5, %6, %7, %8, %9, %10, %11, %12, %13, %14, %15, %16, " \
        " %17, %18, %19, %20, %21, %22, %23, %24, %25, %26, %27, %28, %29, %30, %31, %32};" \
        :: "r"(ta), \
           "r"((r)[0]), "r"((r)[1]), "r"((r)[2]), "r"((r)[3]), \
           "r"((r)[4]), "r"((r)[5]), "r"((r)[6]), "r"((r)[7]), \
           "r"((r)[8]), "r"((r)[9]), "r"((r)[10]), "r"((r)[11]), \
           "r"((r)[12]), "r"((r)[13]), "r"((r)[14]), "r"((r)[15]), \
           "r"((r)[16]), "r"((r)[17]), "r"((r)[18]), "r"((r)[19]), \
           "r"((r)[20]), "r"((r)[21]), "r"((r)[22]), "r"((r)[23]), \
           "r"((r)[24]), "r"((r)[25]), "r"((r)[26]), "r"((r)[27]), \
           "r"((r)[28]), "r"((r)[29]), "r"((r)[30]), "r"((r)[31]) \
        : "memory")

#define TC_MMA_TF32(dt, ad, bd, id, en) do { \
    uint32_t _e = (en) ? 1u : 0u; \
    asm volatile("{\n\t.reg .pred p;\n\tsetp.ne.u32 p, %5, 0;\n\t" \
        "tcgen05.mma.cta_group::1.kind::tf32 [%0], %1, %2, %3, {%4, %4, %4, %4}, p;\n\t}" \
        :: "r"(dt), "l"(ad), "l"(bd), "r"(id), "r"(0u), "r"(_e) : "memory"); \
} while (0)

#define TC_MMA_TF32_TS(dt, at, bd, id, en) do { \
    uint32_t _e = (en) ? 1u : 0u; \
    asm volatile("{\n\t.reg .pred p;\n\tsetp.ne.u32 p, %5, 0;\n\t" \
        "tcgen05.mma.cta_group::1.kind::tf32 [%0], [%1], %2, %3, {%4, %4, %4, %4}, p;\n\t}" \
        :: "r"(dt), "r"(at), "l"(bd), "r"(id), "r"(0u), "r"(_e) : "memory"); \
} while (0)

__device__ __forceinline__ uint64_t make_desc(uint32_t addr) {
    return ((uint64_t)2 << 61) | ((uint64_t)1 << 46) | ((uint64_t)64 << 32) |
           ((uint64_t)1 << 16) | (uint64_t)((addr >> 4) & 0x3FFF);
}
#define IDESC_G  ((1u << 4) | (2u << 7) | (2u << 10) | (32u << 17) | (8u << 24))  // M128 N256
#define IDESC_QK ((1u << 4) | (2u << 7) | (2u << 10) | (16u << 17) | (8u << 24))  // M128 N128
#define IDESC_PV ((1u << 4) | (2u << 7) | (2u << 10) | (8u  << 17) | (8u << 24))  // M128 N64
#endif // HAS_TC

// ---------------- single-launch weight pre-swizzle ------------------------------
__global__ __launch_bounds__(256)
void prep_all(const float* __restrict__ Wq, const float* __restrict__ Wk,
              const float* __restrict__ Wv, const float* __restrict__ Wo,
              const float* __restrict__ W1, const float* __restrict__ W2,
              float* __restrict__ wqkvt, float* __restrict__ wot,
              float* __restrict__ w1t, float* __restrict__ w2t)
{
    int id = blockIdx.x;
    const float* src; float* dst; int Kd, Nd, lb;
    if      (id < 1024) { src = Wq; dst = wqkvt;            Kd = 512;  Nd = 512;  lb = id; }
    else if (id < 2048) { src = Wk; dst = wqkvt + 512*512;  Kd = 512;  Nd = 512;  lb = id - 1024; }
    else if (id < 3072) { src = Wv; dst = wqkvt + 2*512*512;Kd = 512;  Nd = 512;  lb = id - 2048; }
    else if (id < 4096) { src = Wo; dst = wot;              Kd = 512;  Nd = 512;  lb = id - 3072; }
    else if (id < 8192) { src = W1; dst = w1t;              Kd = 512;  Nd = 2048; lb = id - 4096; }
    else                { src = W2; dst = w2t;              Kd = 2048; Nd = 512;  lb = id - 8192; }
    int e = lb * 256 + threadIdx.x;
    int k = e / Nd, n = e % Nd;
    float v = src[e];
    int NC = Kd >> 5;
    int blk = (n >> 8) * NC + (k >> 5);
    int off = (n & 255) * 128 + (k & 31) * 4;
    int sw = off ^ ((off >> 3) & 0x70);
    *(float*)((char*)(dst + (size_t)blk * 8192) + sw) = v;
}

// ---------------- GEMM ----------------------------------------------------------
#define GEMM_SMEM       98304
#define GEMM_SMEM_ASWZ  147456
template<int MODE, int ASWZ>
__global__ __launch_bounds__(256, 2)
void gemmT(const float* __restrict__ A, const float* __restrict__ Wt,
           const float* __restrict__ bias0, const float* __restrict__ bias1,
           const float* __restrict__ bias2, const float* __restrict__ resid,
           float* __restrict__ out0, float* __restrict__ out1, float* __restrict__ out2,
           int N, int K)
{
    extern __shared__ __align__(1024) float sm[];
    const int tid = threadIdx.x, wid = tid >> 5, lane = tid & 31;
    const int n0 = blockIdx.x * 256, m0 = blockIdx.y * 128;
    const int NC = K >> 5;

#if HAS_TC
    __shared__ uint32_t s_tptr;
    __shared__ unsigned long long s_mb[6];   // B0 B1 B2 M0 M1 M2
    const uint32_t smb = smem_u32(sm);

    if (wid == 0) TC_ALLOC(smem_u32(&s_tptr), 256);
    if (tid == 0) {
        #pragma unroll
        for (int i = 0; i < 6; ++i) MBAR_INIT(smem_u32(&s_mb[i]), 1);
    }
    __syncthreads();
    const uint32_t tmem = s_tptr;
    uint32_t mbB[3] = {smem_u32(&s_mb[0]), smem_u32(&s_mb[1]), smem_u32(&s_mb[2])};
    uint32_t mbM[3] = {smem_u32(&s_mb[3]), smem_u32(&s_mb[4]), smem_u32(&s_mb[5])};
    const size_t bblk = (size_t)blockIdx.x * NC;

    if (ASWZ) {
        // 3-stage: A_s at smb + s*16384 (48KB), B_s at smb + 49152 + s*32768 (96KB)
        if (tid == 0) {
            int cB[3] = {0, 0, 0}, cM[3] = {0, 0, 0};
            const size_t ablk = (size_t)blockIdx.y * NC;
            #pragma unroll
            for (int s = 0; s < 3; ++s) {
                MBAR_EXPECT_TX(mbB[s], 49152u);
                BULK_CP(smb + s * 16384, (const void*)(A + (ablk + s) * 4096), 16384u, mbB[s]);
                BULK_CP(smb + 49152 + s * 32768, (const void*)(Wt + (bblk + s) * 8192), 32768u, mbB[s]);
            }
            for (int s = 0; s < NC; ++s) {
                const int buf = s % 3;
                MBAR_WAIT(mbB[buf], cB[buf] & 1); cB[buf]++;
                uint64_t ad = make_desc(smb + buf * 16384);
                uint64_t bd = make_desc(smb + 49152 + buf * 32768);
                #pragma unroll
                for (int s2 = 0; s2 < 4; ++s2)
                    TC_MMA_TF32(tmem, ad + 2 * s2, bd + 2 * s2, IDESC_G, (s > 0) || (s2 > 0));
                TC_COMMIT(mbM[buf]);
                if (s + 3 < NC) {
                    MBAR_WAIT(mbM[buf], cM[buf] & 1); cM[buf]++;
                    MBAR_EXPECT_TX(mbB[buf], 49152u);
                    BULK_CP(smb + buf * 16384, (const void*)(A + (ablk + s + 3) * 4096), 16384u, mbB[buf]);
                    BULK_CP(smb + 49152 + buf * 32768, (const void*)(Wt + (bblk + s + 3) * 8192), 32768u, mbB[buf]);
                }
            }
            #pragma unroll
            for (int b2 = 0; b2 < 3; ++b2) {
                int cnt = (NC - b2 + 2) / 3;   // commits on mbM[b2]
                if (cnt > cM[b2]) MBAR_WAIT(mbM[b2], (cnt - 1) & 1);
            }
        }
        __syncthreads();
        TC_FENCE_AFTER();
    } else {
        const float* Ag = A + (size_t)m0 * K;
        for (int s = 0; s < NC; ++s) {
            const int buf = s & 1, u = s >> 1;
            if (s >= 2) MBAR_WAIT(mbM[buf], (u + 1) & 1);
            if (tid == 0) {
                MBAR_EXPECT_TX(mbB[buf], 32768u);
                BULK_CP(smb + 32768 + buf * 32768, (const void*)(Wt + (bblk + s) * 8192),
                        32768u, mbB[buf]);
            }
            #pragma unroll
            for (int i = 0; i < 4; ++i) {
                int idx = tid + i * 256;
                int row = idx >> 3, c4 = idx & 7;
                int off = row * 128 + c4 * 16;
                int sw = off ^ ((off >> 3) & 0x70);
                *(float4*)((char*)sm + buf * 16384 + sw) =
                    *(const float4*)(Ag + (size_t)row * K + s * 32 + c4 * 4);
            }
            __syncthreads();
            if (wid == 0 && elect_one_pred()) {
                MBAR_WAIT(mbB[buf], u & 1);
                FENCE_ASYNC();
                uint64_t ad = make_desc(smb + buf * 16384);
                uint64_t bd = make_desc(smb + 32768 + buf * 32768);
                #pragma unroll
                for (int s2 = 0; s2 < 4; ++s2)
                    TC_MMA_TF32(tmem, ad + 2 * s2, bd + 2 * s2, IDESC_G, (s > 0) || (s2 > 0));
                TC_COMMIT(mbM[buf]);
            }
        }
        MBAR_WAIT(mbM[(NC - 1) & 1], ((NC - 1) >> 1) & 1);
        MBAR_WAIT(mbM[NC & 1], ((NC - 2) >> 1) & 1);
        TC_FENCE_AFTER();
        __syncthreads();
    }

    // ---- epilogue: 4 iterations of 64 cols staged via smem (stride 65) ----
    const int sp = wid & 3, chh = wid >> 2;
    for (int cg = 0; cg < 4; ++cg) {
        uint32_t r[32];
        TC_LD_X32(r, tmem + cg * 64 + chh * 32);
        TC_WAIT_LD();
        const int row = sp * 32 + lane;
        #pragma unroll
        for (int j = 0; j < 32; ++j) sm[row * 65 + chh * 32 + j] = __uint_as_float(r[j]);
        __syncthreads();

        const int nb = n0 + cg * 64;
        if (MODE == 0) {
            const int which = nb >> 9;
            const int hh = (nb >> 6) & 7;
            const int b_ = m0 >> 12;
            const int tile = (m0 & 4095) >> 7;
            const size_t tbase = ((size_t)(b_ * NHEAD + hh) * (SEQ / 128) + tile) * 8192;
            if (which < 2) {
                const int r2 = tid & 127, sel = tid >> 7;
                const float* bp = which ? bias1 : bias0;
                float* outw = which ? out1 : out0;
                const float scale = which ? 1.f : 0.125f;
                const float* src = &sm[r2 * 65 + sel * 32];
                float vv[32];
                #pragma unroll
                for (int j = 0; j < 32; ++j)
                    vv[j] = (src[j] + bp[(nb & 511) + sel * 32 + j]) * scale;
                float* dstb = outw + tbase + sel * 4096 + r2 * 32;
                #pragma unroll
                for (int g = 0; g < 8; ++g)
                    *(float4*)(dstb + ((g ^ (r2 & 7)) << 2)) =
                        make_float4(vv[g * 4], vv[g * 4 + 1], vv[g * 4 + 2], vv[g * 4 + 3]);
            } else {
                const int dloc = tid & 63, kg = tid >> 6;
                const float bia = bias2[(nb & 511) + dloc];
                float vv[32];
                #pragma unroll
                for (int i = 0; i < 32; ++i)
                    vv[i] = sm[(kg * 32 + i) * 65 + dloc] + bia;
                float* dstb = out2 + tbase + kg * 2048 + dloc * 32;
                #pragma unroll
                for (int g = 0; g < 8; ++g)
                    *(float4*)(dstb + ((g ^ (dloc & 7)) << 2)) =
                        make_float4(vv[g * 4], vv[g * 4 + 1], vv[g * 4 + 2], vv[g * 4 + 3]);
            }
        } else if (MODE == 2) {
            const int r2 = tid & 127, sel = tid >> 7;
            const int m = m0 + r2;
            const int n = nb + sel * 32;
            const float* src = &sm[r2 * 65 + sel * 32];   // scalar LDS (4B aligned)
            float* dst = out0 + (size_t)m * N + n;
            const float* rs = resid + (size_t)m * N + n;
            #pragma unroll
            for (int g = 0; g < 8; ++g) {
                float4 b4 = *(const float4*)(bias0 + n + g * 4);
                float4 r4 = *(const float4*)(rs + g * 4);
                *(float4*)(dst + g * 4) = make_float4(
                    src[g * 4 + 0] + b4.x + r4.x, src[g * 4 + 1] + b4.y + r4.y,
                    src[g * 4 + 2] + b4.z + r4.z, src[g * 4 + 3] + b4.w + r4.w);
            }
        } else {
            const int r2 = tid & 127, sel = tid >> 7;
            const int n = nb + sel * 32;
            const float* src = &sm[r2 * 65 + sel * 32];
            float vv[32];
            #pragma unroll
            for (int j = 0; j < 32; ++j) vv[j] = gelu_f(src[j] + bias0[n + j]);
            float* dstb = out0 + ((size_t)(m0 >> 7) * (DFF / 32) + (n >> 5)) * 4096 + r2 * 32;
            #pragma unroll
            for (int g = 0; g < 8; ++g)
                *(float4*)(dstb + ((g ^ (r2 & 7)) << 2)) =
                    make_float4(vv[g * 4], vv[g * 4 + 1], vv[g * 4 + 2], vv[g * 4 + 3]);
        }
        __syncthreads();
    }
    if (wid == 0) TC_DEALLOC(tmem, 256);

#else
    // naive correct fallback (never runs on sm_103a HW)
    for (int e = tid; e < 128 * 256; e += 256) {
        int mr = e & 127, nc = e >> 7;
        int m = m0 + mr, n = n0 + nc;
        float acc = 0.f;
        for (int k = 0; k < K; ++k) {
            float a = ASWZ ? A[((size_t)(m >> 7) * NC + (k >> 5)) * 4096 + swz_fi(m & 127, k & 31)]
                           : A[(size_t)m * K + k];
            acc += a * ld_swz(Wt, NC, n, k);
        }
        if (MODE == 0) {
            int which = n >> 9, hh = (n >> 6) & 7;
            int b_ = m >> 12, l = m & (SEQ - 1);
            size_t tbase = ((size_t)(b_ * NHEAD + hh) * (SEQ / 128) + (l >> 7)) * 8192;
            if (which < 2) {
                const float* bp = which ? bias1 : bias0;
                float* outw = which ? out1 : out0;
                float val = (acc + bp[n & 511]) * (which ? 1.f : 0.125f);
                outw[tbase + ((n >> 5) & 1) * 4096 + swz_fi(l & 127, n & 31)] = val;
            } else {
                out2[tbase + ((l & 127) >> 5) * 2048 + swz_fi(n & 63, l & 31)] = acc + bias2[n & 511];
            }
        } else if (MODE == 2) {
            out0[(size_t)m * N + n] = acc + bias0[n] + resid[(size_t)m * N + n];
        } else {
            out0[((size_t)(m >> 7) * (DFF / 32) + (n >> 5)) * 4096 + swz_fi(m & 127, n & 31)] =
                gelu_f(acc + bias0[n]);
        }
    }
#endif
}

// ---------------- attention: BQ=256, 2 q-subtiles per CTA -----------------------
#define ATTN_SMEM 200704

__global__ __launch_bounds__(256, 1)
void attn_k(const float* __restrict__ q, const float* __restrict__ k,
            const float* __restrict__ v, const int* __restrict__ mask,
            float* __restrict__ ctx)
{
    extern __shared__ __align__(1024) float sm[];
    const int qt2 = blockIdx.x, h = blockIdx.y, b = blockIdx.z;
    const int tid = threadIdx.x;
    const size_t tb = (size_t)(b * NHEAD + h) * (SEQ / 128);

#if HAS_TC
    float* Qs  = sm;                  // 16384 f (2 subtiles)
    float* Ks  = sm + 16384;          // 2 x 8192
    float* VTs = sm + 32768;          // 2 x 8192
    float* lpart = sm + 49152;        // [2 sub][2 chh][128]
    int*   Msm = (int*)(sm + 49664);  // [4][128]

    __shared__ uint32_t s_tptr;
    __shared__ unsigned long long s_mb[8];   // K0 K1 V0 V1 Sa Sb Oa Ob
    const int wid = tid >> 5, lane = tid & 31;
    const int sp = wid & 3, chh = wid >> 2;
    const int NT = SEQ / 128;

    if (wid == 0) TC_ALLOC(smem_u32(&s_tptr), 512);
    if (tid == 0) {
        #pragma unroll
        for (int i = 0; i < 8; ++i) MBAR_INIT(smem_u32(&s_mb[i]), 1);
    }
    __syncthreads();
    const uint32_t tmem = s_tptr;
    uint32_t mbK[2] = {smem_u32(&s_mb[0]), smem_u32(&s_mb[1])};
    uint32_t mbV[2] = {smem_u32(&s_mb[2]), smem_u32(&s_mb[3])};
    const uint32_t mbSa = smem_u32(&s_mb[4]), mbSb = smem_u32(&s_mb[5]);
    const uint32_t mbOa = smem_u32(&s_mb[6]), mbOb = smem_u32(&s_mb[7]);
    const uint32_t S_T0 = tmem, S_T1 = tmem + 128;
    const uint32_t O_T0 = tmem + 256, O_T1 = tmem + 320;

    #define ISSUE_QK(sub, kbuf, mb) do { \
        uint64_t qd = make_desc(smem_u32(Qs + (sub) * 8192)); \
        uint64_t kd = make_desc(smem_u32(Ks + (kbuf) * 8192)); \
        const uint32_t st = (sub) ? S_T1 : S_T0; \
        _Pragma("unroll") \
        for (int c = 0; c < 2; ++c) \
            _Pragma("unroll") \
            for (int s = 0; s < 4; ++s) \
                TC_MMA_TF32(st, qd + c * 1024 + 2 * s, kd + c * 1024 + 2 * s, \
                            IDESC_QK, (c > 0) || (s > 0)); \
        TC_COMMIT(mb); \
    } while (0)

    #define ISSUE_PV(sub, buf, t, mb) do { \
        const uint32_t st = (sub) ? S_T1 : S_T0; \
        const uint32_t ot = (sub) ? O_T1 : O_T0; \
        _Pragma("unroll") \
        for (int cc = 0; cc < 4; ++cc) { \
            uint64_t vd = make_desc(smem_u32(VTs + (buf) * 8192 + cc * 2048)); \
            _Pragma("unroll") \
            for (int s = 0; s < 4; ++s) \
                TC_MMA_TF32_TS(ot, st + cc * 32 + s * 8, vd + 2 * s, IDESC_PV, \
                               ((t) > 0) || (cc > 0) || (s > 0)); \
        } \
        TC_COMMIT(mb); \
    } while (0)

    // softmax over a 64-col half of one S tile, LD/EXP overlapped
    #define SOFTMAX(st, tslot, lsum) do { \
        uint32_t ra[32], rb[32]; \
        TC_LD_X32(ra, (st) + chh * 64); \
        TC_WAIT_LD(); \
        TC_LD_X32(rb, (st) + chh * 64 + 32); \
        const int* mrow = &Msm[(tslot) * 128 + chh * 64]; \
        _Pragma("unroll") \
        for (int j = 0; j < 32; ++j) { \
            float s = __uint_as_float(ra[j]); \
            s = mrow[j] ? s : -1e9f; \
            float p = __expf(fminf(s, 60.f)); \
            (lsum) += p; \
            ra[j] = __float_as_uint(p); \
        } \
        TC_WAIT_LD(); \
        TC_ST_X32((st) + chh * 64, ra); \
        _Pragma("unroll") \
        for (int j = 0; j < 32; ++j) { \
            float s = __uint_as_float(rb[j]); \
            s = mrow[32 + j] ? s : -1e9f; \
            float p = __expf(fminf(s, 60.f)); \
            (lsum) += p; \
            rb[j] = __float_as_uint(p); \
        } \
        TC_ST_X32((st) + chh * 64 + 32, rb); \
        TC_WAIT_ST(); \
        TC_FENCE_BEFORE(); \
    } while (0)

    // ---- prologue ----
    if (tid == 0) {
        MBAR_EXPECT_TX(mbK[0], 98304u);
        BULK_CP(smem_u32(Qs), (const void*)(q + (tb + qt2 * 2) * 8192), 65536u, mbK[0]);
        BULK_CP(smem_u32(Ks), (const void*)(k + tb * 8192), 32768u, mbK[0]);
        MBAR_EXPECT_TX(mbV[0], 32768u);
        BULK_CP(smem_u32(VTs), (const void*)(v + tb * 8192), 32768u, mbV[0]);
        MBAR_EXPECT_TX(mbK[1], 32768u);
        BULK_CP(smem_u32(Ks + 8192), (const void*)(k + (tb + 1) * 8192), 32768u, mbK[1]);
        MBAR_EXPECT_TX(mbV[1], 32768u);
        BULK_CP(smem_u32(VTs + 8192), (const void*)(v + (tb + 1) * 8192), 32768u, mbV[1]);
    }
    if (tid < 128) {
        Msm[tid] = mask[b * SEQ + tid];
        Msm[128 + tid] = mask[b * SEQ + 128 + tid];
    }
    __syncthreads();

    int cK[2] = {1, 0}, cV[2] = {0, 0};
    if (tid == 0) {
        MBAR_WAIT(mbK[0], 0);
        ISSUE_QK(0, 0, mbSa);
        ISSUE_QK(1, 0, mbSb);
    }

    float lsum0 = 0.f, lsum1 = 0.f;

    for (int t = 0; t < NT; ++t) {
        const int buf = t & 1;
        // ---- subtile 0 ----
        MBAR_WAIT(mbSa, t & 1);
        TC_FENCE_AFTER();
        SOFTMAX(S_T0, (t & 3), lsum0);
        __syncthreads();
        if (tid == 0) {
            TC_FENCE_AFTER();
            MBAR_WAIT(mbV[buf], cV[buf] & 1); cV[buf]++;
            ISSUE_PV(0, buf, t, mbOa);
        }
        // ---- subtile 1 ----
        MBAR_WAIT(mbSb, t & 1);
        TC_FENCE_AFTER();
        SOFTMAX(S_T1, (t & 3), lsum1);
        __syncthreads();
        if (tid == 0) {
            TC_FENCE_AFTER();
            ISSUE_PV(1, buf, t, mbOb);
            if (t + 2 < NT) {   // K(t) fully consumed (mbSa,mbSb passed)
                MBAR_EXPECT_TX(mbK[buf], 32768u);
                BULK_CP(smem_u32(Ks + buf * 8192), (const void*)(k + (tb + t + 2) * 8192),
                        32768u, mbK[buf]);
            }
            MBAR_WAIT(mbOa, t & 1);
            if (t + 1 < NT) {
                const int nb2 = (t + 1) & 1;
                MBAR_WAIT(mbK[nb2], cK[nb2] & 1); cK[nb2]++;
                ISSUE_QK(0, nb2, mbSa);
            }
            MBAR_WAIT(mbOb, t & 1);
            if (t + 1 < NT) ISSUE_QK(1, (t + 1) & 1, mbSb);
            if (t + 2 < NT) {   // V(t) consumed by both PVs
                MBAR_EXPECT_TX(mbV[buf], 32768u);
                BULK_CP(smem_u32(VTs + buf * 8192), (const void*)(v + (tb + t + 2) * 8192),
                        32768u, mbV[buf]);
            }
        }
        if (t + 2 < NT && tid < 128)
            Msm[((t + 2) & 3) * 128 + tid] = mask[b * SEQ + (t + 2) * 128 + tid];
        __syncthreads();
    }

    // ---- combine l, read O, normalize, store ctx (A-swizzled layout) ----
    const int rr = sp * 32 + lane;
    lpart[chh * 128 + rr] = lsum0;
    lpart[256 + chh * 128 + rr] = lsum1;
    __syncthreads();
    float linv0 = 1.f / (lpart[rr] + lpart[128 + rr]);
    float linv1 = 1.f / (lpart[256 + rr] + lpart[384 + rr]);

    TC_FENCE_AFTER();
    #pragma unroll
    for (int sub = 0; sub < 2; ++sub) {
        uint32_t ro[32];
        TC_LD_X32(ro, (sub ? O_T1 : O_T0) + chh * 32);
        TC_WAIT_LD();
        const float linv = sub ? linv1 : linv0;
        float vv[32];
        #pragma unroll
        for (int j = 0; j < 32; ++j) vv[j] = __uint_as_float(ro[j]) * linv;
        float* dstb = ctx + ((size_t)(b * (SEQ / 128) + qt2 * 2 + sub) * (D_EMBED / 32)
                             + h * 2 + chh) * 4096 + rr * 32;
        #pragma unroll
        for (int g = 0; g < 8; ++g)
            *(float4*)(dstb + ((g ^ (rr & 7)) << 2)) =
                make_float4(vv[g * 4], vv[g * 4 + 1], vv[g * 4 + 2], vv[g * 4 + 3]);
    }
    __syncthreads();
    if (wid == 0) TC_DEALLOC(tmem, 512);
    #undef ISSUE_QK
    #undef ISSUE_PV
    #undef SOFTMAX

#else
    // naive correct fallback (never runs on sm_103a HW)
    if (tid >= 128) return;
    const int rr = tid;
    for (int sub = 0; sub < 2; ++sub) {
        const int qt = qt2 * 2 + sub;
        const float* qb2 = q + (tb + qt) * 8192;
        float qv[64], o[64];
        #pragma unroll
        for (int d = 0; d < 64; ++d) {
            qv[d] = qb2[(d >> 5) * 4096 + swz_fi(rr, d & 31)];
            o[d] = 0.f;
        }
        float lsum = 0.f;
        for (int l = 0; l < SEQ; ++l) {
            int kt = l >> 7, r = l & 127;
            const float* kb2 = k + (tb + kt) * 8192;
            float s = 0.f;
            for (int d = 0; d < 64; ++d) s += qv[d] * kb2[(d >> 5) * 4096 + swz_fi(r, d & 31)];
            s = mask[b * SEQ + l] ? s : -1e9f;
            float p = __expf(fminf(s, 60.f));
            lsum += p;
            const float* vb2 = v + (tb + kt) * 8192;
            for (int d = 0; d < 64; ++d) o[d] += p * vb2[(r >> 5) * 2048 + swz_fi(d, r & 31)];
        }
        float linv = 1.f / lsum;
        for (int ch = 0; ch < 2; ++ch) {
            float* dstb = ctx + ((size_t)(b * (SEQ / 128) + qt) * (D_EMBED / 32) + h * 2 + ch) * 4096;
            for (int j = 0; j < 32; ++j)
                dstb[swz_fi(rr, j)] = o[ch * 32 + j] * linv;
        }
    }
#endif
}

// ---------------- LayerNorm -----------------------------------------------------
__global__ __launch_bounds__(128)
void ln_k(const float* __restrict__ in, const float* __restrict__ gam,
          const float* __restrict__ bet, float* __restrict__ out)
{
    const int row = blockIdx.x;
    const int tid = threadIdx.x;
    float4 vx = ((const float4*)(in + (size_t)row * D_EMBED))[tid];
    float s  = vx.x + vx.y + vx.z + vx.w;
    float ss = vx.x * vx.x + vx.y * vx.y + vx.z * vx.z + vx.w * vx.w;
    #pragma unroll
    for (int o = 16; o; o >>= 1) {
        s  += __shfl_xor_sync(0xffffffffu, s, o);
        ss += __shfl_xor_sync(0xffffffffu, ss, o);
    }
    __shared__ float sh[8];
    if ((tid & 31) == 0) { sh[tid >> 5] = s; sh[4 + (tid >> 5)] = ss; }
    __syncthreads();
    float S  = sh[0] + sh[1] + sh[2] + sh[3];
    float SS = sh[4] + sh[5] + sh[6] + sh[7];
    float mu   = S * (1.f / 512.f);
    float var  = SS * (1.f / 512.f) - mu * mu;
    float rstd = rsqrtf(var + 1e-5f);
    float4 g  = ((const float4*)gam)[tid];
    float4 bb = ((const float4*)bet)[tid];
    float4 o;
    o.x = (vx.x - mu) * rstd * g.x + bb.x;
    o.y = (vx.y - mu) * rstd * g.y + bb.y;
    o.z = (vx.z - mu) * rstd * g.z + bb.z;
    o.w = (vx.w - mu) * rstd * g.w + bb.w;
    ((float4*)(out + (size_t)row * D_EMBED))[tid] = o;
}

// ---------------- launcher -------------------------------------------------------
extern "C" void kernel_launch(void* const* d_in, const int* in_sizes, int n_in,
                              void* d_out, int out_size)
{
    const float* x    = (const float*)d_in[0];
    const int*   mask = (const int*)  d_in[1];
    const float* Wq   = (const float*)d_in[2];
    const float* bq   = (const float*)d_in[3];
    const float* Wk   = (const float*)d_in[4];
    const float* bk   = (const float*)d_in[5];
    const float* Wv   = (const float*)d_in[6];
    const float* bv   = (const float*)d_in[7];
    const float* Wo   = (const float*)d_in[8];
    const float* bo   = (const float*)d_in[9];

    const float *ln1g, *ln1b, *ln2g, *ln2b, *W1, *b1, *W2, *b2;
    if (in_sizes[12] == D_EMBED * DFF) {
        ln1g = (const float*)d_in[10]; ln1b = (const float*)d_in[11];
        W1   = (const float*)d_in[12]; b1   = (const float*)d_in[13];
        W2   = (const float*)d_in[14]; b2   = (const float*)d_in[15];
        ln2g = (const float*)d_in[16]; ln2b = (const float*)d_in[17];
    } else {
        ln1g = (const float*)d_in[10]; ln1b = (const float*)d_in[11];
        ln2g = (const float*)d_in[12]; ln2b = (const float*)d_in[13];
        W1   = (const float*)d_in[14]; b1   = (const float*)d_in[15];
        W2   = (const float*)d_in[16]; b2   = (const float*)d_in[17];
    }

    float *q, *k, *v, *ctx, *res1, *h, *ff, *res2;
    float *wqkvt, *wot, *w1t, *w2t;
    cudaGetSymbolAddress((void**)&q,    g_q);
    cudaGetSymbolAddress((void**)&k,    g_k);
    cudaGetSymbolAddress((void**)&v,    g_v);
    cudaGetSymbolAddress((void**)&ctx,  g_ctx);
    cudaGetSymbolAddress((void**)&res1, g_res1);
    cudaGetSymbolAddress((void**)&h,    g_h);
    cudaGetSymbolAddress((void**)&ff,   g_ff);
    cudaGetSymbolAddress((void**)&res2, g_res2);
    cudaGetSymbolAddress((void**)&wqkvt, g_wqkvt);
    cudaGetSymbolAddress((void**)&wot,   g_wot);
    cudaGetSymbolAddress((void**)&w1t,   g_w1t);
    cudaGetSymbolAddress((void**)&w2t,   g_w2t);

    static bool attr_done = false;
    if (!attr_done) {
        cudaFuncSetAttribute(attn_k, cudaFuncAttributeMaxDynamicSharedMemorySize, ATTN_SMEM);
        cudaFuncSetAttribute((gemmT<0,0>), cudaFuncAttributeMaxDynamicSharedMemorySize, GEMM_SMEM);
        cudaFuncSetAttribute((gemmT<2,1>), cudaFuncAttributeMaxDynamicSharedMemorySize, GEMM_SMEM_ASWZ);
        cudaFuncSetAttribute((gemmT<3,0>), cudaFuncAttributeMaxDynamicSharedMemorySize, GEMM_SMEM);
        attr_done = true;
    }

    prep_all<<<12288, 256>>>(Wq, Wk, Wv, Wo, W1, W2, wqkvt, wot, w1t, w2t);

    gemmT<0,0><<<dim3(6, 64), 256, GEMM_SMEM>>>(x, wqkvt, bq, bk, bv, nullptr,
                                                q, k, v, 3 * D_EMBED, D_EMBED);

    attn_k<<<dim3(SEQ / 256, NHEAD, BATCH), 256, ATTN_SMEM>>>(q, k, v, mask, ctx);

    gemmT<2,1><<<dim3(2, 64), 256, GEMM_SMEM_ASWZ>>>(ctx, wot, bo, nullptr, nullptr, x,
                                                     res1, nullptr, nullptr, D_EMBED, D_EMBED);
    ln_k<<<NROWS, 128>>>(res1, ln1g, ln1b, h);

    gemmT<3,0><<<dim3(8, 64), 256, GEMM_SMEM>>>(h, w1t, b1, nullptr, nullptr, nullptr,
                                                ff, nullptr, nullptr, DFF, D_EMBED);
    gemmT<2,1><<<dim3(2, 64), 256, GEMM_SMEM_ASWZ>>>(ff, w2t, b2, nullptr, nullptr, h,
                                                     res2, nullptr, nullptr, D_EMBED, DFF);
    ln_k<<<NROWS, 128>>>(res2, ln2g, ln2b, (float*)d_out);
}